// round 1
// baseline (speedup 1.0000x reference)
#include <cuda_runtime.h>
#include <cuda_bf16.h>

// Problem constants
#define NB   32
#define CIN  256
#define CD   512
#define COUT 256
#define H    56
#define W    56
#define HW   3136          // 56*56
#define HW4  784           // HW/4
#define NTOT (NB*HW)       // 100352
#define GRP  32
#define DCH  16

// Scratch (allocation-free: __device__ globals)
__device__ float g_y1[NB * CD * HW];     // conv1 raw output
__device__ float g_y2[NB * CD * HW];     // conv3 raw output
__device__ float g_y3[NB * COUT * HW];   // convA raw output
__device__ float g_scale1[CD], g_shift1[CD];
__device__ float g_scale2[CD], g_shift2[CD];
__device__ float g_scale3[COUT], g_shift3[COUT];

// ---------------------------------------------------------------------------
// 1x1 conv as SGEMM: C[n][m][p] = sum_k Wt[m][k] * B[n][k][p]
// MODE 0: conv1  (B = x external, K=256, M=512, out=g_y1, no transform)
// MODE 1: convA  (B = g_y2, K=512, M=256, out=g_y3, relu(scale2*v+shift2) on load)
// Tiles: BM=128, BN=64, BK=16; 256 threads; 8x4 per-thread microtile.
// ---------------------------------------------------------------------------
template<int MODE>
__global__ void __launch_bounds__(256) gemm1x1_kernel(const float* __restrict__ Wt,
                                                      const float* __restrict__ Bext)
{
    constexpr int K = (MODE == 0) ? CIN : CD;
    constexpr int M = (MODE == 0) ? CD : COUT;
    const float* __restrict__ B = (MODE == 0) ? Bext : g_y2;
    float* __restrict__ C = (MODE == 0) ? g_y1 : g_y3;

    __shared__ float As[16][128];
    __shared__ float Bs[16][64];

    const int tid = threadIdx.x;
    const int pb = blockIdx.x * 64;
    const int mb = blockIdx.y * 128;
    const int n  = blockIdx.z;

    const float* Bn = B + n * (K * HW);

    const int tx = tid & 15, ty = tid >> 4;
    const int n0 = tx * 4, m0 = ty * 8;

    float acc[8][4];
    #pragma unroll
    for (int i = 0; i < 8; i++)
        #pragma unroll
        for (int j = 0; j < 4; j++) acc[i][j] = 0.f;

    for (int k0 = 0; k0 < K; k0 += 16) {
        __syncthreads();
        // Load A tile (weights), store transposed As[k][m]
        #pragma unroll
        for (int l = 0; l < 2; l++) {
            int i = tid + l * 256;          // f4 index in [0,512)
            int r = i >> 2, c = i & 3;      // r: m-row, c: k f4-col
            float4 v = *(const float4*)&Wt[(mb + r) * K + k0 + c * 4];
            As[c*4+0][r] = v.x; As[c*4+1][r] = v.y;
            As[c*4+2][r] = v.z; As[c*4+3][r] = v.w;
        }
        // Load B tile (activations), optional BN+ReLU per k-row
        {
            int r  = tid >> 4;
            int cc = (tid & 15) * 4;
            int krow = k0 + r;
            float4 v = *(const float4*)&Bn[krow * HW + pb + cc];
            if (MODE == 1) {
                float sc = g_scale2[krow], sh = g_shift2[krow];
                v.x = fmaxf(fmaf(sc, v.x, sh), 0.f);
                v.y = fmaxf(fmaf(sc, v.y, sh), 0.f);
                v.z = fmaxf(fmaf(sc, v.z, sh), 0.f);
                v.w = fmaxf(fmaf(sc, v.w, sh), 0.f);
            }
            *(float4*)&Bs[r][cc] = v;
        }
        __syncthreads();
        #pragma unroll
        for (int kk = 0; kk < 16; kk++) {
            float a[8], b[4];
            *(float4*)&a[0] = *(const float4*)&As[kk][m0];
            *(float4*)&a[4] = *(const float4*)&As[kk][m0 + 4];
            *(float4*)&b[0] = *(const float4*)&Bs[kk][n0];
            #pragma unroll
            for (int i = 0; i < 8; i++)
                #pragma unroll
                for (int j = 0; j < 4; j++)
                    acc[i][j] = fmaf(a[i], b[j], acc[i][j]);
        }
    }

    float* Cn = C + n * (M * HW);
    #pragma unroll
    for (int i = 0; i < 8; i++) {
        float4 v = make_float4(acc[i][0], acc[i][1], acc[i][2], acc[i][3]);
        *(float4*)&Cn[(mb + m0 + i) * HW + pb + n0] = v;
    }
}

// ---------------------------------------------------------------------------
// Per-channel batch stats over (N,H,W) -> scale/shift (fixed-order: deterministic)
// WHICH: 1 -> g_y1 (C=512), 2 -> g_y2 (C=512), 3 -> g_y3 (C=256)
// ---------------------------------------------------------------------------
template<int WHICH>
__global__ void __launch_bounds__(256) bn_stats_kernel(const float* __restrict__ gamma,
                                                       const float* __restrict__ beta)
{
    constexpr int C = (WHICH == 3) ? COUT : CD;
    const float* __restrict__ y = (WHICH == 1) ? g_y1 : (WHICH == 2) ? g_y2 : g_y3;
    float* __restrict__ scale = (WHICH == 1) ? g_scale1 : (WHICH == 2) ? g_scale2 : g_scale3;
    float* __restrict__ shift = (WHICH == 1) ? g_shift1 : (WHICH == 2) ? g_shift2 : g_shift3;

    const int c = blockIdx.x;
    float s = 0.f, sq = 0.f;
    const float* base = y + c * HW;
    #pragma unroll 1
    for (int n = 0; n < NB; n++) {
        const float* p = base + n * (C * HW);
        for (int i = threadIdx.x; i < HW; i += 256) {
            float v = p[i];
            s += v;
            sq = fmaf(v, v, sq);
        }
    }
    // block reduce (8 warps)
    __shared__ float sh_s[8], sh_q[8];
    #pragma unroll
    for (int o = 16; o; o >>= 1) {
        s  += __shfl_down_sync(0xffffffffu, s,  o);
        sq += __shfl_down_sync(0xffffffffu, sq, o);
    }
    int lane = threadIdx.x & 31, wrp = threadIdx.x >> 5;
    if (lane == 0) { sh_s[wrp] = s; sh_q[wrp] = sq; }
    __syncthreads();
    if (threadIdx.x < 8) {
        s = sh_s[threadIdx.x]; sq = sh_q[threadIdx.x];
        #pragma unroll
        for (int o = 4; o; o >>= 1) {
            s  += __shfl_down_sync(0xffu, s,  o);
            sq += __shfl_down_sync(0xffu, sq, o);
        }
        if (threadIdx.x == 0) {
            const float inv = 1.f / (float)NTOT;
            float mean = s * inv;
            float var  = sq * inv - mean * mean;
            float sc = gamma[c] * rsqrtf(var + 1e-5f);
            scale[c] = sc;
            shift[c] = beta[c] - mean * sc;
        }
    }
}

// ---------------------------------------------------------------------------
// Grouped 3x3 conv, pad 1, stride 1. 32 groups x (16 in -> 16 out).
// Input transform relu(scale1*v+shift1) applied on load into smem.
// Block: one (ytile of 8 rows, group g, image n). 448 threads.
// Thread: 4 consecutive x positions x 4 output channels (acc 4x4).
// ---------------------------------------------------------------------------
__global__ void __launch_bounds__(448) conv3x3_grouped_kernel(const float* __restrict__ w3)
{
    __shared__ float s_in[16 * 10 * 58];                 // [ci][yy 0..9][xx 0..57]
    __shared__ __align__(16) float s_w[16 * 9 * 16];     // [ci][k 0..8][co 0..15]

    const int tid = threadIdx.x;
    const int y0 = blockIdx.x * 8;
    const int g  = blockIdx.y;
    const int n  = blockIdx.z;

    // load weights: w3 global [co=512][ci=16][3][3]
    for (int i = tid; i < 16 * 9 * 16; i += 448) {
        int co = i / 144, r = i % 144;
        int ci = r / 9, kk = r % 9;
        s_w[ci * 144 + kk * 16 + co] = w3[(g * 16 + co) * 144 + r];
    }
    // load input tile with BN+ReLU + zero padding
    const float* src = g_y1 + (n * CD + g * 16) * HW;
    for (int i = tid; i < 16 * 10 * 58; i += 448) {
        int ci = i / 580, r = i % 580;
        int yy = r / 58, xx = r % 58;
        int gy = y0 + yy - 1, gx = xx - 1;
        float v = 0.f;
        if (gy >= 0 && gy < H && gx >= 0 && gx < W) {
            int cg = g * 16 + ci;
            float t = fmaf(g_scale1[cg], src[ci * HW + gy * W + gx], g_shift1[cg]);
            v = fmaxf(t, 0.f);
        }
        s_in[i] = v;
    }
    __syncthreads();

    const int q   = tid % 112;           // position quad id
    const int cog = tid / 112;           // 0..3 -> co block of 4
    const int qx  = q % 14, qy = q / 14; // x0 = 4*qx, row qy
    const int x0  = qx * 4;

    float acc[4][4];                     // [co][x]
    #pragma unroll
    for (int j = 0; j < 4; j++)
        #pragma unroll
        for (int i = 0; i < 4; i++) acc[j][i] = 0.f;

    #pragma unroll 1
    for (int ci = 0; ci < 16; ci++) {
        const float* wci = &s_w[ci * 144 + cog * 4];
        const float* ici = &s_in[ci * 580 + qy * 58 + x0];
        #pragma unroll
        for (int dy = 0; dy < 3; dy++) {
            #pragma unroll
            for (int dx = 0; dx < 3; dx++) {
                float4 wv = *(const float4*)&wci[(dy * 3 + dx) * 16];
                const float* ip = &ici[dy * 58 + dx];
                float i0 = ip[0], i1 = ip[1], i2 = ip[2], i3 = ip[3];
                acc[0][0] = fmaf(i0, wv.x, acc[0][0]);
                acc[0][1] = fmaf(i1, wv.x, acc[0][1]);
                acc[0][2] = fmaf(i2, wv.x, acc[0][2]);
                acc[0][3] = fmaf(i3, wv.x, acc[0][3]);
                acc[1][0] = fmaf(i0, wv.y, acc[1][0]);
                acc[1][1] = fmaf(i1, wv.y, acc[1][1]);
                acc[1][2] = fmaf(i2, wv.y, acc[1][2]);
                acc[1][3] = fmaf(i3, wv.y, acc[1][3]);
                acc[2][0] = fmaf(i0, wv.z, acc[2][0]);
                acc[2][1] = fmaf(i1, wv.z, acc[2][1]);
                acc[2][2] = fmaf(i2, wv.z, acc[2][2]);
                acc[2][3] = fmaf(i3, wv.z, acc[2][3]);
                acc[3][0] = fmaf(i0, wv.w, acc[3][0]);
                acc[3][1] = fmaf(i1, wv.w, acc[3][1]);
                acc[3][2] = fmaf(i2, wv.w, acc[3][2]);
                acc[3][3] = fmaf(i3, wv.w, acc[3][3]);
            }
        }
    }

    float* dst = g_y2 + (n * CD + g * 16 + cog * 4) * HW + (y0 + qy) * W + x0;
    #pragma unroll
    for (int j = 0; j < 4; j++) {
        float4 v = make_float4(acc[j][0], acc[j][1], acc[j][2], acc[j][3]);
        *(float4*)&dst[j * HW] = v;
    }
}

// ---------------------------------------------------------------------------
// Final: out = relu(scale3*y3 + shift3 + x)   (float4 over 6,422,528 vecs)
// ---------------------------------------------------------------------------
__global__ void __launch_bounds__(256) final_kernel(const float* __restrict__ x,
                                                    float* __restrict__ out)
{
    int i = blockIdx.x * 256 + threadIdx.x;      // f4 index
    int c = (i / HW4) & (COUT - 1);              // channel
    float4 v  = ((const float4*)g_y3)[i];
    float4 xv = ((const float4*)x)[i];
    float sc = g_scale3[c], sh = g_shift3[c];
    float4 o;
    o.x = fmaxf(fmaf(sc, v.x, sh) + xv.x, 0.f);
    o.y = fmaxf(fmaf(sc, v.y, sh) + xv.y, 0.f);
    o.z = fmaxf(fmaf(sc, v.z, sh) + xv.z, 0.f);
    o.w = fmaxf(fmaf(sc, v.w, sh) + xv.w, 0.f);
    ((float4*)out)[i] = o;
}

// ---------------------------------------------------------------------------
extern "C" void kernel_launch(void* const* d_in, const int* in_sizes, int n_in,
                              void* d_out, int out_size)
{
    const float* x  = (const float*)d_in[0];
    const float* w1 = (const float*)d_in[1];
    const float* g1 = (const float*)d_in[2];
    const float* b1 = (const float*)d_in[3];
    const float* w3 = (const float*)d_in[4];
    const float* g3 = (const float*)d_in[5];
    const float* b3 = (const float*)d_in[6];
    const float* wa = (const float*)d_in[7];
    const float* ga = (const float*)d_in[8];
    const float* ba = (const float*)d_in[9];
    float* out = (float*)d_out;

    // conv1: y1 = w1 @ x   (M=512, K=256)
    gemm1x1_kernel<0><<<dim3(HW / 64, CD / 128, NB), 256>>>(w1, x);
    // BN1 stats
    bn_stats_kernel<1><<<CD, 256>>>(g1, b1);
    // grouped 3x3 with fused BN1+ReLU on load
    conv3x3_grouped_kernel<<<dim3(7, GRP, NB), 448>>>(w3);
    // BN2 stats
    bn_stats_kernel<2><<<CD, 256>>>(g3, b3);
    // convA: y3 = wa @ relu(bn2(y2))  (M=256, K=512)
    gemm1x1_kernel<1><<<dim3(HW / 64, COUT / 128, NB), 256>>>(wa, nullptr);
    // BN3 stats
    bn_stats_kernel<3><<<COUT, 256>>>(ga, ba);
    // final: relu(bn3(y3) + x)
    final_kernel<<<(NB * COUT * HW4) / 256, 256>>>(x, out);
}

// round 3
// speedup vs baseline: 1.2590x; 1.2590x over previous
#include <cuda_runtime.h>
#include <cuda_bf16.h>
#include <cstdint>

// Problem constants
#define NB   32
#define CIN  256
#define CD   512
#define COUT 256
#define H    56
#define W    56
#define HW   3136          // 56*56
#define HW4  784           // HW/4
#define NTOT (NB*HW)       // 100352
#define GRP  32

// Scratch (allocation-free: __device__ globals)
__device__ float g_y1[NB * CD * HW];     // conv1 raw output
__device__ float g_y2[NB * CD * HW];     // conv3 raw output
__device__ float g_y3[NB * COUT * HW];   // convA raw output
__device__ float g_scale1[CD], g_shift1[CD];
__device__ float g_scale2[CD], g_shift2[CD];
__device__ float g_scale3[COUT], g_shift3[COUT];

__device__ __forceinline__ uint32_t f2tf32(float f) {
    uint32_t u;
    asm("cvt.rna.tf32.f32 %0, %1;" : "=r"(u) : "f"(f));
    return u;
}

__device__ __forceinline__ void mma_tf32(float* c, const uint32_t* a, const uint32_t* b) {
    asm volatile(
        "mma.sync.aligned.m16n8k8.row.col.f32.tf32.tf32.f32 "
        "{%0,%1,%2,%3}, {%4,%5,%6,%7}, {%8,%9}, {%0,%1,%2,%3};"
        : "+f"(c[0]), "+f"(c[1]), "+f"(c[2]), "+f"(c[3])
        : "r"(a[0]), "r"(a[1]), "r"(a[2]), "r"(a[3]), "r"(b[0]), "r"(b[1]));
}

// ---------------------------------------------------------------------------
// tf32 mma.sync 1x1-conv GEMM:  C[n][m][p] = sum_k W[m][k] * Act[n][k][p]
// MODE 0: conv1 (K=256, Act=x, out g_y1)
// MODE 1: convA (K=512, Act=relu(bn2(g_y2)), out g_y3)
// CTA tile: 128m x 128pix, BK=16, 256 threads (8 warps, 2x4), warp 64x32.
// Smem: double-buffered, [row][k] stride-20 u32 (tf32 bits).
// ---------------------------------------------------------------------------
#define TSTRIDE 20
#define ABUF_U32 (128 * TSTRIDE)                 // 2560 u32 per buffer
#define GEMM_SMEM (4 * ABUF_U32 * 4)             // A0,A1,B0,B1 = 40960 B

template<int MODE>
__global__ void __launch_bounds__(256, 2) mma_gemm_kernel(const float* __restrict__ Wt,
                                                          const float* __restrict__ Bx)
{
    constexpr int K = (MODE == 0) ? CIN : CD;
    constexpr int CH = K / 16;
    constexpr int Mtot = (MODE == 0) ? CD : COUT;
    const float* __restrict__ Bsrc = (MODE == 0) ? Bx : g_y2;
    float* __restrict__ Cdst = (MODE == 0) ? g_y1 : g_y3;

    extern __shared__ uint32_t smem[];
    uint32_t* As = smem;                         // [2][2560]
    uint32_t* Bs = smem + 2 * ABUF_U32;          // [2][2560]

    const int tid = threadIdx.x;
    const int wid = tid >> 5, lane = tid & 31;
    const int lr = lane >> 2, lc = lane & 3;
    const int wm = (wid & 1) * 64;               // warp m offset in tile
    const int wn = (wid >> 1) * 32;              // warp pix offset in tile
    const int pb0 = blockIdx.x * 128;
    const int mb  = blockIdx.y * 128;
    const int n   = blockIdx.z;
    const float* Bn = Bsrc + (size_t)n * K * HW;

    float acc[4][4][4];
    #pragma unroll
    for (int m = 0; m < 4; m++)
        #pragma unroll
        for (int q = 0; q < 4; q++)
            #pragma unroll
            for (int r = 0; r < 4; r++) acc[m][q][r] = 0.f;

    float4 pa[2], pv[2];

    auto ldg = [&](int c) {
        const int k0 = c * 16;
        #pragma unroll
        for (int j = 0; j < 2; j++) {
            int f = j * 256 + tid;
            int row = f >> 2, c4 = f & 3;
            pa[j] = *(const float4*)&Wt[(size_t)(mb + row) * K + k0 + c4 * 4];
        }
        #pragma unroll
        for (int j = 0; j < 2; j++) {
            int f = j * 256 + tid;
            int krow = f >> 5, pix = (f & 31) * 4;
            if (pb0 + pix < HW) {
                float4 v = *(const float4*)&Bn[(size_t)(k0 + krow) * HW + pb0 + pix];
                if (MODE == 1) {
                    float sc = g_scale2[k0 + krow], sh = g_shift2[k0 + krow];
                    v.x = fmaxf(fmaf(sc, v.x, sh), 0.f);
                    v.y = fmaxf(fmaf(sc, v.y, sh), 0.f);
                    v.z = fmaxf(fmaf(sc, v.z, sh), 0.f);
                    v.w = fmaxf(fmaf(sc, v.w, sh), 0.f);
                }
                pv[j] = v;
            } else {
                pv[j] = make_float4(0.f, 0.f, 0.f, 0.f);
            }
        }
    };

    auto sts = [&](int buf) {
        uint32_t* Ab = As + buf * ABUF_U32;
        uint32_t* Bb = Bs + buf * ABUF_U32;
        #pragma unroll
        for (int j = 0; j < 2; j++) {
            int f = j * 256 + tid;
            int row = f >> 2, c4 = f & 3;
            uint32_t* p = &Ab[row * TSTRIDE + c4 * 4];
            p[0] = f2tf32(pa[j].x); p[1] = f2tf32(pa[j].y);
            p[2] = f2tf32(pa[j].z); p[3] = f2tf32(pa[j].w);
        }
        #pragma unroll
        for (int j = 0; j < 2; j++) {
            int f = j * 256 + tid;
            int krow = f >> 5, pix = (f & 31) * 4;
            Bb[(pix + 0) * TSTRIDE + krow] = f2tf32(pv[j].x);
            Bb[(pix + 1) * TSTRIDE + krow] = f2tf32(pv[j].y);
            Bb[(pix + 2) * TSTRIDE + krow] = f2tf32(pv[j].z);
            Bb[(pix + 3) * TSTRIDE + krow] = f2tf32(pv[j].w);
        }
    };

    auto compute = [&](int buf) {
        const uint32_t* Ab = As + buf * ABUF_U32;
        const uint32_t* Bb = Bs + buf * ABUF_U32;
        #pragma unroll
        for (int ks = 0; ks < 2; ks++) {
            const int kk = ks * 8;
            uint32_t a[4][4], b[4][2];
            #pragma unroll
            for (int m = 0; m < 4; m++) {
                const uint32_t* base = &Ab[(wm + m * 16 + lr) * TSTRIDE + kk + lc];
                a[m][0] = base[0];
                a[m][1] = base[8 * TSTRIDE];
                a[m][2] = base[4];
                a[m][3] = base[8 * TSTRIDE + 4];
            }
            #pragma unroll
            for (int q = 0; q < 4; q++) {
                const uint32_t* base = &Bb[(wn + q * 8 + lr) * TSTRIDE + kk + lc];
                b[q][0] = base[0];
                b[q][1] = base[4];
            }
            #pragma unroll
            for (int m = 0; m < 4; m++)
                #pragma unroll
                for (int q = 0; q < 4; q++)
                    mma_tf32(acc[m][q], a[m], b[q]);
        }
    };

    ldg(0);
    sts(0);
    __syncthreads();
    for (int c = 0; c < CH; c++) {
        if (c + 1 < CH) ldg(c + 1);
        compute(c & 1);
        if (c + 1 < CH) sts((c + 1) & 1);
        __syncthreads();
    }

    // Epilogue: direct float2 stores (c0,c1 / c2,c3 are adjacent pixels)
    float* Cp = Cdst + (size_t)n * Mtot * HW;
    #pragma unroll
    for (int m = 0; m < 4; m++) {
        #pragma unroll
        for (int q = 0; q < 4; q++) {
            int row = mb + wm + m * 16 + lr;
            int pix = pb0 + wn + q * 8 + lc * 2;
            if (pix < HW) {
                *(float2*)&Cp[(size_t)row * HW + pix] =
                    make_float2(acc[m][q][0], acc[m][q][1]);
                *(float2*)&Cp[(size_t)(row + 8) * HW + pix] =
                    make_float2(acc[m][q][2], acc[m][q][3]);
            }
        }
    }
}

// ---------------------------------------------------------------------------
// Per-channel batch stats over (N,H,W) -> scale/shift
// ---------------------------------------------------------------------------
template<int WHICH>
__global__ void __launch_bounds__(256) bn_stats_kernel(const float* __restrict__ gamma,
                                                       const float* __restrict__ beta)
{
    constexpr int C = (WHICH == 3) ? COUT : CD;
    const float* __restrict__ y = (WHICH == 1) ? g_y1 : (WHICH == 2) ? g_y2 : g_y3;
    float* __restrict__ scale = (WHICH == 1) ? g_scale1 : (WHICH == 2) ? g_scale2 : g_scale3;
    float* __restrict__ shift = (WHICH == 1) ? g_shift1 : (WHICH == 2) ? g_shift2 : g_shift3;

    const int c = blockIdx.x;
    float s = 0.f, sq = 0.f;
    const float* base = y + (size_t)c * HW;
    #pragma unroll 1
    for (int n = 0; n < NB; n++) {
        const float* p = base + (size_t)n * (C * HW);
        for (int i = threadIdx.x; i < HW; i += 256) {
            float v = p[i];
            s += v;
            sq = fmaf(v, v, sq);
        }
    }
    __shared__ float sh_s[8], sh_q[8];
    #pragma unroll
    for (int o = 16; o; o >>= 1) {
        s  += __shfl_down_sync(0xffffffffu, s,  o);
        sq += __shfl_down_sync(0xffffffffu, sq, o);
    }
    int lane = threadIdx.x & 31, wrp = threadIdx.x >> 5;
    if (lane == 0) { sh_s[wrp] = s; sh_q[wrp] = sq; }
    __syncthreads();
    if (threadIdx.x < 8) {
        s = sh_s[threadIdx.x]; sq = sh_q[threadIdx.x];
        #pragma unroll
        for (int o = 4; o; o >>= 1) {
            s  += __shfl_down_sync(0xffu, s,  o);
            sq += __shfl_down_sync(0xffu, sq, o);
        }
        if (threadIdx.x == 0) {
            const float inv = 1.f / (float)NTOT;
            float mean = s * inv;
            float var  = sq * inv - mean * mean;
            float sc = gamma[c] * rsqrtf(var + 1e-5f);
            scale[c] = sc;
            shift[c] = beta[c] - mean * sc;
        }
    }
}

// ---------------------------------------------------------------------------
// Grouped 3x3 conv (fp32 direct), fused BN1+ReLU on load
// ---------------------------------------------------------------------------
__global__ void __launch_bounds__(448) conv3x3_grouped_kernel(const float* __restrict__ w3)
{
    __shared__ float s_in[16 * 10 * 58];
    __shared__ __align__(16) float s_w[16 * 9 * 16];

    const int tid = threadIdx.x;
    const int y0 = blockIdx.x * 8;
    const int g  = blockIdx.y;
    const int n  = blockIdx.z;

    for (int i = tid; i < 16 * 9 * 16; i += 448) {
        int co = i / 144, r = i % 144;
        int ci = r / 9, kk = r % 9;
        s_w[ci * 144 + kk * 16 + co] = w3[(g * 16 + co) * 144 + r];
    }
    const float* src = g_y1 + (size_t)(n * CD + g * 16) * HW;
    for (int i = tid; i < 16 * 10 * 58; i += 448) {
        int ci = i / 580, r = i % 580;
        int yy = r / 58, xx = r % 58;
        int gy = y0 + yy - 1, gx = xx - 1;
        float v = 0.f;
        if (gy >= 0 && gy < H && gx >= 0 && gx < W) {
            int cg = g * 16 + ci;
            float t = fmaf(g_scale1[cg], src[(size_t)ci * HW + gy * W + gx], g_shift1[cg]);
            v = fmaxf(t, 0.f);
        }
        s_in[i] = v;
    }
    __syncthreads();

    const int q   = tid % 112;
    const int cog = tid / 112;
    const int qx  = q % 14, qy = q / 14;
    const int x0  = qx * 4;

    float acc[4][4];
    #pragma unroll
    for (int j = 0; j < 4; j++)
        #pragma unroll
        for (int i = 0; i < 4; i++) acc[j][i] = 0.f;

    #pragma unroll 1
    for (int ci = 0; ci < 16; ci++) {
        const float* wci = &s_w[ci * 144 + cog * 4];
        const float* ici = &s_in[ci * 580 + qy * 58 + x0];
        #pragma unroll
        for (int dy = 0; dy < 3; dy++) {
            #pragma unroll
            for (int dx = 0; dx < 3; dx++) {
                float4 wv = *(const float4*)&wci[(dy * 3 + dx) * 16];
                const float* ip = &ici[dy * 58 + dx];
                float i0 = ip[0], i1 = ip[1], i2 = ip[2], i3 = ip[3];
                acc[0][0] = fmaf(i0, wv.x, acc[0][0]);
                acc[0][1] = fmaf(i1, wv.x, acc[0][1]);
                acc[0][2] = fmaf(i2, wv.x, acc[0][2]);
                acc[0][3] = fmaf(i3, wv.x, acc[0][3]);
                acc[1][0] = fmaf(i0, wv.y, acc[1][0]);
                acc[1][1] = fmaf(i1, wv.y, acc[1][1]);
                acc[1][2] = fmaf(i2, wv.y, acc[1][2]);
                acc[1][3] = fmaf(i3, wv.y, acc[1][3]);
                acc[2][0] = fmaf(i0, wv.z, acc[2][0]);
                acc[2][1] = fmaf(i1, wv.z, acc[2][1]);
                acc[2][2] = fmaf(i2, wv.z, acc[2][2]);
                acc[2][3] = fmaf(i3, wv.z, acc[2][3]);
                acc[3][0] = fmaf(i0, wv.w, acc[3][0]);
                acc[3][1] = fmaf(i1, wv.w, acc[3][1]);
                acc[3][2] = fmaf(i2, wv.w, acc[3][2]);
                acc[3][3] = fmaf(i3, wv.w, acc[3][3]);
            }
        }
    }

    float* dst = g_y2 + (size_t)(n * CD + g * 16 + cog * 4) * HW + (y0 + qy) * W + x0;
    #pragma unroll
    for (int j = 0; j < 4; j++) {
        float4 v = make_float4(acc[j][0], acc[j][1], acc[j][2], acc[j][3]);
        *(float4*)&dst[(size_t)j * HW] = v;
    }
}

// ---------------------------------------------------------------------------
// Final: out = relu(scale3*y3 + shift3 + x)
// ---------------------------------------------------------------------------
__global__ void __launch_bounds__(256) final_kernel(const float* __restrict__ x,
                                                    float* __restrict__ out)
{
    int i = blockIdx.x * 256 + threadIdx.x;
    int c = (i / HW4) & (COUT - 1);
    float4 v  = ((const float4*)g_y3)[i];
    float4 xv = ((const float4*)x)[i];
    float sc = g_scale3[c], sh = g_shift3[c];
    float4 o;
    o.x = fmaxf(fmaf(sc, v.x, sh) + xv.x, 0.f);
    o.y = fmaxf(fmaf(sc, v.y, sh) + xv.y, 0.f);
    o.z = fmaxf(fmaf(sc, v.z, sh) + xv.z, 0.f);
    o.w = fmaxf(fmaf(sc, v.w, sh) + xv.w, 0.f);
    ((float4*)out)[i] = o;
}

// ---------------------------------------------------------------------------
extern "C" void kernel_launch(void* const* d_in, const int* in_sizes, int n_in,
                              void* d_out, int out_size)
{
    const float* x  = (const float*)d_in[0];
    const float* w1 = (const float*)d_in[1];
    const float* g1 = (const float*)d_in[2];
    const float* b1 = (const float*)d_in[3];
    const float* w3 = (const float*)d_in[4];
    const float* g3 = (const float*)d_in[5];
    const float* b3 = (const float*)d_in[6];
    const float* wa = (const float*)d_in[7];
    const float* ga = (const float*)d_in[8];
    const float* ba = (const float*)d_in[9];
    float* out = (float*)d_out;

    cudaFuncSetAttribute(mma_gemm_kernel<0>, cudaFuncAttributeMaxDynamicSharedMemorySize, GEMM_SMEM);
    cudaFuncSetAttribute(mma_gemm_kernel<1>, cudaFuncAttributeMaxDynamicSharedMemorySize, GEMM_SMEM);

    // conv1: y1 = w1 @ x   (M=512, K=256), 25 pixel tiles of 128
    mma_gemm_kernel<0><<<dim3(25, CD / 128, NB), 256, GEMM_SMEM>>>(w1, x);
    bn_stats_kernel<1><<<CD, 256>>>(g1, b1);
    // grouped 3x3 with fused BN1+ReLU on load
    conv3x3_grouped_kernel<<<dim3(7, GRP, NB), 448>>>(w3);
    bn_stats_kernel<2><<<CD, 256>>>(g3, b3);
    // convA: y3 = wa @ relu(bn2(y2))  (M=256, K=512)
    mma_gemm_kernel<1><<<dim3(25, COUT / 128, NB), 256, GEMM_SMEM>>>(wa, nullptr);
    bn_stats_kernel<3><<<COUT, 256>>>(ga, ba);
    // final: relu(bn3(y3) + x)
    final_kernel<<<(NB * COUT * HW4) / 256, 256>>>(x, out);
}

// round 4
// speedup vs baseline: 1.4767x; 1.1729x over previous
#include <cuda_runtime.h>
#include <cuda_bf16.h>
#include <cstdint>

// Problem constants
#define NB   32
#define CIN  256
#define CD   512
#define COUT 256
#define H    56
#define W    56
#define HW   3136          // 56*56
#define HW4  784           // HW/4
#define NTOT (NB*HW)       // 100352
#define GRP  32

// Scratch (allocation-free: __device__ globals)
__device__ float g_y1[NB * CD * HW];     // conv1 raw output
__device__ float g_y2[NB * CD * HW];     // conv3 raw output
__device__ float g_y3[NB * COUT * HW];   // convA raw output
__device__ float g_scale1[CD], g_shift1[CD];
__device__ float g_scale2[CD], g_shift2[CD];
__device__ float g_scale3[COUT], g_shift3[COUT];

__device__ __forceinline__ uint32_t f2tf32(float f) {
    uint32_t u;
    asm("cvt.rna.tf32.f32 %0, %1;" : "=r"(u) : "f"(f));
    return u;
}

__device__ __forceinline__ void mma_tf32(float* c, const uint32_t* a, const uint32_t* b) {
    asm volatile(
        "mma.sync.aligned.m16n8k8.row.col.f32.tf32.tf32.f32 "
        "{%0,%1,%2,%3}, {%4,%5,%6,%7}, {%8,%9}, {%0,%1,%2,%3};"
        : "+f"(c[0]), "+f"(c[1]), "+f"(c[2]), "+f"(c[3])
        : "r"(a[0]), "r"(a[1]), "r"(a[2]), "r"(a[3]), "r"(b[0]), "r"(b[1]));
}

// ---------------------------------------------------------------------------
// tf32 mma.sync 1x1-conv GEMM:  C[n][m][p] = sum_k W[m][k] * Act[n][k][p]
// MODE 0: conv1 (K=256, Act=x, out g_y1)
// MODE 1: convA (K=512, Act=relu(bn2(g_y2)), out g_y3)
// CTA tile: 128m x 128pix, BK=16, 256 threads (8 warps, 2x4), warp 64x32.
// ---------------------------------------------------------------------------
#define TSTRIDE 20
#define ABUF_U32 (128 * TSTRIDE)
#define GEMM_SMEM (4 * ABUF_U32 * 4)             // 40960 B

template<int MODE>
__global__ void __launch_bounds__(256, 2) mma_gemm_kernel(const float* __restrict__ Wt,
                                                          const float* __restrict__ Bx)
{
    constexpr int K = (MODE == 0) ? CIN : CD;
    constexpr int CH = K / 16;
    constexpr int Mtot = (MODE == 0) ? CD : COUT;
    const float* __restrict__ Bsrc = (MODE == 0) ? Bx : g_y2;
    float* __restrict__ Cdst = (MODE == 0) ? g_y1 : g_y3;

    extern __shared__ uint32_t smem[];
    uint32_t* As = smem;
    uint32_t* Bs = smem + 2 * ABUF_U32;

    const int tid = threadIdx.x;
    const int wid = tid >> 5, lane = tid & 31;
    const int lr = lane >> 2, lc = lane & 3;
    const int wm = (wid & 1) * 64;
    const int wn = (wid >> 1) * 32;
    const int pb0 = blockIdx.x * 128;
    const int mb  = blockIdx.y * 128;
    const int n   = blockIdx.z;
    const float* Bn = Bsrc + (size_t)n * K * HW;

    float acc[4][4][4];
    #pragma unroll
    for (int m = 0; m < 4; m++)
        #pragma unroll
        for (int q = 0; q < 4; q++)
            #pragma unroll
            for (int r = 0; r < 4; r++) acc[m][q][r] = 0.f;

    float4 pa[2], pv[2];

    auto ldg = [&](int c) {
        const int k0 = c * 16;
        #pragma unroll
        for (int j = 0; j < 2; j++) {
            int f = j * 256 + tid;
            int row = f >> 2, c4 = f & 3;
            pa[j] = *(const float4*)&Wt[(size_t)(mb + row) * K + k0 + c4 * 4];
        }
        #pragma unroll
        for (int j = 0; j < 2; j++) {
            int f = j * 256 + tid;
            int krow = f >> 5, pix = (f & 31) * 4;
            if (pb0 + pix < HW) {
                float4 v = *(const float4*)&Bn[(size_t)(k0 + krow) * HW + pb0 + pix];
                if (MODE == 1) {
                    float sc = g_scale2[k0 + krow], sh = g_shift2[k0 + krow];
                    v.x = fmaxf(fmaf(sc, v.x, sh), 0.f);
                    v.y = fmaxf(fmaf(sc, v.y, sh), 0.f);
                    v.z = fmaxf(fmaf(sc, v.z, sh), 0.f);
                    v.w = fmaxf(fmaf(sc, v.w, sh), 0.f);
                }
                pv[j] = v;
            } else {
                pv[j] = make_float4(0.f, 0.f, 0.f, 0.f);
            }
        }
    };

    auto sts = [&](int buf) {
        uint32_t* Ab = As + buf * ABUF_U32;
        uint32_t* Bb = Bs + buf * ABUF_U32;
        #pragma unroll
        for (int j = 0; j < 2; j++) {
            int f = j * 256 + tid;
            int row = f >> 2, c4 = f & 3;
            uint32_t* p = &Ab[row * TSTRIDE + c4 * 4];
            p[0] = f2tf32(pa[j].x); p[1] = f2tf32(pa[j].y);
            p[2] = f2tf32(pa[j].z); p[3] = f2tf32(pa[j].w);
        }
        #pragma unroll
        for (int j = 0; j < 2; j++) {
            int f = j * 256 + tid;
            int krow = f >> 5, pix = (f & 31) * 4;
            Bb[(pix + 0) * TSTRIDE + krow] = f2tf32(pv[j].x);
            Bb[(pix + 1) * TSTRIDE + krow] = f2tf32(pv[j].y);
            Bb[(pix + 2) * TSTRIDE + krow] = f2tf32(pv[j].z);
            Bb[(pix + 3) * TSTRIDE + krow] = f2tf32(pv[j].w);
        }
    };

    auto compute = [&](int buf) {
        const uint32_t* Ab = As + buf * ABUF_U32;
        const uint32_t* Bb = Bs + buf * ABUF_U32;
        #pragma unroll
        for (int ks = 0; ks < 2; ks++) {
            const int kk = ks * 8;
            uint32_t a[4][4], b[4][2];
            #pragma unroll
            for (int m = 0; m < 4; m++) {
                const uint32_t* base = &Ab[(wm + m * 16 + lr) * TSTRIDE + kk + lc];
                a[m][0] = base[0];
                a[m][1] = base[8 * TSTRIDE];
                a[m][2] = base[4];
                a[m][3] = base[8 * TSTRIDE + 4];
            }
            #pragma unroll
            for (int q = 0; q < 4; q++) {
                const uint32_t* base = &Bb[(wn + q * 8 + lr) * TSTRIDE + kk + lc];
                b[q][0] = base[0];
                b[q][1] = base[4];
            }
            #pragma unroll
            for (int m = 0; m < 4; m++)
                #pragma unroll
                for (int q = 0; q < 4; q++)
                    mma_tf32(acc[m][q], a[m], b[q]);
        }
    };

    ldg(0);
    sts(0);
    __syncthreads();
    for (int c = 0; c < CH; c++) {
        if (c + 1 < CH) ldg(c + 1);
        compute(c & 1);
        if (c + 1 < CH) sts((c + 1) & 1);
        __syncthreads();
    }

    float* Cp = Cdst + (size_t)n * Mtot * HW;
    #pragma unroll
    for (int m = 0; m < 4; m++) {
        #pragma unroll
        for (int q = 0; q < 4; q++) {
            int row = mb + wm + m * 16 + lr;
            int pix = pb0 + wn + q * 8 + lc * 2;
            if (pix < HW) {
                *(float2*)&Cp[(size_t)row * HW + pix] =
                    make_float2(acc[m][q][0], acc[m][q][1]);
                *(float2*)&Cp[(size_t)(row + 8) * HW + pix] =
                    make_float2(acc[m][q][2], acc[m][q][3]);
            }
        }
    }
}

// ---------------------------------------------------------------------------
// Per-channel batch stats over (N,H,W) -> scale/shift
// ---------------------------------------------------------------------------
template<int WHICH>
__global__ void __launch_bounds__(256) bn_stats_kernel(const float* __restrict__ gamma,
                                                       const float* __restrict__ beta)
{
    constexpr int C = (WHICH == 3) ? COUT : CD;
    const float* __restrict__ y = (WHICH == 1) ? g_y1 : (WHICH == 2) ? g_y2 : g_y3;
    float* __restrict__ scale = (WHICH == 1) ? g_scale1 : (WHICH == 2) ? g_scale2 : g_scale3;
    float* __restrict__ shift = (WHICH == 1) ? g_shift1 : (WHICH == 2) ? g_shift2 : g_shift3;

    const int c = blockIdx.x;
    float s = 0.f, sq = 0.f;
    const float* base = y + (size_t)c * HW;
    #pragma unroll 1
    for (int n = 0; n < NB; n++) {
        const float* p = base + (size_t)n * (C * HW);
        for (int i = threadIdx.x; i < HW; i += 256) {
            float v = p[i];
            s += v;
            sq = fmaf(v, v, sq);
        }
    }
    __shared__ float sh_s[8], sh_q[8];
    #pragma unroll
    for (int o = 16; o; o >>= 1) {
        s  += __shfl_down_sync(0xffffffffu, s,  o);
        sq += __shfl_down_sync(0xffffffffu, sq, o);
    }
    int lane = threadIdx.x & 31, wrp = threadIdx.x >> 5;
    if (lane == 0) { sh_s[wrp] = s; sh_q[wrp] = sq; }
    __syncthreads();
    if (threadIdx.x < 8) {
        s = sh_s[threadIdx.x]; sq = sh_q[threadIdx.x];
        #pragma unroll
        for (int o = 4; o; o >>= 1) {
            s  += __shfl_down_sync(0xffu, s,  o);
            sq += __shfl_down_sync(0xffu, sq, o);
        }
        if (threadIdx.x == 0) {
            const float inv = 1.f / (float)NTOT;
            float mean = s * inv;
            float var  = sq * inv - mean * mean;
            float sc = gamma[c] * rsqrtf(var + 1e-5f);
            scale[c] = sc;
            shift[c] = beta[c] - mean * sc;
        }
    }
}

// ---------------------------------------------------------------------------
// Grouped 3x3 conv as tf32 mma.sync implicit GEMM.
// Per CTA (ytile of 8 rows, group g, image n): GEMM M=16(co) x N=448(px) x K=144.
// K order: k = tap*16 + ci  (tap = dy*3+dx) -> each k8 step has a FIXED tap,
// so B-frag smem addresses are (ci-plane, fixed spatial shift) -> with ci-plane
// stride 584 u32 (mod 32 = 8), all 32 lanes hit distinct banks.
// 8 warps = 8 output rows; per warp 18 ksteps x 7 nfrags of m16n8k8.
// BN1+ReLU fused on tile load; tf32 cvt on STS path.
// ---------------------------------------------------------------------------
#define CI_STRIDE 584   // 10*58=580 used, pad to 584 (mod 32 == 8)
#define W_STRIDE  148   // 144 used, pad to 148

__global__ void __launch_bounds__(256) conv3x3_tc_kernel(const float* __restrict__ w3)
{
    __shared__ uint32_t s_in[16 * CI_STRIDE];   // [ci][yy*58+xx], tf32 bits
    __shared__ uint32_t s_w[16 * W_STRIDE];     // [co][tap*16+ci], tf32 bits

    const int tid = threadIdx.x;
    const int warp = tid >> 5, lane = tid & 31;
    const int lr = lane >> 2, lc = lane & 3;
    const int y0 = blockIdx.x * 8;
    const int g  = blockIdx.y;
    const int n  = blockIdx.z;

    // weights: w3[(g*16+co)*144 + ci*9 + tap] -> s_w[co*148 + tap*16 + ci]
    for (int i = tid; i < 16 * 144; i += 256) {
        int co = i / 144, rem = i % 144;
        int ci = rem / 9, tap = rem % 9;
        s_w[co * W_STRIDE + tap * 16 + ci] = f2tf32(w3[(g * 16 + co) * 144 + rem]);
    }
    // input tile 16ci x 10 x 58 with BN1+ReLU and zero halo
    const float* src = g_y1 + (size_t)(n * CD + g * 16) * HW;
    for (int i = tid; i < 16 * 580; i += 256) {
        int ci = i / 580, r = i % 580;
        int yy = r / 58, xx = r % 58;
        int gy = y0 + yy - 1, gx = xx - 1;
        float v = 0.f;
        if (gy >= 0 && gy < H && gx >= 0 && gx < W) {
            int cg = g * 16 + ci;
            v = fmaxf(fmaf(g_scale1[cg], src[(size_t)ci * HW + gy * W + gx], g_shift1[cg]), 0.f);
        }
        s_in[ci * CI_STRIDE + yy * 58 + xx] = f2tf32(v);
    }
    __syncthreads();

    float acc[7][4];
    #pragma unroll
    for (int f = 0; f < 7; f++)
        #pragma unroll
        for (int r = 0; r < 4; r++) acc[f][r] = 0.f;

    const int row = warp;  // output row within 8-row tile

    #pragma unroll
    for (int kk = 0; kk < 18; kk++) {
        const int tap = kk >> 1, ci0 = (kk & 1) * 8;
        const int dy = tap / 3, dx = tap % 3;
        uint32_t a[4];
        const uint32_t* ab = &s_w[lr * W_STRIDE + kk * 8 + lc];
        a[0] = ab[0];
        a[1] = ab[8 * W_STRIDE];
        a[2] = ab[4];
        a[3] = ab[8 * W_STRIDE + 4];
        const uint32_t* bb = &s_in[(ci0 + lc) * CI_STRIDE + (row + dy) * 58 + dx + lr];
        #pragma unroll
        for (int f = 0; f < 7; f++) {
            uint32_t b[2];
            b[0] = bb[f * 8];
            b[1] = bb[f * 8 + 4 * CI_STRIDE];
            mma_tf32(acc[f], a, b);
        }
    }

    // store: co rows lr and lr+8, pixels f*8 + lc*2 (+1)
    float* dst = g_y2 + (size_t)(n * CD + g * 16) * HW + (size_t)(y0 + row) * W;
    #pragma unroll
    for (int f = 0; f < 7; f++) {
        int px = f * 8 + lc * 2;
        *(float2*)&dst[(size_t)lr * HW + px] = make_float2(acc[f][0], acc[f][1]);
        *(float2*)&dst[(size_t)(lr + 8) * HW + px] = make_float2(acc[f][2], acc[f][3]);
    }
}

// ---------------------------------------------------------------------------
// Final: out = relu(scale3*y3 + shift3 + x)
// ---------------------------------------------------------------------------
__global__ void __launch_bounds__(256) final_kernel(const float* __restrict__ x,
                                                    float* __restrict__ out)
{
    int i = blockIdx.x * 256 + threadIdx.x;
    int c = (i / HW4) & (COUT - 1);
    float4 v  = ((const float4*)g_y3)[i];
    float4 xv = ((const float4*)x)[i];
    float sc = g_scale3[c], sh = g_shift3[c];
    float4 o;
    o.x = fmaxf(fmaf(sc, v.x, sh) + xv.x, 0.f);
    o.y = fmaxf(fmaf(sc, v.y, sh) + xv.y, 0.f);
    o.z = fmaxf(fmaf(sc, v.z, sh) + xv.z, 0.f);
    o.w = fmaxf(fmaf(sc, v.w, sh) + xv.w, 0.f);
    ((float4*)out)[i] = o;
}

// ---------------------------------------------------------------------------
extern "C" void kernel_launch(void* const* d_in, const int* in_sizes, int n_in,
                              void* d_out, int out_size)
{
    const float* x  = (const float*)d_in[0];
    const float* w1 = (const float*)d_in[1];
    const float* g1 = (const float*)d_in[2];
    const float* b1 = (const float*)d_in[3];
    const float* w3 = (const float*)d_in[4];
    const float* g3 = (const float*)d_in[5];
    const float* b3 = (const float*)d_in[6];
    const float* wa = (const float*)d_in[7];
    const float* ga = (const float*)d_in[8];
    const float* ba = (const float*)d_in[9];
    float* out = (float*)d_out;

    cudaFuncSetAttribute(mma_gemm_kernel<0>, cudaFuncAttributeMaxDynamicSharedMemorySize, GEMM_SMEM);
    cudaFuncSetAttribute(mma_gemm_kernel<1>, cudaFuncAttributeMaxDynamicSharedMemorySize, GEMM_SMEM);

    // conv1: y1 = w1 @ x   (M=512, K=256)
    mma_gemm_kernel<0><<<dim3(25, CD / 128, NB), 256, GEMM_SMEM>>>(w1, x);
    bn_stats_kernel<1><<<CD, 256>>>(g1, b1);
    // grouped 3x3 (tensor cores) with fused BN1+ReLU on load
    conv3x3_tc_kernel<<<dim3(7, GRP, NB), 256>>>(w3);
    bn_stats_kernel<2><<<CD, 256>>>(g3, b3);
    // convA: y3 = wa @ relu(bn2(y2))  (M=256, K=512)
    mma_gemm_kernel<1><<<dim3(25, COUT / 128, NB), 256, GEMM_SMEM>>>(wa, nullptr);
    bn_stats_kernel<3><<<COUT, 256>>>(ga, ba);
    // final: relu(bn3(y3) + x)
    final_kernel<<<(NB * COUT * HW4) / 256, 256>>>(x, out);
}

// round 6
// speedup vs baseline: 1.8501x; 1.2529x over previous
#include <cuda_runtime.h>
#include <cuda_bf16.h>
#include <cstdint>

// Problem constants
#define NB   32
#define CIN  256
#define CD   512
#define COUT 256
#define H    56
#define W    56
#define HW   3136          // 56*56
#define HW4  784           // HW/4
#define NTOT (NB*HW)       // 100352
#define GRP  32

// Scratch (allocation-free: __device__ globals)
__device__ float g_y1[NB * CD * HW];     // conv1 raw output
__device__ float g_y2[NB * CD * HW];     // conv3 raw output
__device__ float g_y3[NB * COUT * HW];   // convA raw output
__device__ float g_scale1[CD], g_shift1[CD];
__device__ float g_scale2[CD], g_shift2[CD];
__device__ float g_scale3[COUT], g_shift3[COUT];

__device__ __forceinline__ uint32_t f2tf32(float f) {
    uint32_t u;
    asm("cvt.rna.tf32.f32 %0, %1;" : "=r"(u) : "f"(f));
    return u;
}

__device__ __forceinline__ void mma_tf32(float* c, const uint32_t* a, const uint32_t* b) {
    asm volatile(
        "mma.sync.aligned.m16n8k8.row.col.f32.tf32.tf32.f32 "
        "{%0,%1,%2,%3}, {%4,%5,%6,%7}, {%8,%9}, {%0,%1,%2,%3};"
        : "+f"(c[0]), "+f"(c[1]), "+f"(c[2]), "+f"(c[3])
        : "r"(a[0]), "r"(a[1]), "r"(a[2]), "r"(a[3]), "r"(b[0]), "r"(b[1]));
}

// ---------------------------------------------------------------------------
// tf32 mma.sync 1x1-conv GEMM:  C[n][m][p] = sum_k W[m][k] * Act[n][k][p]
// MODE 0: conv1 (K=256, Act=x, out g_y1)
// MODE 1: convA (K=512, Act=relu(bn2(g_y2)), out g_y3)
// CTA tile 128m x 128pix, BK=32, double-buffered. 256 threads, 8 warps
// (warp tile 64x32). Smem holds PERMUTED fragments in mma register order:
//   A_perm[mb 0..7][ks 0..3][lane^ks (lc bits)][4]   -> 1 LDS.128 per a-frag
//   B_perm[qb 0..15][ks 0..3][lane^(qb&3)][2]        -> 1 LDS.64  per b-frag
// ---------------------------------------------------------------------------
#define BUF_U32 8192                       // 4096 (A) + 4096 (B) u32 per buffer
#define GEMM_SMEM (2 * BUF_U32 * 4)        // 65536 B

template<int MODE>
__global__ void __launch_bounds__(256) mma_gemm_kernel(const float* __restrict__ Wt,
                                                       const float* __restrict__ Bx)
{
    constexpr int K = (MODE == 0) ? CIN : CD;
    constexpr int CH = K / 32;
    constexpr int Mtot = (MODE == 0) ? CD : COUT;
    const float* __restrict__ Bsrc = (MODE == 0) ? Bx : g_y2;
    float* __restrict__ Cdst = (MODE == 0) ? g_y1 : g_y3;

    extern __shared__ uint32_t smem[];

    const int tid = threadIdx.x;
    const int wid = tid >> 5, lane = tid & 31;
    const int lr = lane >> 2, lc = lane & 3;
    const int pb0 = blockIdx.x * 128;
    const int mb  = blockIdx.y * 128;
    const int n   = blockIdx.z;
    const float* Bn = Bsrc + (size_t)n * K * HW;

    // B-load geometry: 8 k-quads x 32 lanes; each thread: 4 krows x 4 pixels
    const int kq = tid >> 5;               // 0..7 -> krows kq*4..+3
    const int lane32 = tid & 31;

    float acc[4][4][4];
    #pragma unroll
    for (int m = 0; m < 4; m++)
        #pragma unroll
        for (int q = 0; q < 4; q++)
            #pragma unroll
            for (int r = 0; r < 4; r++) acc[m][q][r] = 0.f;

    float4 pa[4];
    float  pb[4][4];                        // [p(pix)][i(krow)]

    auto ldgA = [&](int c) {
        const int k0 = c * 32;
        #pragma unroll
        for (int jj = 0; jj < 4; jj++) {
            int f = jj * 256 + tid;
            int row = f >> 3, c4 = f & 7;
            pa[jj] = *(const float4*)&Wt[(size_t)(mb + row) * K + k0 + c4 * 4];
        }
    };

    auto ldgB = [&](int c) {
        const int k0 = c * 32;
        #pragma unroll
        for (int i = 0; i < 4; i++) {
            const int kg = k0 + kq * 4 + i;
            const float* src = &Bn[(size_t)kg * HW + pb0 + lane32];
            float sc, sh;
            if (MODE == 1) { sc = g_scale2[kg]; sh = g_shift2[kg]; }
            #pragma unroll
            for (int p = 0; p < 4; p++) {
                int pix = pb0 + lane32 + p * 32;
                float v = (pix < HW) ? src[p * 32] : 0.f;
                if (MODE == 1) v = fmaxf(fmaf(sc, v, sh), 0.f);
                pb[p][i] = v;
            }
        }
    };

    auto sts = [&](int buf) {
        uint32_t* A = smem + buf * BUF_U32;
        uint32_t* B = A + 4096;
        #pragma unroll
        for (int jj = 0; jj < 4; jj++) {
            int f = jj * 256 + tid;
            int row = f >> 3, c4 = f & 7;
            int mbl = row >> 4, lrr = row & 7, rsel = (row >> 3) & 1;
            int ks = c4 >> 1, csel = c4 & 1;
            uint32_t* base = &A[(mbl * 4 + ks) * 128 + rsel + 2 * csel];
            const float* v = &pa[jj].x;
            #pragma unroll
            for (int lcc = 0; lcc < 4; lcc++)
                base[((lrr * 4) | (lcc ^ ks)) * 4] = f2tf32(v[lcc]);
        }
        {
            int ks = kq >> 1, csel = kq & 1;
            #pragma unroll
            for (int p = 0; p < 4; p++) {
                int pixl = lane32 + p * 32;
                int qb = pixl >> 3, lrr = pixl & 7;
                uint32_t* base = &B[(qb * 4 + ks) * 64 + csel];
                #pragma unroll
                for (int i = 0; i < 4; i++)
                    base[((lrr * 4) | (i ^ (qb & 3))) * 2] = f2tf32(pb[p][i]);
            }
        }
    };

    auto compute = [&](int buf) {
        const uint32_t* A = smem + buf * BUF_U32;
        const uint32_t* B = A + 4096;
        #pragma unroll
        for (int ks = 0; ks < 4; ks++) {
            uint32_t a[4][4], b[4][2];
            #pragma unroll
            for (int m = 0; m < 4; m++) {
                int mbl = (wid & 1) * 4 + m;
                uint4 t = *(const uint4*)&A[((mbl * 4 + ks) * 32 + (lane ^ ks)) * 4];
                a[m][0] = t.x; a[m][1] = t.y; a[m][2] = t.z; a[m][3] = t.w;
            }
            #pragma unroll
            for (int q = 0; q < 4; q++) {
                int qb = (wid >> 1) * 4 + q;
                uint2 t = *(const uint2*)&B[((qb * 4 + ks) * 32 + (lane ^ (qb & 3))) * 2];
                b[q][0] = t.x; b[q][1] = t.y;
            }
            #pragma unroll
            for (int m = 0; m < 4; m++)
                #pragma unroll
                for (int q = 0; q < 4; q++)
                    mma_tf32(acc[m][q], a[m], b[q]);
        }
    };

    ldgA(0); ldgB(0);
    sts(0);
    __syncthreads();
    for (int c = 0; c < CH; c++) {
        if (c + 1 < CH) { ldgA(c + 1); ldgB(c + 1); }
        compute(c & 1);
        if (c + 1 < CH) sts((c + 1) & 1);
        __syncthreads();
    }

    // Epilogue: direct float2 stores
    const int wm = (wid & 1) * 64;
    const int wn = (wid >> 1) * 32;
    float* Cp = Cdst + (size_t)n * Mtot * HW;
    #pragma unroll
    for (int m = 0; m < 4; m++) {
        #pragma unroll
        for (int q = 0; q < 4; q++) {
            int row = mb + wm + m * 16 + lr;
            int pix = pb0 + wn + q * 8 + lc * 2;
            if (pix < HW) {
                *(float2*)&Cp[(size_t)row * HW + pix] =
                    make_float2(acc[m][q][0], acc[m][q][1]);
                *(float2*)&Cp[(size_t)(row + 8) * HW + pix] =
                    make_float2(acc[m][q][2], acc[m][q][3]);
            }
        }
    }
}

// ---------------------------------------------------------------------------
// Per-channel batch stats over (N,H,W) -> scale/shift
// ---------------------------------------------------------------------------
template<int WHICH>
__global__ void __launch_bounds__(256) bn_stats_kernel(const float* __restrict__ gamma,
                                                       const float* __restrict__ beta)
{
    constexpr int C = (WHICH == 3) ? COUT : CD;
    const float* __restrict__ y = (WHICH == 1) ? g_y1 : (WHICH == 2) ? g_y2 : g_y3;
    float* __restrict__ scale = (WHICH == 1) ? g_scale1 : (WHICH == 2) ? g_scale2 : g_scale3;
    float* __restrict__ shift = (WHICH == 1) ? g_shift1 : (WHICH == 2) ? g_shift2 : g_shift3;

    const int c = blockIdx.x;
    float s = 0.f, sq = 0.f;
    const float* base = y + (size_t)c * HW;
    #pragma unroll 1
    for (int n = 0; n < NB; n++) {
        const float* p = base + (size_t)n * (C * HW);
        for (int i = threadIdx.x; i < HW; i += 256) {
            float v = p[i];
            s += v;
            sq = fmaf(v, v, sq);
        }
    }
    __shared__ float sh_s[8], sh_q[8];
    #pragma unroll
    for (int o = 16; o; o >>= 1) {
        s  += __shfl_down_sync(0xffffffffu, s,  o);
        sq += __shfl_down_sync(0xffffffffu, sq, o);
    }
    int lane = threadIdx.x & 31, wrp = threadIdx.x >> 5;
    if (lane == 0) { sh_s[wrp] = s; sh_q[wrp] = sq; }
    __syncthreads();
    if (threadIdx.x < 8) {
        s = sh_s[threadIdx.x]; sq = sh_q[threadIdx.x];
        #pragma unroll
        for (int o = 4; o; o >>= 1) {
            s  += __shfl_down_sync(0xffu, s,  o);
            sq += __shfl_down_sync(0xffu, sq, o);
        }
        if (threadIdx.x == 0) {
            const float inv = 1.f / (float)NTOT;
            float mean = s * inv;
            float var  = sq * inv - mean * mean;
            float sc = gamma[c] * rsqrtf(var + 1e-5f);
            scale[c] = sc;
            shift[c] = beta[c] - mean * sc;
        }
    }
}

// ---------------------------------------------------------------------------
// Grouped 3x3 conv as tf32 mma.sync implicit GEMM (unchanged from R4).
// ---------------------------------------------------------------------------
#define CI_STRIDE 584
#define W_STRIDE  148

__global__ void __launch_bounds__(256) conv3x3_tc_kernel(const float* __restrict__ w3)
{
    __shared__ uint32_t s_in[16 * CI_STRIDE];
    __shared__ uint32_t s_w[16 * W_STRIDE];

    const int tid = threadIdx.x;
    const int warp = tid >> 5, lane = tid & 31;
    const int lr = lane >> 2, lc = lane & 3;
    const int y0 = blockIdx.x * 8;
    const int g  = blockIdx.y;
    const int n  = blockIdx.z;

    for (int i = tid; i < 16 * 144; i += 256) {
        int co = i / 144, rem = i % 144;
        int ci = rem / 9, tap = rem % 9;
        s_w[co * W_STRIDE + tap * 16 + ci] = f2tf32(w3[(g * 16 + co) * 144 + rem]);
    }
    const float* src = g_y1 + (size_t)(n * CD + g * 16) * HW;
    for (int i = tid; i < 16 * 580; i += 256) {
        int ci = i / 580, r = i % 580;
        int yy = r / 58, xx = r % 58;
        int gy = y0 + yy - 1, gx = xx - 1;
        float v = 0.f;
        if (gy >= 0 && gy < H && gx >= 0 && gx < W) {
            int cg = g * 16 + ci;
            v = fmaxf(fmaf(g_scale1[cg], src[(size_t)ci * HW + gy * W + gx], g_shift1[cg]), 0.f);
        }
        s_in[ci * CI_STRIDE + yy * 58 + xx] = f2tf32(v);
    }
    __syncthreads();

    float acc[7][4];
    #pragma unroll
    for (int f = 0; f < 7; f++)
        #pragma unroll
        for (int r = 0; r < 4; r++) acc[f][r] = 0.f;

    const int row = warp;

    #pragma unroll
    for (int kk = 0; kk < 18; kk++) {
        const int tap = kk >> 1, ci0 = (kk & 1) * 8;
        const int dy = tap / 3, dx = tap % 3;
        uint32_t a[4];
        const uint32_t* ab = &s_w[lr * W_STRIDE + kk * 8 + lc];
        a[0] = ab[0];
        a[1] = ab[8 * W_STRIDE];
        a[2] = ab[4];
        a[3] = ab[8 * W_STRIDE + 4];
        const uint32_t* bb = &s_in[(ci0 + lc) * CI_STRIDE + (row + dy) * 58 + dx + lr];
        #pragma unroll
        for (int f = 0; f < 7; f++) {
            uint32_t b[2];
            b[0] = bb[f * 8];
            b[1] = bb[f * 8 + 4 * CI_STRIDE];
            mma_tf32(acc[f], a, b);
        }
    }

    float* dst = g_y2 + (size_t)(n * CD + g * 16) * HW + (size_t)(y0 + row) * W;
    #pragma unroll
    for (int f = 0; f < 7; f++) {
        int px = f * 8 + lc * 2;
        *(float2*)&dst[(size_t)lr * HW + px] = make_float2(acc[f][0], acc[f][1]);
        *(float2*)&dst[(size_t)(lr + 8) * HW + px] = make_float2(acc[f][2], acc[f][3]);
    }
}

// ---------------------------------------------------------------------------
// Final: out = relu(scale3*y3 + shift3 + x)
// ---------------------------------------------------------------------------
__global__ void __launch_bounds__(256) final_kernel(const float* __restrict__ x,
                                                    float* __restrict__ out)
{
    int i = blockIdx.x * 256 + threadIdx.x;
    int c = (i / HW4) & (COUT - 1);
    float4 v  = ((const float4*)g_y3)[i];
    float4 xv = ((const float4*)x)[i];
    float sc = g_scale3[c], sh = g_shift3[c];
    float4 o;
    o.x = fmaxf(fmaf(sc, v.x, sh) + xv.x, 0.f);
    o.y = fmaxf(fmaf(sc, v.y, sh) + xv.y, 0.f);
    o.z = fmaxf(fmaf(sc, v.z, sh) + xv.z, 0.f);
    o.w = fmaxf(fmaf(sc, v.w, sh) + xv.w, 0.f);
    ((float4*)out)[i] = o;
}

// ---------------------------------------------------------------------------
extern "C" void kernel_launch(void* const* d_in, const int* in_sizes, int n_in,
                              void* d_out, int out_size)
{
    const float* x  = (const float*)d_in[0];
    const float* w1 = (const float*)d_in[1];
    const float* g1 = (const float*)d_in[2];
    const float* b1 = (const float*)d_in[3];
    const float* w3 = (const float*)d_in[4];
    const float* g3 = (const float*)d_in[5];
    const float* b3 = (const float*)d_in[6];
    const float* wa = (const float*)d_in[7];
    const float* ga = (const float*)d_in[8];
    const float* ba = (const float*)d_in[9];
    float* out = (float*)d_out;

    cudaFuncSetAttribute(mma_gemm_kernel<0>, cudaFuncAttributeMaxDynamicSharedMemorySize, GEMM_SMEM);
    cudaFuncSetAttribute(mma_gemm_kernel<1>, cudaFuncAttributeMaxDynamicSharedMemorySize, GEMM_SMEM);

    // conv1: y1 = w1 @ x   (M=512, K=256)
    mma_gemm_kernel<0><<<dim3(25, CD / 128, NB), 256, GEMM_SMEM>>>(w1, x);
    bn_stats_kernel<1><<<CD, 256>>>(g1, b1);
    // grouped 3x3 (tensor cores) with fused BN1+ReLU on load
    conv3x3_tc_kernel<<<dim3(7, GRP, NB), 256>>>(w3);
    bn_stats_kernel<2><<<CD, 256>>>(g3, b3);
    // convA: y3 = wa @ relu(bn2(y2))  (M=256, K=512)
    mma_gemm_kernel<1><<<dim3(25, COUT / 128, NB), 256, GEMM_SMEM>>>(wa, nullptr);
    bn_stats_kernel<3><<<COUT, 256>>>(ga, ba);
    // final: relu(bn3(y3) + x)
    final_kernel<<<(NB * COUT * HW4) / 256, 256>>>(x, out);
}

// round 7
// speedup vs baseline: 1.9887x; 1.0749x over previous
#include <cuda_runtime.h>
#include <cuda_bf16.h>
#include <cstdint>

// Problem constants
#define NB   32
#define CIN  256
#define CD   512
#define COUT 256
#define H    56
#define W    56
#define HW   3136          // 56*56
#define HW4  784           // HW/4
#define NTOT (NB*HW)       // 100352
#define GRP  32

// Scratch (allocation-free: __device__ globals)
__device__ __align__(16) float g_y1[NB * CD * HW];     // conv1 raw output
__device__ __align__(16) float g_y2[NB * CD * HW];     // conv3 raw output
__device__ __align__(16) float g_y3[NB * COUT * HW];   // convA raw output
__device__ float g_scale1[CD], g_shift1[CD];
__device__ float g_scale2[CD], g_shift2[CD];
__device__ float g_scale3[COUT], g_shift3[COUT];
// Per-CTA BN partial sums (sum, sumsq)
__device__ float2 g_part1[CD * 800];     // conv1: 25 px-tiles * 32 imgs
__device__ float2 g_part2[CD * 224];     // conv3: 7 y-tiles * 32 imgs
__device__ float2 g_part3[COUT * 800];   // convA
// Pre-converted tf32 weights
__device__ __align__(16) uint32_t g_cw1[CD * CIN];
__device__ __align__(16) uint32_t g_cwa[COUT * CD];

__device__ __forceinline__ uint32_t f2tf32(float f) {
    uint32_t u;
    asm("cvt.rna.tf32.f32 %0, %1;" : "=r"(u) : "f"(f));
    return u;
}

__device__ __forceinline__ void mma_tf32(float* c, const uint32_t* a, const uint32_t* b) {
    asm volatile(
        "mma.sync.aligned.m16n8k8.row.col.f32.tf32.tf32.f32 "
        "{%0,%1,%2,%3}, {%4,%5,%6,%7}, {%8,%9}, {%0,%1,%2,%3};"
        : "+f"(c[0]), "+f"(c[1]), "+f"(c[2]), "+f"(c[3])
        : "r"(a[0]), "r"(a[1]), "r"(a[2]), "r"(a[3]), "r"(b[0]), "r"(b[1]));
}

// ---------------------------------------------------------------------------
// Weight pre-convert fp32 -> tf32 bits (rna)
// ---------------------------------------------------------------------------
__global__ void cvt_kernel(const float* __restrict__ s, uint32_t* __restrict__ d, int n)
{
    int i = blockIdx.x * 256 + threadIdx.x;
    if (i < n) d[i] = f2tf32(s[i]);
}

// ---------------------------------------------------------------------------
// tf32 mma.sync 1x1-conv GEMM:  C[n][m][p] = sum_k W[m][k] * Act[n][k][p]
// MODE 0: conv1 (K=256, Act=x, out g_y1, partials -> g_part1)
// MODE 1: convA (K=512, Act=relu(bn2(g_y2)), out g_y3, partials -> g_part3)
// CTA tile 256m x 128pix, BK=16, double-buffered. 256 threads, 8 warps
// (4 m-groups x 2 px-groups, warp tile 64m x 64px).
// Permuted-fragment smem: A uint4/frag, B uint2/frag, conflict-free LDS.
// Epilogue: fixed-order per-CTA BN partial reduction (deterministic) + STG.
// ---------------------------------------------------------------------------
#define BUF_U32 6144                       // 4096 (A: 256x16) + 2048 (B: 128x16)
#define GEMM_SMEM (2 * BUF_U32 * 4)        // 49152 B

template<int MODE>
__global__ void __launch_bounds__(256) mma_gemm_kernel(const float* __restrict__ Bx)
{
    constexpr int K = (MODE == 0) ? CIN : CD;
    constexpr int CH = K / 16;
    constexpr int Mtot = (MODE == 0) ? CD : COUT;
    const uint32_t* __restrict__ Wt = (MODE == 0) ? g_cw1 : g_cwa;
    const float* __restrict__ Bsrc = (MODE == 0) ? Bx : g_y2;
    float* __restrict__ Cdst = (MODE == 0) ? g_y1 : g_y3;
    float2* __restrict__ Part = (MODE == 0) ? g_part1 : g_part3;

    extern __shared__ uint32_t smem[];

    const int tid = threadIdx.x;
    const int wid = tid >> 5, lane = tid & 31;
    const int lr = lane >> 2, lc = lane & 3;
    const int wm = (wid & 3) * 64;          // warp m offset (4 groups)
    const int wn = (wid >> 2) * 64;         // warp px offset (2 groups)
    const int pb0 = blockIdx.x * 128;
    const int mbb = blockIdx.y * 256;
    const int n   = blockIdx.z;
    const float* Bn = Bsrc + (size_t)n * K * HW;

    float acc[4][8][4];
    #pragma unroll
    for (int m = 0; m < 4; m++)
        #pragma unroll
        for (int q = 0; q < 8; q++)
            #pragma unroll
            for (int r = 0; r < 4; r++) acc[m][q][r] = 0.f;

    uint4 pa[4];
    float pb[2][4];

    auto ldgA = [&](int c) {
        #pragma unroll
        for (int jj = 0; jj < 4; jj++) {
            int f = jj * 256 + tid;
            int row = f >> 2, c4 = f & 3;
            pa[jj] = *(const uint4*)&Wt[(size_t)(mbb + row) * K + c * 16 + c4 * 4];
        }
    };

    auto ldgB = [&](int c) {
        const int k0 = c * 16;
        #pragma unroll
        for (int i = 0; i < 2; i++) {
            const int kg = k0 + wid * 2 + i;
            float sc, sh;
            if (MODE == 1) { sc = g_scale2[kg]; sh = g_shift2[kg]; }
            const float* src = &Bn[(size_t)kg * HW + pb0 + lane];
            #pragma unroll
            for (int p = 0; p < 4; p++) {
                int pix = pb0 + lane + p * 32;
                float v = 0.f;
                if (pix < HW) {
                    v = src[p * 32];
                    if (MODE == 1) v = fmaxf(fmaf(sc, v, sh), 0.f);
                }
                pb[i][p] = v;
            }
        }
    };

    auto sts = [&](int buf) {
        uint32_t* A = smem + buf * BUF_U32;
        uint32_t* B = A + 4096;
        #pragma unroll
        for (int jj = 0; jj < 4; jj++) {
            int f = jj * 256 + tid;
            int row = f >> 2, c4 = f & 3;
            int mbl = row >> 4, lrr = row & 7, rsel = (row >> 3) & 1;
            int ks = c4 >> 1, csel = c4 & 1;
            uint32_t* base = &A[(mbl * 2 + ks) * 128 + rsel + 2 * csel];
            const uint32_t* v = &pa[jj].x;
            #pragma unroll
            for (int lcc = 0; lcc < 4; lcc++)
                base[((lrr * 4) | (lcc ^ ks)) * 4] = v[lcc];
        }
        #pragma unroll
        for (int i = 0; i < 2; i++) {
            int kin = wid * 2 + i;
            int ks = kin >> 3, j = (kin >> 2) & 1, lcb = kin & 3;
            #pragma unroll
            for (int p = 0; p < 4; p++) {
                int pxl = lane + p * 32;
                int qb = pxl >> 3, n8 = pxl & 7;
                B[((qb * 2 + ks) * 32 + ((n8 * 4 + lcb) ^ (qb & 3))) * 2 + j] =
                    f2tf32(pb[i][p]);
            }
        }
    };

    auto compute = [&](int buf) {
        const uint32_t* A = smem + buf * BUF_U32;
        const uint32_t* B = A + 4096;
        #pragma unroll
        for (int ks = 0; ks < 2; ks++) {
            uint32_t a[4][4], b[8][2];
            #pragma unroll
            for (int m = 0; m < 4; m++) {
                int mbl = (wid & 3) * 4 + m;
                uint4 t = *(const uint4*)&A[((mbl * 2 + ks) * 32 + (lane ^ ks)) * 4];
                a[m][0] = t.x; a[m][1] = t.y; a[m][2] = t.z; a[m][3] = t.w;
            }
            #pragma unroll
            for (int q = 0; q < 8; q++) {
                int qb = (wid >> 2) * 8 + q;
                uint2 t = *(const uint2*)&B[((qb * 2 + ks) * 32 + (lane ^ (qb & 3))) * 2];
                b[q][0] = t.x; b[q][1] = t.y;
            }
            #pragma unroll
            for (int m = 0; m < 4; m++)
                #pragma unroll
                for (int q = 0; q < 8; q++)
                    mma_tf32(acc[m][q], a[m], b[q]);
        }
    };

    ldgA(0); ldgB(0);
    sts(0);
    __syncthreads();
    for (int c = 0; c < CH; c++) {
        if (c + 1 < CH) { ldgA(c + 1); ldgB(c + 1); }
        compute(c & 1);
        if (c + 1 < CH) sts((c + 1) & 1);
        __syncthreads();
    }

    // ---- BN partial stats (deterministic fixed-order reduction) ----
    float2* s_st = (float2*)smem;           // [2 pxg][256 rows]
    const int pxg = wid >> 2;
    #pragma unroll
    for (int m = 0; m < 4; m++) {
        float sl = 0.f, ql = 0.f, shi = 0.f, qhi = 0.f;
        #pragma unroll
        for (int q = 0; q < 8; q++) {
            const float* a = acc[m][q];
            sl += a[0] + a[1];
            ql += a[0] * a[0] + a[1] * a[1];
            shi += a[2] + a[3];
            qhi += a[2] * a[2] + a[3] * a[3];
        }
        #pragma unroll
        for (int o = 1; o < 4; o <<= 1) {
            sl  += __shfl_xor_sync(0xffffffffu, sl,  o);
            ql  += __shfl_xor_sync(0xffffffffu, ql,  o);
            shi += __shfl_xor_sync(0xffffffffu, shi, o);
            qhi += __shfl_xor_sync(0xffffffffu, qhi, o);
        }
        if (lc == 0) {
            s_st[pxg * 256 + wm + m * 16 + lr]     = make_float2(sl, ql);
            s_st[pxg * 256 + wm + m * 16 + lr + 8] = make_float2(shi, qhi);
        }
    }
    __syncthreads();
    {
        float2 a = s_st[tid], b = s_st[256 + tid];
        Part[(size_t)(mbb + tid) * 800 + n * 25 + blockIdx.x] =
            make_float2(a.x + b.x, a.y + b.y);
    }

    // ---- output STG ----
    float* Cp = Cdst + (size_t)n * Mtot * HW;
    #pragma unroll
    for (int m = 0; m < 4; m++) {
        #pragma unroll
        for (int q = 0; q < 8; q++) {
            int row = mbb + wm + m * 16 + lr;
            int pix = pb0 + wn + q * 8 + lc * 2;
            if (pix < HW) {
                *(float2*)&Cp[(size_t)row * HW + pix] =
                    make_float2(acc[m][q][0], acc[m][q][1]);
                *(float2*)&Cp[(size_t)(row + 8) * HW + pix] =
                    make_float2(acc[m][q][2], acc[m][q][3]);
            }
        }
    }
}

// ---------------------------------------------------------------------------
// Finalize BN: reduce per-CTA partials (fixed order) -> scale/shift
// ---------------------------------------------------------------------------
template<int WHICH>
__global__ void __launch_bounds__(256) bn_fin_kernel(const float* __restrict__ gamma,
                                                     const float* __restrict__ beta)
{
    constexpr int PARTS = (WHICH == 2) ? 224 : 800;
    const float2* __restrict__ part =
        (WHICH == 1) ? g_part1 : (WHICH == 2) ? g_part2 : g_part3;
    float* __restrict__ scale = (WHICH == 1) ? g_scale1 : (WHICH == 2) ? g_scale2 : g_scale3;
    float* __restrict__ shift = (WHICH == 1) ? g_shift1 : (WHICH == 2) ? g_shift2 : g_shift3;

    const int c = blockIdx.x;
    float s = 0.f, sq = 0.f;
    for (int i = threadIdx.x; i < PARTS; i += 256) {
        float2 p = part[(size_t)c * PARTS + i];
        s += p.x; sq += p.y;
    }
    __shared__ float sh_s[8], sh_q[8];
    #pragma unroll
    for (int o = 16; o; o >>= 1) {
        s  += __shfl_down_sync(0xffffffffu, s,  o);
        sq += __shfl_down_sync(0xffffffffu, sq, o);
    }
    int lane = threadIdx.x & 31, wrp = threadIdx.x >> 5;
    if (lane == 0) { sh_s[wrp] = s; sh_q[wrp] = sq; }
    __syncthreads();
    if (threadIdx.x < 8) {
        s = sh_s[threadIdx.x]; sq = sh_q[threadIdx.x];
        #pragma unroll
        for (int o = 4; o; o >>= 1) {
            s  += __shfl_down_sync(0xffu, s,  o);
            sq += __shfl_down_sync(0xffu, sq, o);
        }
        if (threadIdx.x == 0) {
            const float inv = 1.f / (float)NTOT;
            float mean = s * inv;
            float var  = sq * inv - mean * mean;
            float sc = gamma[c] * rsqrtf(var + 1e-5f);
            scale[c] = sc;
            shift[c] = beta[c] - mean * sc;
        }
    }
}

// ---------------------------------------------------------------------------
// Grouped 3x3 conv as tf32 mma.sync implicit GEMM + fused BN2 partials.
// ---------------------------------------------------------------------------
#define CI_STRIDE 584
#define W_STRIDE  148

__global__ void __launch_bounds__(256) conv3x3_tc_kernel(const float* __restrict__ w3)
{
    __shared__ uint32_t s_in[16 * CI_STRIDE];
    __shared__ uint32_t s_w[16 * W_STRIDE];
    __shared__ float2 s3[8][16];

    const int tid = threadIdx.x;
    const int warp = tid >> 5, lane = tid & 31;
    const int lr = lane >> 2, lc = lane & 3;
    const int y0 = blockIdx.x * 8;
    const int g  = blockIdx.y;
    const int n  = blockIdx.z;

    for (int i = tid; i < 16 * 144; i += 256) {
        int co = i / 144, rem = i % 144;
        int ci = rem / 9, tap = rem % 9;
        s_w[co * W_STRIDE + tap * 16 + ci] = f2tf32(w3[(g * 16 + co) * 144 + rem]);
    }
    const float* src = g_y1 + (size_t)(n * CD + g * 16) * HW;
    for (int i = tid; i < 16 * 580; i += 256) {
        int ci = i / 580, r = i % 580;
        int yy = r / 58, xx = r % 58;
        int gy = y0 + yy - 1, gx = xx - 1;
        float v = 0.f;
        if (gy >= 0 && gy < H && gx >= 0 && gx < W) {
            int cg = g * 16 + ci;
            v = fmaxf(fmaf(g_scale1[cg], src[(size_t)ci * HW + gy * W + gx], g_shift1[cg]), 0.f);
        }
        s_in[ci * CI_STRIDE + yy * 58 + xx] = f2tf32(v);
    }
    __syncthreads();

    float acc[7][4];
    #pragma unroll
    for (int f = 0; f < 7; f++)
        #pragma unroll
        for (int r = 0; r < 4; r++) acc[f][r] = 0.f;

    const int row = warp;

    #pragma unroll
    for (int kk = 0; kk < 18; kk++) {
        const int tap = kk >> 1, ci0 = (kk & 1) * 8;
        const int dy = tap / 3, dx = tap % 3;
        uint32_t a[4];
        const uint32_t* ab = &s_w[lr * W_STRIDE + kk * 8 + lc];
        a[0] = ab[0];
        a[1] = ab[8 * W_STRIDE];
        a[2] = ab[4];
        a[3] = ab[8 * W_STRIDE + 4];
        const uint32_t* bb = &s_in[(ci0 + lc) * CI_STRIDE + (row + dy) * 58 + dx + lr];
        #pragma unroll
        for (int f = 0; f < 7; f++) {
            uint32_t b[2];
            b[0] = bb[f * 8];
            b[1] = bb[f * 8 + 4 * CI_STRIDE];
            mma_tf32(acc[f], a, b);
        }
    }

    // ---- BN2 partials (56 px per warp-row, fixed order) ----
    {
        float sl = 0.f, ql = 0.f, shi = 0.f, qhi = 0.f;
        #pragma unroll
        for (int f = 0; f < 7; f++) {
            sl += acc[f][0] + acc[f][1];
            ql += acc[f][0] * acc[f][0] + acc[f][1] * acc[f][1];
            shi += acc[f][2] + acc[f][3];
            qhi += acc[f][2] * acc[f][2] + acc[f][3] * acc[f][3];
        }
        #pragma unroll
        for (int o = 1; o < 4; o <<= 1) {
            sl  += __shfl_xor_sync(0xffffffffu, sl,  o);
            ql  += __shfl_xor_sync(0xffffffffu, ql,  o);
            shi += __shfl_xor_sync(0xffffffffu, shi, o);
            qhi += __shfl_xor_sync(0xffffffffu, qhi, o);
        }
        if (lc == 0) {
            s3[warp][lr]     = make_float2(sl, ql);
            s3[warp][lr + 8] = make_float2(shi, qhi);
        }
    }
    __syncthreads();
    if (tid < 16) {
        float s = 0.f, q = 0.f;
        #pragma unroll
        for (int w = 0; w < 8; w++) { float2 p = s3[w][tid]; s += p.x; q += p.y; }
        g_part2[(size_t)(g * 16 + tid) * 224 + n * 7 + blockIdx.x] = make_float2(s, q);
    }

    float* dst = g_y2 + (size_t)(n * CD + g * 16) * HW + (size_t)(y0 + row) * W;
    #pragma unroll
    for (int f = 0; f < 7; f++) {
        int px = f * 8 + lc * 2;
        *(float2*)&dst[(size_t)lr * HW + px] = make_float2(acc[f][0], acc[f][1]);
        *(float2*)&dst[(size_t)(lr + 8) * HW + px] = make_float2(acc[f][2], acc[f][3]);
    }
}

// ---------------------------------------------------------------------------
// Final: out = relu(scale3*y3 + shift3 + x)
// ---------------------------------------------------------------------------
__global__ void __launch_bounds__(256) final_kernel(const float* __restrict__ x,
                                                    float* __restrict__ out)
{
    int i = blockIdx.x * 256 + threadIdx.x;
    int c = (i / HW4) & (COUT - 1);
    float4 v  = ((const float4*)g_y3)[i];
    float4 xv = ((const float4*)x)[i];
    float sc = g_scale3[c], sh = g_shift3[c];
    float4 o;
    o.x = fmaxf(fmaf(sc, v.x, sh) + xv.x, 0.f);
    o.y = fmaxf(fmaf(sc, v.y, sh) + xv.y, 0.f);
    o.z = fmaxf(fmaf(sc, v.z, sh) + xv.z, 0.f);
    o.w = fmaxf(fmaf(sc, v.w, sh) + xv.w, 0.f);
    ((float4*)out)[i] = o;
}

// ---------------------------------------------------------------------------
extern "C" void kernel_launch(void* const* d_in, const int* in_sizes, int n_in,
                              void* d_out, int out_size)
{
    const float* x  = (const float*)d_in[0];
    const float* w1 = (const float*)d_in[1];
    const float* g1 = (const float*)d_in[2];
    const float* b1 = (const float*)d_in[3];
    const float* w3 = (const float*)d_in[4];
    const float* g3 = (const float*)d_in[5];
    const float* b3 = (const float*)d_in[6];
    const float* wa = (const float*)d_in[7];
    const float* ga = (const float*)d_in[8];
    const float* ba = (const float*)d_in[9];
    float* out = (float*)d_out;

    cudaFuncSetAttribute(mma_gemm_kernel<0>, cudaFuncAttributeMaxDynamicSharedMemorySize, GEMM_SMEM);
    cudaFuncSetAttribute(mma_gemm_kernel<1>, cudaFuncAttributeMaxDynamicSharedMemorySize, GEMM_SMEM);

    uint32_t* cw1;  cudaGetSymbolAddress((void**)&cw1, g_cw1);
    uint32_t* cwa;  cudaGetSymbolAddress((void**)&cwa, g_cwa);
    cvt_kernel<<<512, 256>>>(w1, cw1, CD * CIN);
    cvt_kernel<<<512, 256>>>(wa, cwa, COUT * CD);

    // conv1: y1 = w1 @ x   (M=512 -> 2 M-tiles of 256, K=256)
    mma_gemm_kernel<0><<<dim3(25, 2, NB), 256, GEMM_SMEM>>>(x);
    bn_fin_kernel<1><<<CD, 256>>>(g1, b1);
    // grouped 3x3 (tensor cores) with fused BN1+ReLU on load, BN2 partials out
    conv3x3_tc_kernel<<<dim3(7, GRP, NB), 256>>>(w3);
    bn_fin_kernel<2><<<CD, 256>>>(g3, b3);
    // convA: y3 = wa @ relu(bn2(y2))  (M=256 -> 1 M-tile, K=512)
    mma_gemm_kernel<1><<<dim3(25, 1, NB), 256, GEMM_SMEM>>>(nullptr);
    bn_fin_kernel<3><<<COUT, 256>>>(ga, ba);
    // final: relu(bn3(y3) + x)
    final_kernel<<<(NB * COUT * HW4) / 256, 256>>>(x, out);
}

// round 8
// speedup vs baseline: 2.7129x; 1.3642x over previous
#include <cuda_runtime.h>
#include <cuda_fp16.h>
#include <cstdint>

// Problem constants
#define NB   32
#define CIN  256
#define CD   512
#define COUT 256
#define H    56
#define W    56
#define HW   3136          // 56*56
#define HW4  784           // HW/4
#define NTOT (NB*HW)       // 100352
#define GRP  32

// Scratch (allocation-free: __device__ globals)
__device__ __align__(16) float g_y1[NB * CD * HW];     // conv1 raw output
__device__ __align__(16) float g_y2[NB * CD * HW];     // conv3 raw output
__device__ __align__(16) float g_y3[NB * COUT * HW];   // convA raw output
__device__ float g_scale1[CD], g_shift1[CD];
__device__ float g_scale2[CD], g_shift2[CD];
__device__ float g_scale3[COUT], g_shift3[COUT];
// Per-CTA BN partial sums (sum, sumsq)
__device__ float2 g_part1[CD * 1568];    // conv1: 49 px-tiles * 32 imgs
__device__ float2 g_part2[CD * 224];     // conv3: 7 y-tiles * 32 imgs
__device__ float2 g_part3[COUT * 1568];  // convA
// Pre-converted fp16 weights in frag-permuted layout
__device__ __align__(16) uint32_t g_cw1h[CD * CIN / 2];
__device__ __align__(16) uint32_t g_cwah[COUT * CD / 2];

__device__ __forceinline__ uint32_t f2tf32(float f) {
    uint32_t u;
    asm("cvt.rna.tf32.f32 %0, %1;" : "=r"(u) : "f"(f));
    return u;
}

__device__ __forceinline__ void mma_tf32(float* c, const uint32_t* a, const uint32_t* b) {
    asm volatile(
        "mma.sync.aligned.m16n8k8.row.col.f32.tf32.tf32.f32 "
        "{%0,%1,%2,%3}, {%4,%5,%6,%7}, {%8,%9}, {%0,%1,%2,%3};"
        : "+f"(c[0]), "+f"(c[1]), "+f"(c[2]), "+f"(c[3])
        : "r"(a[0]), "r"(a[1]), "r"(a[2]), "r"(a[3]), "r"(b[0]), "r"(b[1]));
}

__device__ __forceinline__ void mma_f16(float* c, const uint32_t* a, const uint32_t* b) {
    asm volatile(
        "mma.sync.aligned.m16n8k16.row.col.f32.f16.f16.f32 "
        "{%0,%1,%2,%3}, {%4,%5,%6,%7}, {%8,%9}, {%0,%1,%2,%3};"
        : "+f"(c[0]), "+f"(c[1]), "+f"(c[2]), "+f"(c[3])
        : "r"(a[0]), "r"(a[1]), "r"(a[2]), "r"(a[3]), "r"(b[0]), "r"(b[1]));
}

// ---------------------------------------------------------------------------
// Weight prepass: fp32 -> half2, permuted into frag-ready uint4 blocks.
// Block (mt, ch) = 4096 u32 = one 256m x 32k tile.
// u32 at [(mbl*2+ks)*128 + lane*4 + w] = half2 of W[row][k], W[row][k+1] with
// row = mt*256 + mbl*16 + lr + (w&1)*8,  k = ch*32 + ks*16 + (w>>1)*8 + lc*2.
// ---------------------------------------------------------------------------
template<int MT, int KK>
__global__ void __launch_bounds__(256) cvtA_kernel(const float* __restrict__ w,
                                                   uint32_t* __restrict__ dst)
{
    constexpr int NCH = KK / 32;
    int u = blockIdx.x * 256 + threadIdx.x;
    int blk = u >> 12, r = u & 4095;
    int mt = blk / NCH, ch = blk % NCH;
    int fr = r >> 7, lane = (r >> 2) & 31, ww = r & 3;
    int mbl = fr >> 1, ks = fr & 1, lr = lane >> 2, lc = lane & 3;
    int row = mt * 256 + mbl * 16 + lr + (ww & 1) * 8;
    int k   = ch * 32 + ks * 16 + (ww >> 1) * 8 + lc * 2;
    __half2 h = __floats2half2_rn(w[(size_t)row * KK + k], w[(size_t)row * KK + k + 1]);
    dst[u] = *reinterpret_cast<uint32_t*>(&h);
}

// ---------------------------------------------------------------------------
// fp16 mma.sync 1x1-conv GEMM:  C[n][m][p] = sum_k W[m][k] * Act[n][k][p]
// MODE 0: conv1 (K=256, Act=x, out g_y1, partials -> g_part1)
// MODE 1: convA (K=512, Act=relu(bn2(g_y2)), out g_y3, partials -> g_part3)
// CTA tile 256m x 64px (HW = 49*64 exactly -> no predication), BK=32,
// double-buffered. 256 threads, 8 warps (4m x 2px), warp tile 64m x 32px.
// A: frag-permuted uint4 blocks (prepass) -> LDG.128/STS.128/LDS.128.
// B: half2[kp][px] stride 72 (==8 mod 32): conflict-free STS.32 + frag LDS.32.
// ---------------------------------------------------------------------------
#define PXS 72                             // B px-stride in u32 (64 used)
#define BUF_U32 (4096 + 16 * PXS)          // A 4096 + B 1152 = 5248
#define GEMM_SMEM (2 * BUF_U32 * 4)        // 41984 B

template<int MODE>
__global__ void __launch_bounds__(256) mma_gemm_kernel(const float* __restrict__ Bx)
{
    constexpr int K = (MODE == 0) ? CIN : CD;
    constexpr int CH = K / 32;
    constexpr int Mtot = (MODE == 0) ? CD : COUT;
    const uint32_t* __restrict__ Wp = (MODE == 0) ? g_cw1h : g_cwah;
    const float* __restrict__ Bsrc = (MODE == 0) ? Bx : g_y2;
    float* __restrict__ Cdst = (MODE == 0) ? g_y1 : g_y3;
    float2* __restrict__ Part = (MODE == 0) ? g_part1 : g_part3;

    extern __shared__ uint32_t smem[];

    const int tid = threadIdx.x;
    const int wid = tid >> 5, lane = tid & 31;
    const int lr = lane >> 2, lc = lane & 3;
    const int wm = (wid & 3) * 64;          // warp m offset
    const int wn = (wid >> 2) * 32;         // warp px offset
    const int pb0 = blockIdx.x * 64;
    const int mbb = blockIdx.y * 256;
    const int n   = blockIdx.z;
    const float* Bn = Bsrc + (size_t)n * K * HW;
    const uint32_t* Ablk = Wp + ((size_t)blockIdx.y * CH) * 4096;

    float acc[4][4][4];
    #pragma unroll
    for (int m = 0; m < 4; m++)
        #pragma unroll
        for (int q = 0; q < 4; q++)
            #pragma unroll
            for (int r = 0; r < 4; r++) acc[m][q][r] = 0.f;

    uint4 pa[4];
    float pb[4][2];                          // [krow i][px group p]

    auto ldgA = [&](int c) {
        const uint32_t* src = Ablk + c * 4096;
        #pragma unroll
        for (int jj = 0; jj < 4; jj++)
            pa[jj] = *(const uint4*)&src[jj * 1024 + tid * 4];
    };

    auto ldgB = [&](int c) {
        const int k0 = c * 32;
        #pragma unroll
        for (int i = 0; i < 4; i++) {
            const int kg = k0 + wid * 4 + i;
            float sc, sh;
            if (MODE == 1) { sc = g_scale2[kg]; sh = g_shift2[kg]; }
            const float* src = &Bn[(size_t)kg * HW + pb0 + lane];
            #pragma unroll
            for (int p = 0; p < 2; p++) {
                float v = src[p * 32];
                if (MODE == 1) v = fmaxf(fmaf(sc, v, sh), 0.f);
                pb[i][p] = v;
            }
        }
    };

    auto sts = [&](int buf) {
        uint32_t* A = smem + buf * BUF_U32;
        uint32_t* B = A + 4096;
        #pragma unroll
        for (int jj = 0; jj < 4; jj++)
            *(uint4*)&A[jj * 1024 + tid * 4] = pa[jj];
        #pragma unroll
        for (int j = 0; j < 2; j++) {
            #pragma unroll
            for (int p = 0; p < 2; p++) {
                __half2 h = __floats2half2_rn(pb[2 * j][p], pb[2 * j + 1][p]);
                B[(wid * 2 + j) * PXS + lane + p * 32] = *reinterpret_cast<uint32_t*>(&h);
            }
        }
    };

    auto compute = [&](int buf) {
        const uint32_t* A = smem + buf * BUF_U32;
        const uint32_t* B = A + 4096;
        #pragma unroll
        for (int ks = 0; ks < 2; ks++) {
            uint32_t a[4][4], b[4][2];
            #pragma unroll
            for (int m = 0; m < 4; m++) {
                int mbl = (wid & 3) * 4 + m;
                uint4 t = *(const uint4*)&A[(mbl * 2 + ks) * 128 + lane * 4];
                a[m][0] = t.x; a[m][1] = t.y; a[m][2] = t.z; a[m][3] = t.w;
            }
            #pragma unroll
            for (int q = 0; q < 4; q++) {
                b[q][0] = B[(ks * 8 + lc) * PXS + wn + q * 8 + lr];
                b[q][1] = B[(ks * 8 + 4 + lc) * PXS + wn + q * 8 + lr];
            }
            #pragma unroll
            for (int m = 0; m < 4; m++)
                #pragma unroll
                for (int q = 0; q < 4; q++)
                    mma_f16(acc[m][q], a[m], b[q]);
        }
    };

    ldgA(0); ldgB(0);
    sts(0);
    __syncthreads();
    for (int c = 0; c < CH; c++) {
        if (c + 1 < CH) { ldgA(c + 1); ldgB(c + 1); }
        compute(c & 1);
        if (c + 1 < CH) sts((c + 1) & 1);
        __syncthreads();
    }

    // ---- BN partial stats (deterministic fixed-order reduction) ----
    float2* s_st = (float2*)smem;           // [2 pxg][256 rows]
    const int pxg = wid >> 2;
    #pragma unroll
    for (int m = 0; m < 4; m++) {
        float sl = 0.f, ql = 0.f, shi = 0.f, qhi = 0.f;
        #pragma unroll
        for (int q = 0; q < 4; q++) {
            const float* a = acc[m][q];
            sl += a[0] + a[1];
            ql += a[0] * a[0] + a[1] * a[1];
            shi += a[2] + a[3];
            qhi += a[2] * a[2] + a[3] * a[3];
        }
        #pragma unroll
        for (int o = 1; o < 4; o <<= 1) {
            sl  += __shfl_xor_sync(0xffffffffu, sl,  o);
            ql  += __shfl_xor_sync(0xffffffffu, ql,  o);
            shi += __shfl_xor_sync(0xffffffffu, shi, o);
            qhi += __shfl_xor_sync(0xffffffffu, qhi, o);
        }
        if (lc == 0) {
            s_st[pxg * 256 + wm + m * 16 + lr]     = make_float2(sl, ql);
            s_st[pxg * 256 + wm + m * 16 + lr + 8] = make_float2(shi, qhi);
        }
    }
    __syncthreads();
    {
        float2 a = s_st[tid], b = s_st[256 + tid];
        Part[(size_t)(mbb + tid) * 1568 + n * 49 + blockIdx.x] =
            make_float2(a.x + b.x, a.y + b.y);
    }

    // ---- output STG (no bounds checks: 49*64 == HW) ----
    float* Cp = Cdst + (size_t)n * Mtot * HW;
    #pragma unroll
    for (int m = 0; m < 4; m++) {
        #pragma unroll
        for (int q = 0; q < 4; q++) {
            int row = mbb + wm + m * 16 + lr;
            int pix = pb0 + wn + q * 8 + lc * 2;
            *(float2*)&Cp[(size_t)row * HW + pix] =
                make_float2(acc[m][q][0], acc[m][q][1]);
            *(float2*)&Cp[(size_t)(row + 8) * HW + pix] =
                make_float2(acc[m][q][2], acc[m][q][3]);
        }
    }
}

// ---------------------------------------------------------------------------
// Finalize BN: reduce per-CTA partials (fixed order) -> scale/shift
// ---------------------------------------------------------------------------
template<int WHICH>
__global__ void __launch_bounds__(256) bn_fin_kernel(const float* __restrict__ gamma,
                                                     const float* __restrict__ beta)
{
    constexpr int PARTS = (WHICH == 2) ? 224 : 1568;
    const float2* __restrict__ part =
        (WHICH == 1) ? g_part1 : (WHICH == 2) ? g_part2 : g_part3;
    float* __restrict__ scale = (WHICH == 1) ? g_scale1 : (WHICH == 2) ? g_scale2 : g_scale3;
    float* __restrict__ shift = (WHICH == 1) ? g_shift1 : (WHICH == 2) ? g_shift2 : g_shift3;

    const int c = blockIdx.x;
    float s = 0.f, sq = 0.f;
    for (int i = threadIdx.x; i < PARTS; i += 256) {
        float2 p = part[(size_t)c * PARTS + i];
        s += p.x; sq += p.y;
    }
    __shared__ float sh_s[8], sh_q[8];
    #pragma unroll
    for (int o = 16; o; o >>= 1) {
        s  += __shfl_down_sync(0xffffffffu, s,  o);
        sq += __shfl_down_sync(0xffffffffu, sq, o);
    }
    int lane = threadIdx.x & 31, wrp = threadIdx.x >> 5;
    if (lane == 0) { sh_s[wrp] = s; sh_q[wrp] = sq; }
    __syncthreads();
    if (threadIdx.x < 8) {
        s = sh_s[threadIdx.x]; sq = sh_q[threadIdx.x];
        #pragma unroll
        for (int o = 4; o; o >>= 1) {
            s  += __shfl_down_sync(0xffu, s,  o);
            sq += __shfl_down_sync(0xffu, sq, o);
        }
        if (threadIdx.x == 0) {
            const float inv = 1.f / (float)NTOT;
            float mean = s * inv;
            float var  = sq * inv - mean * mean;
            float sc = gamma[c] * rsqrtf(var + 1e-5f);
            scale[c] = sc;
            shift[c] = beta[c] - mean * sc;
        }
    }
}

// ---------------------------------------------------------------------------
// Grouped 3x3 conv as tf32 mma.sync implicit GEMM + fused BN2 partials.
// ---------------------------------------------------------------------------
#define CI_STRIDE 584
#define W_STRIDE  148

__global__ void __launch_bounds__(256) conv3x3_tc_kernel(const float* __restrict__ w3)
{
    __shared__ uint32_t s_in[16 * CI_STRIDE];
    __shared__ uint32_t s_w[16 * W_STRIDE];
    __shared__ float2 s3[8][16];

    const int tid = threadIdx.x;
    const int warp = tid >> 5, lane = tid & 31;
    const int lr = lane >> 2, lc = lane & 3;
    const int y0 = blockIdx.x * 8;
    const int g  = blockIdx.y;
    const int n  = blockIdx.z;

    for (int i = tid; i < 16 * 144; i += 256) {
        int co = i / 144, rem = i % 144;
        int ci = rem / 9, tap = rem % 9;
        s_w[co * W_STRIDE + tap * 16 + ci] = f2tf32(w3[(g * 16 + co) * 144 + rem]);
    }
    const float* src = g_y1 + (size_t)(n * CD + g * 16) * HW;
    for (int i = tid; i < 16 * 580; i += 256) {
        int ci = i / 580, r = i % 580;
        int yy = r / 58, xx = r % 58;
        int gy = y0 + yy - 1, gx = xx - 1;
        float v = 0.f;
        if (gy >= 0 && gy < H && gx >= 0 && gx < W) {
            int cg = g * 16 + ci;
            v = fmaxf(fmaf(g_scale1[cg], src[(size_t)ci * HW + gy * W + gx], g_shift1[cg]), 0.f);
        }
        s_in[ci * CI_STRIDE + yy * 58 + xx] = f2tf32(v);
    }
    __syncthreads();

    float acc[7][4];
    #pragma unroll
    for (int f = 0; f < 7; f++)
        #pragma unroll
        for (int r = 0; r < 4; r++) acc[f][r] = 0.f;

    const int row = warp;

    #pragma unroll
    for (int kk = 0; kk < 18; kk++) {
        const int tap = kk >> 1, ci0 = (kk & 1) * 8;
        const int dy = tap / 3, dx = tap % 3;
        uint32_t a[4];
        const uint32_t* ab = &s_w[lr * W_STRIDE + kk * 8 + lc];
        a[0] = ab[0];
        a[1] = ab[8 * W_STRIDE];
        a[2] = ab[4];
        a[3] = ab[8 * W_STRIDE + 4];
        const uint32_t* bb = &s_in[(ci0 + lc) * CI_STRIDE + (row + dy) * 58 + dx + lr];
        #pragma unroll
        for (int f = 0; f < 7; f++) {
            uint32_t b[2];
            b[0] = bb[f * 8];
            b[1] = bb[f * 8 + 4 * CI_STRIDE];
            mma_tf32(acc[f], a, b);
        }
    }

    // ---- BN2 partials (fixed order) ----
    {
        float sl = 0.f, ql = 0.f, shi = 0.f, qhi = 0.f;
        #pragma unroll
        for (int f = 0; f < 7; f++) {
            sl += acc[f][0] + acc[f][1];
            ql += acc[f][0] * acc[f][0] + acc[f][1] * acc[f][1];
            shi += acc[f][2] + acc[f][3];
            qhi += acc[f][2] * acc[f][2] + acc[f][3] * acc[f][3];
        }
        #pragma unroll
        for (int o = 1; o < 4; o <<= 1) {
            sl  += __shfl_xor_sync(0xffffffffu, sl,  o);
            ql  += __shfl_xor_sync(0xffffffffu, ql,  o);
            shi += __shfl_xor_sync(0xffffffffu, shi, o);
            qhi += __shfl_xor_sync(0xffffffffu, qhi, o);
        }
        if (lc == 0) {
            s3[warp][lr]     = make_float2(sl, ql);
            s3[warp][lr + 8] = make_float2(shi, qhi);
        }
    }
    __syncthreads();
    if (tid < 16) {
        float s = 0.f, q = 0.f;
        #pragma unroll
        for (int w = 0; w < 8; w++) { float2 p = s3[w][tid]; s += p.x; q += p.y; }
        g_part2[(size_t)(g * 16 + tid) * 224 + n * 7 + blockIdx.x] = make_float2(s, q);
    }

    float* dst = g_y2 + (size_t)(n * CD + g * 16) * HW + (size_t)(y0 + row) * W;
    #pragma unroll
    for (int f = 0; f < 7; f++) {
        int px = f * 8 + lc * 2;
        *(float2*)&dst[(size_t)lr * HW + px] = make_float2(acc[f][0], acc[f][1]);
        *(float2*)&dst[(size_t)(lr + 8) * HW + px] = make_float2(acc[f][2], acc[f][3]);
    }
}

// ---------------------------------------------------------------------------
// Final: out = relu(scale3*y3 + shift3 + x)
// ---------------------------------------------------------------------------
__global__ void __launch_bounds__(256) final_kernel(const float* __restrict__ x,
                                                    float* __restrict__ out)
{
    int i = blockIdx.x * 256 + threadIdx.x;
    int c = (i / HW4) & (COUT - 1);
    float4 v  = ((const float4*)g_y3)[i];
    float4 xv = ((const float4*)x)[i];
    float sc = g_scale3[c], sh = g_shift3[c];
    float4 o;
    o.x = fmaxf(fmaf(sc, v.x, sh) + xv.x, 0.f);
    o.y = fmaxf(fmaf(sc, v.y, sh) + xv.y, 0.f);
    o.z = fmaxf(fmaf(sc, v.z, sh) + xv.z, 0.f);
    o.w = fmaxf(fmaf(sc, v.w, sh) + xv.w, 0.f);
    ((float4*)out)[i] = o;
}

// ---------------------------------------------------------------------------
extern "C" void kernel_launch(void* const* d_in, const int* in_sizes, int n_in,
                              void* d_out, int out_size)
{
    const float* x  = (const float*)d_in[0];
    const float* w1 = (const float*)d_in[1];
    const float* g1 = (const float*)d_in[2];
    const float* b1 = (const float*)d_in[3];
    const float* w3 = (const float*)d_in[4];
    const float* g3 = (const float*)d_in[5];
    const float* b3 = (const float*)d_in[6];
    const float* wa = (const float*)d_in[7];
    const float* ga = (const float*)d_in[8];
    const float* ba = (const float*)d_in[9];
    float* out = (float*)d_out;

    cudaFuncSetAttribute(mma_gemm_kernel<0>, cudaFuncAttributeMaxDynamicSharedMemorySize, GEMM_SMEM);
    cudaFuncSetAttribute(mma_gemm_kernel<1>, cudaFuncAttributeMaxDynamicSharedMemorySize, GEMM_SMEM);

    uint32_t* cw1h;  cudaGetSymbolAddress((void**)&cw1h, g_cw1h);
    uint32_t* cwah;  cudaGetSymbolAddress((void**)&cwah, g_cwah);
    cvtA_kernel<512, 256><<<256, 256>>>(w1, cw1h);
    cvtA_kernel<256, 512><<<256, 256>>>(wa, cwah);

    // conv1: y1 = w1 @ x   (M=512 -> 2 M-tiles of 256, K=256, 49 px-tiles)
    mma_gemm_kernel<0><<<dim3(49, 2, NB), 256, GEMM_SMEM>>>(x);
    bn_fin_kernel<1><<<CD, 256>>>(g1, b1);
    // grouped 3x3 (tf32 tensor cores) with fused BN1+ReLU on load, BN2 partials
    conv3x3_tc_kernel<<<dim3(7, GRP, NB), 256>>>(w3);
    bn_fin_kernel<2><<<CD, 256>>>(g3, b3);
    // convA: y3 = wa @ relu(bn2(y2))  (M=256 -> 1 M-tile, K=512)
    mma_gemm_kernel<1><<<dim3(49, 1, NB), 256, GEMM_SMEM>>>(nullptr);
    bn_fin_kernel<3><<<COUT, 256>>>(ga, ba);
    // final: relu(bn3(y3) + x)
    final_kernel<<<(NB * COUT * HW4) / 256, 256>>>(x, out);
}

// round 10
// speedup vs baseline: 3.2525x; 1.1989x over previous
#include <cuda_runtime.h>
#include <cuda_fp16.h>
#include <cstdint>

// Problem constants
#define NB   32
#define CIN  256
#define CD   512
#define COUT 256
#define H    56
#define W    56
#define HW   3136          // 56*56
#define HW4  784           // HW/4
#define NTOT (NB*HW)       // 100352
#define GRP  32

// Scratch (allocation-free: __device__ globals)
__device__ __align__(16) __half g_y1h[NB * CD * HW];   // conv1 raw output (fp16)
__device__ __align__(16) __half g_y2h[NB * CD * HW];   // conv3 raw output (fp16)
__device__ __align__(16) float  g_y3[NB * COUT * HW];  // convA raw output (fp32)
__device__ float g_scale1[CD], g_shift1[CD];
__device__ float g_scale2[CD], g_shift2[CD];
__device__ float g_scale3[COUT], g_shift3[COUT];
// Per-CTA BN partial sums (sum, sumsq) from fp32 accumulators
__device__ float2 g_part1[CD * 1568];    // conv1: 49 px-tiles * 32 imgs
__device__ float2 g_part2[CD * 224];     // conv3: 7 y-tiles * 32 imgs
__device__ float2 g_part3[COUT * 1568];  // convA
// Pre-converted fp16 weights in frag-permuted layout
__device__ __align__(16) uint32_t g_cw1h[CD * CIN / 2];
__device__ __align__(16) uint32_t g_cwah[COUT * CD / 2];

__device__ __forceinline__ uint32_t h2bits(__half2 h) {
    return *reinterpret_cast<uint32_t*>(&h);
}

__device__ __forceinline__ void mma_f16(float* c, const uint32_t* a, const uint32_t* b) {
    asm volatile(
        "mma.sync.aligned.m16n8k16.row.col.f32.f16.f16.f32 "
        "{%0,%1,%2,%3}, {%4,%5,%6,%7}, {%8,%9}, {%0,%1,%2,%3};"
        : "+f"(c[0]), "+f"(c[1]), "+f"(c[2]), "+f"(c[3])
        : "r"(a[0]), "r"(a[1]), "r"(a[2]), "r"(a[3]), "r"(b[0]), "r"(b[1]));
}

// ---------------------------------------------------------------------------
// Weight prepass: fp32 -> half2, permuted into frag-ready uint4 blocks.
// ---------------------------------------------------------------------------
template<int MT, int KK>
__global__ void __launch_bounds__(256) cvtA_kernel(const float* __restrict__ w,
                                                   uint32_t* __restrict__ dst)
{
    constexpr int NCH = KK / 32;
    int u = blockIdx.x * 256 + threadIdx.x;
    int blk = u >> 12, r = u & 4095;
    int mt = blk / NCH, ch = blk % NCH;
    int fr = r >> 7, lane = (r >> 2) & 31, ww = r & 3;
    int mbl = fr >> 1, ks = fr & 1, lr = lane >> 2, lc = lane & 3;
    int row = mt * 256 + mbl * 16 + lr + (ww & 1) * 8;
    int k   = ch * 32 + ks * 16 + (ww >> 1) * 8 + lc * 2;
    __half2 h = __floats2half2_rn(w[(size_t)row * KK + k], w[(size_t)row * KK + k + 1]);
    dst[u] = h2bits(h);
}

// ---------------------------------------------------------------------------
// fp16 mma.sync 1x1-conv GEMM:  C[n][m][p] = sum_k W[m][k] * Act[n][k][p]
// MODE 0: conv1 (K=256, Act=x fp32, out g_y1h fp16, partials -> g_part1)
// MODE 1: convA (K=512, Act=relu(bn2(g_y2h)) fp16-in, out g_y3 fp32, -> g_part3)
// CTA tile 256m x 64px (HW = 49*64: no predication), BK=32, double-buffered.
// ---------------------------------------------------------------------------
#define PXS 72                             // B px-stride in u32 (64 used)
#define BUF_U32 (4096 + 16 * PXS)          // A 4096 + B 1152 = 5248
#define GEMM_SMEM (2 * BUF_U32 * 4)        // 41984 B

template<int MODE>
__global__ void __launch_bounds__(256) mma_gemm_kernel(const float* __restrict__ Bx)
{
    constexpr int K = (MODE == 0) ? CIN : CD;
    constexpr int CH = K / 32;
    const uint32_t* __restrict__ Wp = (MODE == 0) ? g_cw1h : g_cwah;
    float2* __restrict__ Part = (MODE == 0) ? g_part1 : g_part3;

    extern __shared__ uint32_t smem[];

    const int tid = threadIdx.x;
    const int wid = tid >> 5, lane = tid & 31;
    const int lr = lane >> 2, lc = lane & 3;
    const int wm = (wid & 3) * 64;
    const int wn = (wid >> 2) * 32;
    const int pb0 = blockIdx.x * 64;
    const int mbb = blockIdx.y * 256;
    const int n   = blockIdx.z;
    const uint32_t* Ablk = Wp + ((size_t)blockIdx.y * CH) * 4096;

    float acc[4][4][4];
    #pragma unroll
    for (int m = 0; m < 4; m++)
        #pragma unroll
        for (int q = 0; q < 4; q++)
            #pragma unroll
            for (int r = 0; r < 4; r++) acc[m][q][r] = 0.f;

    uint4 pa[4];
    float pb[4][2];                          // [krow i][px slot]

    auto ldgA = [&](int c) {
        const uint32_t* src = Ablk + c * 4096;
        #pragma unroll
        for (int jj = 0; jj < 4; jj++)
            pa[jj] = *(const uint4*)&src[jj * 1024 + tid * 4];
    };

    auto ldgB = [&](int c) {
        const int k0 = c * 32;
        #pragma unroll
        for (int i = 0; i < 4; i++) {
            const int kg = k0 + wid * 4 + i;
            if (MODE == 0) {
                const float* src = Bx + (size_t)n * K * HW + (size_t)kg * HW + pb0 + lane;
                pb[i][0] = src[0];
                pb[i][1] = src[32];
            } else {
                float sc = g_scale2[kg], sh = g_shift2[kg];
                const __half2* src2 = reinterpret_cast<const __half2*>(
                    g_y2h + (size_t)n * K * HW + (size_t)kg * HW + pb0);
                float2 f = __half22float2(src2[lane]);
                pb[i][0] = fmaxf(fmaf(sc, f.x, sh), 0.f);
                pb[i][1] = fmaxf(fmaf(sc, f.y, sh), 0.f);
            }
        }
    };

    auto sts = [&](int buf) {
        uint32_t* A = smem + buf * BUF_U32;
        uint32_t* B = A + 4096;
        #pragma unroll
        for (int jj = 0; jj < 4; jj++)
            *(uint4*)&A[jj * 1024 + tid * 4] = pa[jj];
        if (MODE == 0) {
            // px = lane + p*32
            #pragma unroll
            for (int j = 0; j < 2; j++)
                #pragma unroll
                for (int p = 0; p < 2; p++)
                    B[(wid * 2 + j) * PXS + lane + p * 32] =
                        h2bits(__floats2half2_rn(pb[2 * j][p], pb[2 * j + 1][p]));
        } else {
            // px = lane*2 + {0,1}
            #pragma unroll
            for (int j = 0; j < 2; j++) {
                uint2 w;
                w.x = h2bits(__floats2half2_rn(pb[2 * j][0], pb[2 * j + 1][0]));
                w.y = h2bits(__floats2half2_rn(pb[2 * j][1], pb[2 * j + 1][1]));
                *(uint2*)&B[(wid * 2 + j) * PXS + lane * 2] = w;
            }
        }
    };

    auto compute = [&](int buf) {
        const uint32_t* A = smem + buf * BUF_U32;
        const uint32_t* B = A + 4096;
        #pragma unroll
        for (int ks = 0; ks < 2; ks++) {
            uint32_t a[4][4], b[4][2];
            #pragma unroll
            for (int m = 0; m < 4; m++) {
                int mbl = (wid & 3) * 4 + m;
                uint4 t = *(const uint4*)&A[(mbl * 2 + ks) * 128 + lane * 4];
                a[m][0] = t.x; a[m][1] = t.y; a[m][2] = t.z; a[m][3] = t.w;
            }
            #pragma unroll
            for (int q = 0; q < 4; q++) {
                b[q][0] = B[(ks * 8 + lc) * PXS + wn + q * 8 + lr];
                b[q][1] = B[(ks * 8 + 4 + lc) * PXS + wn + q * 8 + lr];
            }
            #pragma unroll
            for (int m = 0; m < 4; m++)
                #pragma unroll
                for (int q = 0; q < 4; q++)
                    mma_f16(acc[m][q], a[m], b[q]);
        }
    };

    ldgA(0); ldgB(0);
    sts(0);
    __syncthreads();
    for (int c = 0; c < CH; c++) {
        if (c + 1 < CH) { ldgA(c + 1); ldgB(c + 1); }
        compute(c & 1);
        if (c + 1 < CH) sts((c + 1) & 1);
        __syncthreads();
    }

    // ---- BN partial stats (deterministic fixed-order reduction) ----
    float2* s_st = (float2*)smem;
    const int pxg = wid >> 2;
    #pragma unroll
    for (int m = 0; m < 4; m++) {
        float sl = 0.f, ql = 0.f, shi = 0.f, qhi = 0.f;
        #pragma unroll
        for (int q = 0; q < 4; q++) {
            const float* a = acc[m][q];
            sl += a[0] + a[1];
            ql += a[0] * a[0] + a[1] * a[1];
            shi += a[2] + a[3];
            qhi += a[2] * a[2] + a[3] * a[3];
        }
        #pragma unroll
        for (int o = 1; o < 4; o <<= 1) {
            sl  += __shfl_xor_sync(0xffffffffu, sl,  o);
            ql  += __shfl_xor_sync(0xffffffffu, ql,  o);
            shi += __shfl_xor_sync(0xffffffffu, shi, o);
            qhi += __shfl_xor_sync(0xffffffffu, qhi, o);
        }
        if (lc == 0) {
            s_st[pxg * 256 + wm + m * 16 + lr]     = make_float2(sl, ql);
            s_st[pxg * 256 + wm + m * 16 + lr + 8] = make_float2(shi, qhi);
        }
    }
    __syncthreads();
    {
        float2 a = s_st[tid], b = s_st[256 + tid];
        Part[(size_t)(mbb + tid) * 1568 + n * 49 + blockIdx.x] =
            make_float2(a.x + b.x, a.y + b.y);
    }

    // ---- output STG ----
    #pragma unroll
    for (int m = 0; m < 4; m++) {
        #pragma unroll
        for (int q = 0; q < 4; q++) {
            int row = mbb + wm + m * 16 + lr;
            int pix = pb0 + wn + q * 8 + lc * 2;
            if (MODE == 0) {
                __half* Cp = g_y1h + (size_t)n * CD * HW;
                *(__half2*)&Cp[(size_t)row * HW + pix] =
                    __floats2half2_rn(acc[m][q][0], acc[m][q][1]);
                *(__half2*)&Cp[(size_t)(row + 8) * HW + pix] =
                    __floats2half2_rn(acc[m][q][2], acc[m][q][3]);
            } else {
                float* Cp = g_y3 + (size_t)n * COUT * HW;
                *(float2*)&Cp[(size_t)row * HW + pix] =
                    make_float2(acc[m][q][0], acc[m][q][1]);
                *(float2*)&Cp[(size_t)(row + 8) * HW + pix] =
                    make_float2(acc[m][q][2], acc[m][q][3]);
            }
        }
    }
}

// ---------------------------------------------------------------------------
// Finalize BN: reduce per-CTA partials (fixed order) -> scale/shift
// ---------------------------------------------------------------------------
template<int WHICH>
__global__ void __launch_bounds__(256) bn_fin_kernel(const float* __restrict__ gamma,
                                                     const float* __restrict__ beta)
{
    constexpr int PARTS = (WHICH == 2) ? 224 : 1568;
    const float2* __restrict__ part =
        (WHICH == 1) ? g_part1 : (WHICH == 2) ? g_part2 : g_part3;
    float* __restrict__ scale = (WHICH == 1) ? g_scale1 : (WHICH == 2) ? g_scale2 : g_scale3;
    float* __restrict__ shift = (WHICH == 1) ? g_shift1 : (WHICH == 2) ? g_shift2 : g_shift3;

    const int c = blockIdx.x;
    float s = 0.f, sq = 0.f;
    for (int i = threadIdx.x; i < PARTS; i += 256) {
        float2 p = part[(size_t)c * PARTS + i];
        s += p.x; sq += p.y;
    }
    __shared__ float sh_s[8], sh_q[8];
    #pragma unroll
    for (int o = 16; o; o >>= 1) {
        s  += __shfl_down_sync(0xffffffffu, s,  o);
        sq += __shfl_down_sync(0xffffffffu, sq, o);
    }
    int lane = threadIdx.x & 31, wrp = threadIdx.x >> 5;
    if (lane == 0) { sh_s[wrp] = s; sh_q[wrp] = sq; }
    __syncthreads();
    if (threadIdx.x < 8) {
        s = sh_s[threadIdx.x]; sq = sh_q[threadIdx.x];
        #pragma unroll
        for (int o = 4; o; o >>= 1) {
            s  += __shfl_down_sync(0xffu, s,  o);
            sq += __shfl_down_sync(0xffu, sq, o);
        }
        if (threadIdx.x == 0) {
            const float inv = 1.f / (float)NTOT;
            float mean = s * inv;
            float var  = sq * inv - mean * mean;
            float sc = gamma[c] * rsqrtf(var + 1e-5f);
            scale[c] = sc;
            shift[c] = beta[c] - mean * sc;
        }
    }
}

// ---------------------------------------------------------------------------
// Grouped 3x3 conv as fp16 m16n8k16 implicit GEMM + fused BN2 partials.
// K = 144 ordered tap-major: kstep kk (0..8) = tap, 16 ci per step.
// smem: input packed half2 over ci pairs: s_in2[ci2][yy*58+xx], stride 584
// (== 8 mod 32 -> B-frag LDS conflict-free); weights s_w2[co][tap*8+ci2],
// stride 76 (lr*12+lc distinct mod 32 -> A-frag LDS conflict-free).
// ---------------------------------------------------------------------------
#define CI2_STRIDE 584
#define W2_STRIDE  76

__global__ void __launch_bounds__(256) conv3x3_tc_kernel(const float* __restrict__ w3)
{
    __shared__ uint32_t s_in2[8 * CI2_STRIDE];
    __shared__ uint32_t s_w2[16 * W2_STRIDE];
    __shared__ float2 s3[8][16];

    const int tid = threadIdx.x;
    const int warp = tid >> 5, lane = tid & 31;
    const int lr = lane >> 2, lc = lane & 3;
    const int y0 = blockIdx.x * 8;
    const int g  = blockIdx.y;
    const int n  = blockIdx.z;

    // weights: pack half2 over ci pairs, tap-major k
    for (int i = tid; i < 16 * 72; i += 256) {
        int co = i / 72, rem = i % 72;
        int tap = rem >> 3, ci2 = rem & 7;
        const float* wp = &w3[(size_t)(g * 16 + co) * 144 + tap];
        __half2 h = __floats2half2_rn(wp[(2 * ci2) * 9], wp[(2 * ci2 + 1) * 9]);
        s_w2[co * W2_STRIDE + tap * 8 + ci2] = h2bits(h);
    }
    // input tile: 8 ci2-planes x 10 x 58, BN1+ReLU fused, zero halo
    const __half* src = g_y1h + (size_t)(n * CD + g * 16) * HW;
    for (int i = tid; i < 8 * 580; i += 256) {
        int ci2 = i / 580, r = i % 580;
        int yy = r / 58, xx = r % 58;
        int gy = y0 + yy - 1, gx = xx - 1;
        float v0 = 0.f, v1 = 0.f;
        if (gy >= 0 && gy < H && gx >= 0 && gx < W) {
            int cg = g * 16 + ci2 * 2;
            int off = gy * W + gx;
            v0 = fmaxf(fmaf(g_scale1[cg],
                            __half2float(src[(size_t)(ci2 * 2) * HW + off]),
                            g_shift1[cg]), 0.f);
            v1 = fmaxf(fmaf(g_scale1[cg + 1],
                            __half2float(src[(size_t)(ci2 * 2 + 1) * HW + off]),
                            g_shift1[cg + 1]), 0.f);
        }
        s_in2[ci2 * CI2_STRIDE + yy * 58 + xx] = h2bits(__floats2half2_rn(v0, v1));
    }
    __syncthreads();

    float acc[7][4];
    #pragma unroll
    for (int f = 0; f < 7; f++)
        #pragma unroll
        for (int r = 0; r < 4; r++) acc[f][r] = 0.f;

    const int row = warp;

    #pragma unroll
    for (int kk = 0; kk < 9; kk++) {
        const int dy = kk / 3, dx = kk % 3;
        uint32_t a[4];
        const uint32_t* ab = &s_w2[lr * W2_STRIDE + kk * 8 + lc];
        a[0] = ab[0];
        a[1] = ab[8 * W2_STRIDE];
        a[2] = ab[4];
        a[3] = ab[8 * W2_STRIDE + 4];
        const uint32_t* bb = &s_in2[lc * CI2_STRIDE + (row + dy) * 58 + dx + lr];
        #pragma unroll
        for (int f = 0; f < 7; f++) {
            uint32_t b[2];
            b[0] = bb[f * 8];
            b[1] = bb[f * 8 + 4 * CI2_STRIDE];
            mma_f16(acc[f], a, b);
        }
    }

    // ---- BN2 partials (fixed order, fp32 accs) ----
    {
        float sl = 0.f, ql = 0.f, shi = 0.f, qhi = 0.f;
        #pragma unroll
        for (int f = 0; f < 7; f++) {
            sl += acc[f][0] + acc[f][1];
            ql += acc[f][0] * acc[f][0] + acc[f][1] * acc[f][1];
            shi += acc[f][2] + acc[f][3];
            qhi += acc[f][2] * acc[f][2] + acc[f][3] * acc[f][3];
        }
        #pragma unroll
        for (int o = 1; o < 4; o <<= 1) {
            sl  += __shfl_xor_sync(0xffffffffu, sl,  o);
            ql  += __shfl_xor_sync(0xffffffffu, ql,  o);
            shi += __shfl_xor_sync(0xffffffffu, shi, o);
            qhi += __shfl_xor_sync(0xffffffffu, qhi, o);
        }
        if (lc == 0) {
            s3[warp][lr]     = make_float2(sl, ql);
            s3[warp][lr + 8] = make_float2(shi, qhi);
        }
    }
    __syncthreads();
    if (tid < 16) {
        float s = 0.f, q = 0.f;
        #pragma unroll
        for (int w = 0; w < 8; w++) { float2 p = s3[w][tid]; s += p.x; q += p.y; }
        g_part2[(size_t)(g * 16 + tid) * 224 + n * 7 + blockIdx.x] = make_float2(s, q);
    }

    __half* dst = g_y2h + (size_t)(n * CD + g * 16) * HW + (size_t)(y0 + row) * W;
    #pragma unroll
    for (int f = 0; f < 7; f++) {
        int px = f * 8 + lc * 2;
        *(__half2*)&dst[(size_t)lr * HW + px] = __floats2half2_rn(acc[f][0], acc[f][1]);
        *(__half2*)&dst[(size_t)(lr + 8) * HW + px] = __floats2half2_rn(acc[f][2], acc[f][3]);
    }
}

// ---------------------------------------------------------------------------
// Final: out = relu(scale3*y3 + shift3 + x)
// ---------------------------------------------------------------------------
__global__ void __launch_bounds__(256) final_kernel(const float* __restrict__ x,
                                                    float* __restrict__ out)
{
    int i = blockIdx.x * 256 + threadIdx.x;
    int c = (i / HW4) & (COUT - 1);
    float4 v  = ((const float4*)g_y3)[i];
    float4 xv = ((const float4*)x)[i];
    float sc = g_scale3[c], sh = g_shift3[c];
    float4 o;
    o.x = fmaxf(fmaf(sc, v.x, sh) + xv.x, 0.f);
    o.y = fmaxf(fmaf(sc, v.y, sh) + xv.y, 0.f);
    o.z = fmaxf(fmaf(sc, v.z, sh) + xv.z, 0.f);
    o.w = fmaxf(fmaf(sc, v.w, sh) + xv.w, 0.f);
    ((float4*)out)[i] = o;
}

// ---------------------------------------------------------------------------
extern "C" void kernel_launch(void* const* d_in, const int* in_sizes, int n_in,
                              void* d_out, int out_size)
{
    const float* x  = (const float*)d_in[0];
    const float* w1 = (const float*)d_in[1];
    const float* g1 = (const float*)d_in[2];
    const float* b1 = (const float*)d_in[3];
    const float* w3 = (const float*)d_in[4];
    const float* g3 = (const float*)d_in[5];
    const float* b3 = (const float*)d_in[6];
    const float* wa = (const float*)d_in[7];
    const float* ga = (const float*)d_in[8];
    const float* ba = (const float*)d_in[9];
    float* out = (float*)d_out;

    cudaFuncSetAttribute(mma_gemm_kernel<0>, cudaFuncAttributeMaxDynamicSharedMemorySize, GEMM_SMEM);
    cudaFuncSetAttribute(mma_gemm_kernel<1>, cudaFuncAttributeMaxDynamicSharedMemorySize, GEMM_SMEM);

    uint32_t* cw1h;  cudaGetSymbolAddress((void**)&cw1h, g_cw1h);
    uint32_t* cwah;  cudaGetSymbolAddress((void**)&cwah, g_cwah);
    cvtA_kernel<512, 256><<<256, 256>>>(w1, cw1h);
    cvtA_kernel<256, 512><<<256, 256>>>(wa, cwah);

    // conv1: y1h = w1 @ x   (M=512 -> 2 M-tiles of 256, K=256, 49 px-tiles)
    mma_gemm_kernel<0><<<dim3(49, 2, NB), 256, GEMM_SMEM>>>(x);
    bn_fin_kernel<1><<<CD, 256>>>(g1, b1);
    // grouped 3x3 (fp16 tensor cores) with fused BN1+ReLU on load, BN2 partials
    conv3x3_tc_kernel<<<dim3(7, GRP, NB), 256>>>(w3);
    bn_fin_kernel<2><<<CD, 256>>>(g3, b3);
    // convA: y3 = wa @ relu(bn2(y2h))  (M=256 -> 1 M-tile, K=512)
    mma_gemm_kernel<1><<<dim3(49, 1, NB), 256, GEMM_SMEM>>>(nullptr);
    bn_fin_kernel<3><<<COUT, 256>>>(ga, ba);
    // final: relu(bn3(y3) + x)
    final_kernel<<<(NB * COUT * HW4) / 256, 256>>>(x, out);
}

// round 11
// speedup vs baseline: 3.4791x; 1.0697x over previous
#include <cuda_runtime.h>
#include <cuda_fp16.h>
#include <cstdint>

// Problem constants
#define NB   32
#define CIN  256
#define CD   512
#define COUT 256
#define H    56
#define W    56
#define HW   3136          // 56*56
#define HW4  784           // HW/4
#define NTOT (NB*HW)       // 100352
#define GRP  32

// Scratch (allocation-free: __device__ globals)
__device__ __align__(16) __half g_y1h[NB * CD * HW];   // conv1 raw output (fp16)
__device__ __align__(16) __half g_y2h[NB * CD * HW];   // conv3 raw output (fp16)
__device__ __align__(16) float  g_y3[NB * COUT * HW];  // convA raw output (fp32)
__device__ float g_scale1[CD], g_shift1[CD];
__device__ float g_scale2[CD], g_shift2[CD];
__device__ float g_scale3[COUT], g_shift3[COUT];
// Per-CTA BN partial sums (sum, sumsq) from fp32 accumulators
__device__ float2 g_part1[CD * 1568];    // conv1: 49 px-tiles * 32 imgs
__device__ float2 g_part2[CD * 224];     // conv3: 7 y-tiles * 32 imgs
__device__ float2 g_part3[COUT * 1568];  // convA
// Pre-converted fp16 weights in frag-permuted layout
__device__ __align__(16) uint32_t g_cw1h[CD * CIN / 2];
__device__ __align__(16) uint32_t g_cwah[COUT * CD / 2];
// Pre-packed x in B-frag layout: [n][chunk 0..7][kp 0..15][px 0..3135] u32=half2(k2kp,k2kp+1)
__device__ __align__(16) uint32_t g_xt[NB * 8 * 16 * HW];

__device__ __forceinline__ uint32_t h2bits(__half2 h) {
    return *reinterpret_cast<uint32_t*>(&h);
}
__device__ __forceinline__ uint32_t smem_u32addr(const void* p) {
    uint32_t a;
    asm("{ .reg .u64 t; cvta.to.shared.u64 t, %1; cvt.u32.u64 %0, t; }" : "=r"(a) : "l"(p));
    return a;
}
#define CP_A16(dst, src) asm volatile("cp.async.cg.shared.global [%0], [%1], 16;" :: "r"(dst), "l"(src))
#define CP_COMMIT()      asm volatile("cp.async.commit_group;")
#define CP_WAIT1()       asm volatile("cp.async.wait_group 1;" ::: "memory")
#define CP_WAIT0()       asm volatile("cp.async.wait_group 0;" ::: "memory")

__device__ __forceinline__ void mma_f16(float* c, const uint32_t* a, const uint32_t* b) {
    asm volatile(
        "mma.sync.aligned.m16n8k16.row.col.f32.f16.f16.f32 "
        "{%0,%1,%2,%3}, {%4,%5,%6,%7}, {%8,%9}, {%0,%1,%2,%3};"
        : "+f"(c[0]), "+f"(c[1]), "+f"(c[2]), "+f"(c[3])
        : "r"(a[0]), "r"(a[1]), "r"(a[2]), "r"(a[3]), "r"(b[0]), "r"(b[1]));
}

// ---------------------------------------------------------------------------
// Combined prepass: w1 + wa frag-permute, and x -> g_xt B-frag pack.
// ---------------------------------------------------------------------------
__device__ __forceinline__ void wperm(const float* __restrict__ w, uint32_t* __restrict__ dst,
                                      int u, int NCH, int KK) {
    int blk = u >> 12, r = u & 4095;
    int mt = blk / NCH, ch = blk % NCH;
    int fr = r >> 7, lane = (r >> 2) & 31, ww = r & 3;
    int mbl = fr >> 1, ks = fr & 1, lr = lane >> 2, lc = lane & 3;
    int row = mt * 256 + mbl * 16 + lr + (ww & 1) * 8;
    int k   = ch * 32 + ks * 16 + (ww >> 1) * 8 + lc * 2;
    __half2 h = __floats2half2_rn(w[(size_t)row * KK + k], w[(size_t)row * KK + k + 1]);
    dst[u] = h2bits(h);
}

__global__ void __launch_bounds__(256) cvt_all_kernel(const float* __restrict__ w1,
                                                      const float* __restrict__ wa,
                                                      const float* __restrict__ x)
{
    int u = blockIdx.x * 256 + threadIdx.x;
    if (u < 65536) {
        wperm(w1, g_cw1h, u, 8, 256);
    } else if (u < 131072) {
        wperm(wa, g_cwah, u - 65536, 16, 512);
    } else {
        u -= 131072;                       // 0 .. 12845055
        int px = u % HW;
        int r  = u / HW;
        int kp = r & 15; r >>= 4;
        int c  = r & 7;  r >>= 3;
        int n  = r;
        int k = c * 32 + 2 * kp;
        float v0 = x[((size_t)n * CIN + k) * HW + px];
        float v1 = x[((size_t)n * CIN + k + 1) * HW + px];
        g_xt[(size_t)blockIdx.x * 256 + threadIdx.x - 131072 + 0] = 0; // placeholder avoided below
        g_xt[u] = h2bits(__floats2half2_rn(v0, v1));
    }
}

// ---------------------------------------------------------------------------
// fp16 mma.sync 1x1-conv GEMM, cp.async 3-stage pipeline.
// MODE 0: conv1 (K=256, B from g_xt via cp.async, out g_y1h fp16)
// MODE 1: convA (K=512, B = relu(bn2(g_y2h)) via reg transform, out g_y3 fp32)
// CTA tile 256m x 64px, BK=32. 256 threads, 8 warps (4m x 2px).
// Stage = A 4096 u32 (frag-permuted) + B 16*72 u32 (kp-major, stride 72).
// ---------------------------------------------------------------------------
#define PXS 72
#define STG_U32 (4096 + 16 * PXS)          // 5248
#define DEPTH 3
#define GEMM_SMEM (DEPTH * STG_U32 * 4)    // 62976 B

template<int MODE>
__global__ void __launch_bounds__(256) mma_gemm_kernel(const float* __restrict__ Bx)
{
    constexpr int K = (MODE == 0) ? CIN : CD;
    constexpr int CH = K / 32;
    const uint32_t* __restrict__ Wp = (MODE == 0) ? g_cw1h : g_cwah;
    float2* __restrict__ Part = (MODE == 0) ? g_part1 : g_part3;

    extern __shared__ uint32_t smem[];
    const uint32_t sbase = smem_u32addr(smem);

    const int tid = threadIdx.x;
    const int wid = tid >> 5, lane = tid & 31;
    const int lr = lane >> 2, lc = lane & 3;
    const int wm = (wid & 3) * 64;
    const int wn = (wid >> 2) * 32;
    const int pb0 = blockIdx.x * 64;
    const int mbb = blockIdx.y * 256;
    const int n   = blockIdx.z;
    const uint32_t* Ablk = Wp + ((size_t)blockIdx.y * CH) * 4096;
    const int kp  = tid >> 4, seg = tid & 15;

    float acc[4][4][4];
    #pragma unroll
    for (int m = 0; m < 4; m++)
        #pragma unroll
        for (int q = 0; q < 4; q++)
            #pragma unroll
            for (int r = 0; r < 4; r++) acc[m][q][r] = 0.f;

    uint32_t breg[4];

    auto issueA = [&](int c) {
        int s = c % DEPTH;
        uint32_t dst = sbase + s * (STG_U32 * 4) + tid * 16;
        const uint32_t* src = Ablk + (size_t)c * 4096 + tid * 4;
        #pragma unroll
        for (int jj = 0; jj < 4; jj++)
            CP_A16(dst + jj * 4096, src + jj * 1024);
    };
    auto issueB0 = [&](int c) {
        int s = c % DEPTH;
        uint32_t dst = sbase + s * (STG_U32 * 4) + (4096 + kp * PXS + seg * 4) * 4;
        const uint32_t* src = g_xt + (((size_t)n * 8 + c) * 16 + kp) * HW + pb0 + seg * 4;
        CP_A16(dst, src);
    };
    auto ldgB1 = [&](int c) {
        int k = c * 32 + kp * 2;
        const __half* base = g_y2h + ((size_t)n * CD + k) * HW + pb0 + seg * 4;
        uint2 r0 = *(const uint2*)base;
        uint2 r1 = *(const uint2*)(base + HW);
        float sc0 = g_scale2[k], sh0 = g_shift2[k];
        float sc1 = g_scale2[k + 1], sh1 = g_shift2[k + 1];
        float2 a0 = __half22float2(*reinterpret_cast<__half2*>(&r0.x));
        float2 a1 = __half22float2(*reinterpret_cast<__half2*>(&r0.y));
        float2 b0 = __half22float2(*reinterpret_cast<__half2*>(&r1.x));
        float2 b1 = __half22float2(*reinterpret_cast<__half2*>(&r1.y));
        float t0, t1;
        t0 = fmaxf(fmaf(sc0, a0.x, sh0), 0.f); t1 = fmaxf(fmaf(sc1, b0.x, sh1), 0.f);
        breg[0] = h2bits(__floats2half2_rn(t0, t1));
        t0 = fmaxf(fmaf(sc0, a0.y, sh0), 0.f); t1 = fmaxf(fmaf(sc1, b0.y, sh1), 0.f);
        breg[1] = h2bits(__floats2half2_rn(t0, t1));
        t0 = fmaxf(fmaf(sc0, a1.x, sh0), 0.f); t1 = fmaxf(fmaf(sc1, b1.x, sh1), 0.f);
        breg[2] = h2bits(__floats2half2_rn(t0, t1));
        t0 = fmaxf(fmaf(sc0, a1.y, sh0), 0.f); t1 = fmaxf(fmaf(sc1, b1.y, sh1), 0.f);
        breg[3] = h2bits(__floats2half2_rn(t0, t1));
    };
    auto stsB1 = [&](int c) {
        int s = c % DEPTH;
        *(uint4*)&smem[s * STG_U32 + 4096 + kp * PXS + seg * 4] = *(uint4*)breg;
    };

    auto compute = [&](int s) {
        const uint32_t* A = smem + s * STG_U32;
        const uint32_t* B = A + 4096;
        #pragma unroll
        for (int ks = 0; ks < 2; ks++) {
            uint32_t a[4][4], b[4][2];
            #pragma unroll
            for (int m = 0; m < 4; m++) {
                int mbl = (wid & 3) * 4 + m;
                uint4 t = *(const uint4*)&A[(mbl * 2 + ks) * 128 + lane * 4];
                a[m][0] = t.x; a[m][1] = t.y; a[m][2] = t.z; a[m][3] = t.w;
            }
            #pragma unroll
            for (int q = 0; q < 4; q++) {
                b[q][0] = B[(ks * 8 + lc) * PXS + wn + q * 8 + lr];
                b[q][1] = B[(ks * 8 + 4 + lc) * PXS + wn + q * 8 + lr];
            }
            #pragma unroll
            for (int m = 0; m < 4; m++)
                #pragma unroll
                for (int q = 0; q < 4; q++)
                    mma_f16(acc[m][q], a[m], b[q]);
        }
    };

    // Prologue: stages 0, 1
    #pragma unroll
    for (int c = 0; c < DEPTH - 1; c++) {
        if (MODE == 1) { ldgB1(c); stsB1(c); }
        issueA(c);
        if (MODE == 0) issueB0(c);
        CP_COMMIT();
    }

    for (int c = 0; c < CH; c++) {
        CP_WAIT1();
        __syncthreads();
        if (MODE == 1 && c + 2 < CH) ldgB1(c + 2);
        compute(c % DEPTH);
        if (c + 2 < CH) {
            if (MODE == 1) stsB1(c + 2);
            issueA(c + 2);
            if (MODE == 0) issueB0(c + 2);
        }
        CP_COMMIT();
    }
    CP_WAIT0();
    __syncthreads();

    // ---- BN partial stats (deterministic fixed-order reduction) ----
    float2* s_st = (float2*)smem;
    const int pxg = wid >> 2;
    #pragma unroll
    for (int m = 0; m < 4; m++) {
        float sl = 0.f, ql = 0.f, shi = 0.f, qhi = 0.f;
        #pragma unroll
        for (int q = 0; q < 4; q++) {
            const float* a = acc[m][q];
            sl += a[0] + a[1];
            ql += a[0] * a[0] + a[1] * a[1];
            shi += a[2] + a[3];
            qhi += a[2] * a[2] + a[3] * a[3];
        }
        #pragma unroll
        for (int o = 1; o < 4; o <<= 1) {
            sl  += __shfl_xor_sync(0xffffffffu, sl,  o);
            ql  += __shfl_xor_sync(0xffffffffu, ql,  o);
            shi += __shfl_xor_sync(0xffffffffu, shi, o);
            qhi += __shfl_xor_sync(0xffffffffu, qhi, o);
        }
        if (lc == 0) {
            s_st[pxg * 256 + wm + m * 16 + lr]     = make_float2(sl, ql);
            s_st[pxg * 256 + wm + m * 16 + lr + 8] = make_float2(shi, qhi);
        }
    }
    __syncthreads();
    {
        float2 a = s_st[tid], b = s_st[256 + tid];
        Part[(size_t)(mbb + tid) * 1568 + n * 49 + blockIdx.x] =
            make_float2(a.x + b.x, a.y + b.y);
    }

    // ---- output STG ----
    #pragma unroll
    for (int m = 0; m < 4; m++) {
        #pragma unroll
        for (int q = 0; q < 4; q++) {
            int row = mbb + wm + m * 16 + lr;
            int pix = pb0 + wn + q * 8 + lc * 2;
            if (MODE == 0) {
                __half* Cp = g_y1h + (size_t)n * CD * HW;
                *(__half2*)&Cp[(size_t)row * HW + pix] =
                    __floats2half2_rn(acc[m][q][0], acc[m][q][1]);
                *(__half2*)&Cp[(size_t)(row + 8) * HW + pix] =
                    __floats2half2_rn(acc[m][q][2], acc[m][q][3]);
            } else {
                float* Cp = g_y3 + (size_t)n * COUT * HW;
                *(float2*)&Cp[(size_t)row * HW + pix] =
                    make_float2(acc[m][q][0], acc[m][q][1]);
                *(float2*)&Cp[(size_t)(row + 8) * HW + pix] =
                    make_float2(acc[m][q][2], acc[m][q][3]);
            }
        }
    }
}

// ---------------------------------------------------------------------------
// Finalize BN: reduce per-CTA partials (fixed order) -> scale/shift
// ---------------------------------------------------------------------------
template<int WHICH>
__global__ void __launch_bounds__(256) bn_fin_kernel(const float* __restrict__ gamma,
                                                     const float* __restrict__ beta)
{
    constexpr int PARTS = (WHICH == 2) ? 224 : 1568;
    const float2* __restrict__ part =
        (WHICH == 1) ? g_part1 : (WHICH == 2) ? g_part2 : g_part3;
    float* __restrict__ scale = (WHICH == 1) ? g_scale1 : (WHICH == 2) ? g_scale2 : g_scale3;
    float* __restrict__ shift = (WHICH == 1) ? g_shift1 : (WHICH == 2) ? g_shift2 : g_shift3;

    const int c = blockIdx.x;
    float s = 0.f, sq = 0.f;
    for (int i = threadIdx.x; i < PARTS; i += 256) {
        float2 p = part[(size_t)c * PARTS + i];
        s += p.x; sq += p.y;
    }
    __shared__ float sh_s[8], sh_q[8];
    #pragma unroll
    for (int o = 16; o; o >>= 1) {
        s  += __shfl_down_sync(0xffffffffu, s,  o);
        sq += __shfl_down_sync(0xffffffffu, sq, o);
    }
    int lane = threadIdx.x & 31, wrp = threadIdx.x >> 5;
    if (lane == 0) { sh_s[wrp] = s; sh_q[wrp] = sq; }
    __syncthreads();
    if (threadIdx.x < 8) {
        s = sh_s[threadIdx.x]; sq = sh_q[threadIdx.x];
        #pragma unroll
        for (int o = 4; o; o >>= 1) {
            s  += __shfl_down_sync(0xffu, s,  o);
            sq += __shfl_down_sync(0xffu, sq, o);
        }
        if (threadIdx.x == 0) {
            const float inv = 1.f / (float)NTOT;
            float mean = s * inv;
            float var  = sq * inv - mean * mean;
            float sc = gamma[c] * rsqrtf(var + 1e-5f);
            scale[c] = sc;
            shift[c] = beta[c] - mean * sc;
        }
    }
}

// ---------------------------------------------------------------------------
// Grouped 3x3 conv as fp16 m16n8k16 implicit GEMM + fused BN2 partials.
// ---------------------------------------------------------------------------
#define CI2_STRIDE 584
#define W2_STRIDE  76

__global__ void __launch_bounds__(256) conv3x3_tc_kernel(const float* __restrict__ w3)
{
    __shared__ uint32_t s_in2[8 * CI2_STRIDE];
    __shared__ uint32_t s_w2[16 * W2_STRIDE];
    __shared__ float2 s3[8][16];

    const int tid = threadIdx.x;
    const int warp = tid >> 5, lane = tid & 31;
    const int lr = lane >> 2, lc = lane & 3;
    const int y0 = blockIdx.x * 8;
    const int g  = blockIdx.y;
    const int n  = blockIdx.z;

    for (int i = tid; i < 16 * 72; i += 256) {
        int co = i / 72, rem = i % 72;
        int tap = rem >> 3, ci2 = rem & 7;
        const float* wp = &w3[(size_t)(g * 16 + co) * 144 + tap];
        __half2 h = __floats2half2_rn(wp[(2 * ci2) * 9], wp[(2 * ci2 + 1) * 9]);
        s_w2[co * W2_STRIDE + tap * 8 + ci2] = h2bits(h);
    }
    const __half* src = g_y1h + (size_t)(n * CD + g * 16) * HW;
    for (int i = tid; i < 8 * 580; i += 256) {
        int ci2 = i / 580, r = i % 580;
        int yy = r / 58, xx = r % 58;
        int gy = y0 + yy - 1, gx = xx - 1;
        float v0 = 0.f, v1 = 0.f;
        if (gy >= 0 && gy < H && gx >= 0 && gx < W) {
            int cg = g * 16 + ci2 * 2;
            int off = gy * W + gx;
            v0 = fmaxf(fmaf(g_scale1[cg],
                            __half2float(src[(size_t)(ci2 * 2) * HW + off]),
                            g_shift1[cg]), 0.f);
            v1 = fmaxf(fmaf(g_scale1[cg + 1],
                            __half2float(src[(size_t)(ci2 * 2 + 1) * HW + off]),
                            g_shift1[cg + 1]), 0.f);
        }
        s_in2[ci2 * CI2_STRIDE + yy * 58 + xx] = h2bits(__floats2half2_rn(v0, v1));
    }
    __syncthreads();

    float acc[7][4];
    #pragma unroll
    for (int f = 0; f < 7; f++)
        #pragma unroll
        for (int r = 0; r < 4; r++) acc[f][r] = 0.f;

    const int row = warp;

    #pragma unroll
    for (int kk = 0; kk < 9; kk++) {
        const int dy = kk / 3, dx = kk % 3;
        uint32_t a[4];
        const uint32_t* ab = &s_w2[lr * W2_STRIDE + kk * 8 + lc];
        a[0] = ab[0];
        a[1] = ab[8 * W2_STRIDE];
        a[2] = ab[4];
        a[3] = ab[8 * W2_STRIDE + 4];
        const uint32_t* bb = &s_in2[lc * CI2_STRIDE + (row + dy) * 58 + dx + lr];
        #pragma unroll
        for (int f = 0; f < 7; f++) {
            uint32_t b[2];
            b[0] = bb[f * 8];
            b[1] = bb[f * 8 + 4 * CI2_STRIDE];
            mma_f16(acc[f], a, b);
        }
    }

    {
        float sl = 0.f, ql = 0.f, shi = 0.f, qhi = 0.f;
        #pragma unroll
        for (int f = 0; f < 7; f++) {
            sl += acc[f][0] + acc[f][1];
            ql += acc[f][0] * acc[f][0] + acc[f][1] * acc[f][1];
            shi += acc[f][2] + acc[f][3];
            qhi += acc[f][2] * acc[f][2] + acc[f][3] * acc[f][3];
        }
        #pragma unroll
        for (int o = 1; o < 4; o <<= 1) {
            sl  += __shfl_xor_sync(0xffffffffu, sl,  o);
            ql  += __shfl_xor_sync(0xffffffffu, ql,  o);
            shi += __shfl_xor_sync(0xffffffffu, shi, o);
            qhi += __shfl_xor_sync(0xffffffffu, qhi, o);
        }
        if (lc == 0) {
            s3[warp][lr]     = make_float2(sl, ql);
            s3[warp][lr + 8] = make_float2(shi, qhi);
        }
    }
    __syncthreads();
    if (tid < 16) {
        float s = 0.f, q = 0.f;
        #pragma unroll
        for (int w = 0; w < 8; w++) { float2 p = s3[w][tid]; s += p.x; q += p.y; }
        g_part2[(size_t)(g * 16 + tid) * 224 + n * 7 + blockIdx.x] = make_float2(s, q);
    }

    __half* dst = g_y2h + (size_t)(n * CD + g * 16) * HW + (size_t)(y0 + row) * W;
    #pragma unroll
    for (int f = 0; f < 7; f++) {
        int px = f * 8 + lc * 2;
        *(__half2*)&dst[(size_t)lr * HW + px] = __floats2half2_rn(acc[f][0], acc[f][1]);
        *(__half2*)&dst[(size_t)(lr + 8) * HW + px] = __floats2half2_rn(acc[f][2], acc[f][3]);
    }
}

// ---------------------------------------------------------------------------
// Final: out = relu(scale3*y3 + shift3 + x)
// ---------------------------------------------------------------------------
__global__ void __launch_bounds__(256) final_kernel(const float* __restrict__ x,
                                                    float* __restrict__ out)
{
    int i = blockIdx.x * 256 + threadIdx.x;
    int c = (i / HW4) & (COUT - 1);
    float4 v  = ((const float4*)g_y3)[i];
    float4 xv = ((const float4*)x)[i];
    float sc = g_scale3[c], sh = g_shift3[c];
    float4 o;
    o.x = fmaxf(fmaf(sc, v.x, sh) + xv.x, 0.f);
    o.y = fmaxf(fmaf(sc, v.y, sh) + xv.y, 0.f);
    o.z = fmaxf(fmaf(sc, v.z, sh) + xv.z, 0.f);
    o.w = fmaxf(fmaf(sc, v.w, sh) + xv.w, 0.f);
    ((float4*)out)[i] = o;
}

// ---------------------------------------------------------------------------
extern "C" void kernel_launch(void* const* d_in, const int* in_sizes, int n_in,
                              void* d_out, int out_size)
{
    const float* x  = (const float*)d_in[0];
    const float* w1 = (const float*)d_in[1];
    const float* g1 = (const float*)d_in[2];
    const float* b1 = (const float*)d_in[3];
    const float* w3 = (const float*)d_in[4];
    const float* g3 = (const float*)d_in[5];
    const float* b3 = (const float*)d_in[6];
    const float* wa = (const float*)d_in[7];
    const float* ga = (const float*)d_in[8];
    const float* ba = (const float*)d_in[9];
    float* out = (float*)d_out;

    cudaFuncSetAttribute(mma_gemm_kernel<0>, cudaFuncAttributeMaxDynamicSharedMemorySize, GEMM_SMEM);
    cudaFuncSetAttribute(mma_gemm_kernel<1>, cudaFuncAttributeMaxDynamicSharedMemorySize, GEMM_SMEM);

    // 0: combined prepass (weights permute + x pack)
    cvt_all_kernel<<<(131072 + NB * 8 * 16 * HW + 255) / 256, 256>>>(w1, wa, x);
    // 1: conv1 (M=512 -> 2 M-tiles, K=256)
    mma_gemm_kernel<0><<<dim3(49, 2, NB), 256, GEMM_SMEM>>>(x);
    // 2
    bn_fin_kernel<1><<<CD, 256>>>(g1, b1);
    // 3: grouped 3x3 fp16 tensor cores
    conv3x3_tc_kernel<<<dim3(7, GRP, NB), 256>>>(w3);
    // 4
    bn_fin_kernel<2><<<CD, 256>>>(g3, b3);
    // 5: convA (profiled by ncu -s 5 -c 1)
    mma_gemm_kernel<1><<<dim3(49, 1, NB), 256, GEMM_SMEM>>>(nullptr);
    // 6
    bn_fin_kernel<3><<<COUT, 256>>>(ga, ba);
    // 7: final residual
    final_kernel<<<(NB * COUT * HW4) / 256, 256>>>(x, out);
}

// round 12
// speedup vs baseline: 3.7419x; 1.0755x over previous
#include <cuda_runtime.h>
#include <cuda_fp16.h>
#include <cstdint>

// Problem constants
#define NB   32
#define CIN  256
#define CD   512
#define COUT 256
#define H    56
#define W    56
#define HW   3136          // 56*56
#define HW4  784           // HW/4
#define NTOT (NB*HW)       // 100352
#define GRP  32

// Scratch (allocation-free: __device__ globals)
__device__ __align__(16) __half g_y1h[NB * CD * HW];   // conv1 raw output (fp16)
__device__ __align__(16) __half g_y2h[NB * CD * HW];   // conv3 raw output (fp16)
__device__ __align__(16) float  g_y3[NB * COUT * HW];  // convA raw output (fp32)
__device__ float g_scale1[CD], g_shift1[CD];
__device__ float g_scale2[CD], g_shift2[CD];
__device__ float g_scale3[COUT], g_shift3[COUT];
// Per-CTA BN partial sums (sum, sumsq) from fp32 accumulators
__device__ float2 g_part1[CD * 1568];    // conv1: 49 px-tiles * 32 imgs
__device__ float2 g_part2[CD * 224];     // conv3: 7 y-tiles * 32 imgs
__device__ float2 g_part3[COUT * 1568];  // convA
// Pre-converted fp16 weights in frag-permuted layout
__device__ __align__(16) uint32_t g_cw1h[CD * CIN / 2];
__device__ __align__(16) uint32_t g_cwah[COUT * CD / 2];
// Pre-packed x in B-frag layout: [n][chunk 0..7][kp 0..15][px] u32=half2
__device__ __align__(16) uint32_t g_xt[NB * 8 * 16 * HW];

__device__ __forceinline__ uint32_t h2bits(__half2 h) {
    return *reinterpret_cast<uint32_t*>(&h);
}
__device__ __forceinline__ uint32_t smem_u32addr(const void* p) {
    uint32_t a;
    asm("{ .reg .u64 t; cvta.to.shared.u64 t, %1; cvt.u32.u64 %0, t; }" : "=r"(a) : "l"(p));
    return a;
}
#define CP_A16(dst, src) asm volatile("cp.async.cg.shared.global [%0], [%1], 16;" :: "r"(dst), "l"(src))
#define CP_COMMIT()      asm volatile("cp.async.commit_group;")
#define CP_WAIT1()       asm volatile("cp.async.wait_group 1;" ::: "memory")
#define CP_WAIT0()       asm volatile("cp.async.wait_group 0;" ::: "memory")

__device__ __forceinline__ void mma_f16(float* c, const uint32_t* a, const uint32_t* b) {
    asm volatile(
        "mma.sync.aligned.m16n8k16.row.col.f32.f16.f16.f32 "
        "{%0,%1,%2,%3}, {%4,%5,%6,%7}, {%8,%9}, {%0,%1,%2,%3};"
        : "+f"(c[0]), "+f"(c[1]), "+f"(c[2]), "+f"(c[3])
        : "r"(a[0]), "r"(a[1]), "r"(a[2]), "r"(a[3]), "r"(b[0]), "r"(b[1]));
}

// ---------------------------------------------------------------------------
// Combined prepass: w1 + wa frag-permute, and x -> g_xt B-frag pack.
// ---------------------------------------------------------------------------
__device__ __forceinline__ void wperm(const float* __restrict__ w, uint32_t* __restrict__ dst,
                                      int u, int NCH, int KK) {
    int blk = u >> 12, r = u & 4095;
    int mt = blk / NCH, ch = blk % NCH;
    int fr = r >> 7, lane = (r >> 2) & 31, ww = r & 3;
    int mbl = fr >> 1, ks = fr & 1, lr = lane >> 2, lc = lane & 3;
    int row = mt * 256 + mbl * 16 + lr + (ww & 1) * 8;
    int k   = ch * 32 + ks * 16 + (ww >> 1) * 8 + lc * 2;
    __half2 h = __floats2half2_rn(w[(size_t)row * KK + k], w[(size_t)row * KK + k + 1]);
    dst[u] = h2bits(h);
}

__global__ void __launch_bounds__(256) cvt_all_kernel(const float* __restrict__ w1,
                                                      const float* __restrict__ wa,
                                                      const float* __restrict__ x)
{
    int u = blockIdx.x * 256 + threadIdx.x;
    if (u < 65536) {
        wperm(w1, g_cw1h, u, 8, 256);
    } else if (u < 131072) {
        wperm(wa, g_cwah, u - 65536, 16, 512);
    } else {
        u -= 131072;                       // 0 .. 12845055
        int px = u % HW;
        int r  = u / HW;
        int kp = r & 15; r >>= 4;
        int c  = r & 7;  r >>= 3;
        int n  = r;
        int k = c * 32 + 2 * kp;
        float v0 = x[((size_t)n * CIN + k) * HW + px];
        float v1 = x[((size_t)n * CIN + k + 1) * HW + px];
        g_xt[u] = h2bits(__floats2half2_rn(v0, v1));
    }
}

// ---------------------------------------------------------------------------
// fp16 mma.sync 1x1-conv GEMM, cp.async 3-stage pipeline (unchanged from R11).
// ---------------------------------------------------------------------------
#define PXS 72
#define STG_U32 (4096 + 16 * PXS)          // 5248
#define DEPTH 3
#define GEMM_SMEM (DEPTH * STG_U32 * 4)    // 62976 B

template<int MODE>
__global__ void __launch_bounds__(256) mma_gemm_kernel(const float* __restrict__ Bx)
{
    constexpr int K = (MODE == 0) ? CIN : CD;
    constexpr int CH = K / 32;
    const uint32_t* __restrict__ Wp = (MODE == 0) ? g_cw1h : g_cwah;
    float2* __restrict__ Part = (MODE == 0) ? g_part1 : g_part3;

    extern __shared__ uint32_t smem[];
    const uint32_t sbase = smem_u32addr(smem);

    const int tid = threadIdx.x;
    const int wid = tid >> 5, lane = tid & 31;
    const int lr = lane >> 2, lc = lane & 3;
    const int wm = (wid & 3) * 64;
    const int wn = (wid >> 2) * 32;
    const int pb0 = blockIdx.x * 64;
    const int mbb = blockIdx.y * 256;
    const int n   = blockIdx.z;
    const uint32_t* Ablk = Wp + ((size_t)blockIdx.y * CH) * 4096;
    const int kp  = tid >> 4, seg = tid & 15;

    float acc[4][4][4];
    #pragma unroll
    for (int m = 0; m < 4; m++)
        #pragma unroll
        for (int q = 0; q < 4; q++)
            #pragma unroll
            for (int r = 0; r < 4; r++) acc[m][q][r] = 0.f;

    uint32_t breg[4];

    auto issueA = [&](int c) {
        int s = c % DEPTH;
        uint32_t dst = sbase + s * (STG_U32 * 4) + tid * 16;
        const uint32_t* src = Ablk + (size_t)c * 4096 + tid * 4;
        #pragma unroll
        for (int jj = 0; jj < 4; jj++)
            CP_A16(dst + jj * 4096, src + jj * 1024);
    };
    auto issueB0 = [&](int c) {
        int s = c % DEPTH;
        uint32_t dst = sbase + s * (STG_U32 * 4) + (4096 + kp * PXS + seg * 4) * 4;
        const uint32_t* src = g_xt + (((size_t)n * 8 + c) * 16 + kp) * HW + pb0 + seg * 4;
        CP_A16(dst, src);
    };
    auto ldgB1 = [&](int c) {
        int k = c * 32 + kp * 2;
        const __half* base = g_y2h + ((size_t)n * CD + k) * HW + pb0 + seg * 4;
        uint2 r0 = *(const uint2*)base;
        uint2 r1 = *(const uint2*)(base + HW);
        float sc0 = g_scale2[k], sh0 = g_shift2[k];
        float sc1 = g_scale2[k + 1], sh1 = g_shift2[k + 1];
        float2 a0 = __half22float2(*reinterpret_cast<__half2*>(&r0.x));
        float2 a1 = __half22float2(*reinterpret_cast<__half2*>(&r0.y));
        float2 b0 = __half22float2(*reinterpret_cast<__half2*>(&r1.x));
        float2 b1 = __half22float2(*reinterpret_cast<__half2*>(&r1.y));
        float t0, t1;
        t0 = fmaxf(fmaf(sc0, a0.x, sh0), 0.f); t1 = fmaxf(fmaf(sc1, b0.x, sh1), 0.f);
        breg[0] = h2bits(__floats2half2_rn(t0, t1));
        t0 = fmaxf(fmaf(sc0, a0.y, sh0), 0.f); t1 = fmaxf(fmaf(sc1, b0.y, sh1), 0.f);
        breg[1] = h2bits(__floats2half2_rn(t0, t1));
        t0 = fmaxf(fmaf(sc0, a1.x, sh0), 0.f); t1 = fmaxf(fmaf(sc1, b1.x, sh1), 0.f);
        breg[2] = h2bits(__floats2half2_rn(t0, t1));
        t0 = fmaxf(fmaf(sc0, a1.y, sh0), 0.f); t1 = fmaxf(fmaf(sc1, b1.y, sh1), 0.f);
        breg[3] = h2bits(__floats2half2_rn(t0, t1));
    };
    auto stsB1 = [&](int c) {
        int s = c % DEPTH;
        *(uint4*)&smem[s * STG_U32 + 4096 + kp * PXS + seg * 4] = *(uint4*)breg;
    };

    auto compute = [&](int s) {
        const uint32_t* A = smem + s * STG_U32;
        const uint32_t* B = A + 4096;
        #pragma unroll
        for (int ks = 0; ks < 2; ks++) {
            uint32_t a[4][4], b[4][2];
            #pragma unroll
            for (int m = 0; m < 4; m++) {
                int mbl = (wid & 3) * 4 + m;
                uint4 t = *(const uint4*)&A[(mbl * 2 + ks) * 128 + lane * 4];
                a[m][0] = t.x; a[m][1] = t.y; a[m][2] = t.z; a[m][3] = t.w;
            }
            #pragma unroll
            for (int q = 0; q < 4; q++) {
                b[q][0] = B[(ks * 8 + lc) * PXS + wn + q * 8 + lr];
                b[q][1] = B[(ks * 8 + 4 + lc) * PXS + wn + q * 8 + lr];
            }
            #pragma unroll
            for (int m = 0; m < 4; m++)
                #pragma unroll
                for (int q = 0; q < 4; q++)
                    mma_f16(acc[m][q], a[m], b[q]);
        }
    };

    #pragma unroll
    for (int c = 0; c < DEPTH - 1; c++) {
        if (MODE == 1) { ldgB1(c); stsB1(c); }
        issueA(c);
        if (MODE == 0) issueB0(c);
        CP_COMMIT();
    }

    for (int c = 0; c < CH; c++) {
        CP_WAIT1();
        __syncthreads();
        if (MODE == 1 && c + 2 < CH) ldgB1(c + 2);
        compute(c % DEPTH);
        if (c + 2 < CH) {
            if (MODE == 1) stsB1(c + 2);
            issueA(c + 2);
            if (MODE == 0) issueB0(c + 2);
        }
        CP_COMMIT();
    }
    CP_WAIT0();
    __syncthreads();

    // ---- BN partial stats (deterministic fixed-order reduction) ----
    float2* s_st = (float2*)smem;
    const int pxg = wid >> 2;
    #pragma unroll
    for (int m = 0; m < 4; m++) {
        float sl = 0.f, ql = 0.f, shi = 0.f, qhi = 0.f;
        #pragma unroll
        for (int q = 0; q < 4; q++) {
            const float* a = acc[m][q];
            sl += a[0] + a[1];
            ql += a[0] * a[0] + a[1] * a[1];
            shi += a[2] + a[3];
            qhi += a[2] * a[2] + a[3] * a[3];
        }
        #pragma unroll
        for (int o = 1; o < 4; o <<= 1) {
            sl  += __shfl_xor_sync(0xffffffffu, sl,  o);
            ql  += __shfl_xor_sync(0xffffffffu, ql,  o);
            shi += __shfl_xor_sync(0xffffffffu, shi, o);
            qhi += __shfl_xor_sync(0xffffffffu, qhi, o);
        }
        if (lc == 0) {
            s_st[pxg * 256 + wm + m * 16 + lr]     = make_float2(sl, ql);
            s_st[pxg * 256 + wm + m * 16 + lr + 8] = make_float2(shi, qhi);
        }
    }
    __syncthreads();
    {
        float2 a = s_st[tid], b = s_st[256 + tid];
        Part[(size_t)(mbb + tid) * 1568 + n * 49 + blockIdx.x] =
            make_float2(a.x + b.x, a.y + b.y);
    }

    // ---- output STG ----
    #pragma unroll
    for (int m = 0; m < 4; m++) {
        #pragma unroll
        for (int q = 0; q < 4; q++) {
            int row = mbb + wm + m * 16 + lr;
            int pix = pb0 + wn + q * 8 + lc * 2;
            if (MODE == 0) {
                __half* Cp = g_y1h + (size_t)n * CD * HW;
                *(__half2*)&Cp[(size_t)row * HW + pix] =
                    __floats2half2_rn(acc[m][q][0], acc[m][q][1]);
                *(__half2*)&Cp[(size_t)(row + 8) * HW + pix] =
                    __floats2half2_rn(acc[m][q][2], acc[m][q][3]);
            } else {
                float* Cp = g_y3 + (size_t)n * COUT * HW;
                *(float2*)&Cp[(size_t)row * HW + pix] =
                    make_float2(acc[m][q][0], acc[m][q][1]);
                *(float2*)&Cp[(size_t)(row + 8) * HW + pix] =
                    make_float2(acc[m][q][2], acc[m][q][3]);
            }
        }
    }
}

// ---------------------------------------------------------------------------
// Finalize BN: reduce per-CTA partials (fixed order) -> scale/shift
// ---------------------------------------------------------------------------
template<int WHICH>
__global__ void __launch_bounds__(256) bn_fin_kernel(const float* __restrict__ gamma,
                                                     const float* __restrict__ beta)
{
    constexpr int PARTS = (WHICH == 2) ? 224 : 1568;
    const float2* __restrict__ part =
        (WHICH == 1) ? g_part1 : (WHICH == 2) ? g_part2 : g_part3;
    float* __restrict__ scale = (WHICH == 1) ? g_scale1 : (WHICH == 2) ? g_scale2 : g_scale3;
    float* __restrict__ shift = (WHICH == 1) ? g_shift1 : (WHICH == 2) ? g_shift2 : g_shift3;

    const int c = blockIdx.x;
    float s = 0.f, sq = 0.f;
    for (int i = threadIdx.x; i < PARTS; i += 256) {
        float2 p = part[(size_t)c * PARTS + i];
        s += p.x; sq += p.y;
    }
    __shared__ float sh_s[8], sh_q[8];
    #pragma unroll
    for (int o = 16; o; o >>= 1) {
        s  += __shfl_down_sync(0xffffffffu, s,  o);
        sq += __shfl_down_sync(0xffffffffu, sq, o);
    }
    int lane = threadIdx.x & 31, wrp = threadIdx.x >> 5;
    if (lane == 0) { sh_s[wrp] = s; sh_q[wrp] = sq; }
    __syncthreads();
    if (threadIdx.x < 8) {
        s = sh_s[threadIdx.x]; sq = sh_q[threadIdx.x];
        #pragma unroll
        for (int o = 4; o; o >>= 1) {
            s  += __shfl_down_sync(0xffu, s,  o);
            sq += __shfl_down_sync(0xffu, sq, o);
        }
        if (threadIdx.x == 0) {
            const float inv = 1.f / (float)NTOT;
            float mean = s * inv;
            float var  = sq * inv - mean * mean;
            float sc = gamma[c] * rsqrtf(var + 1e-5f);
            scale[c] = sc;
            shift[c] = beta[c] - mean * sc;
        }
    }
}

// ---------------------------------------------------------------------------
// Grouped 3x3 conv, fp16 m16n8k16 implicit GEMM. ALU-lean restructure:
//  - weights frag-permuted in smem: s_w[kk*128 + lane*4 + j] -> 1 LDS.128/frag
//  - input fill: warp w <-> ci-pair w; loops (yy, x-chunk) only, no div/mod,
//    coalesced gmem, conflict-free stride-1 STS.
//  - B mainloop layout unchanged (verified conflict-free).
// ---------------------------------------------------------------------------
#define CI2_STRIDE 584

__global__ void __launch_bounds__(256) conv3x3_tc_kernel(const float* __restrict__ w3)
{
    __shared__ __align__(16) uint32_t s_w[9 * 128];      // frag-permuted weights
    __shared__ uint32_t s_in2[8 * CI2_STRIDE];           // [ci2][yy*58+xx]
    __shared__ float2 s3[8][16];

    const int tid = threadIdx.x;
    const int warp = tid >> 5, lane = tid & 31;
    const int lr = lane >> 2, lc = lane & 3;
    const int y0 = blockIdx.x * 8;
    const int g  = blockIdx.y;
    const int n  = blockIdx.z;

    // ---- weights -> frag-permuted [kk][lane][j], shift-only mapping ----
    const float* wg = w3 + (size_t)g * 16 * 144;
    #pragma unroll
    for (int it = 0; it < 5; it++) {
        int u = it * 256 + tid;                  // < 1152
        if (u < 9 * 128) {
            int kk = u >> 7, rem = u & 127;
            int ln = rem >> 2, j = rem & 3;
            int co = (ln >> 2) + (j & 1) * 8;
            int p  = (ln & 3) + (j >> 1) * 4;
            const float* wp = wg + co * 144 + p * 18 + kk;
            s_w[u] = h2bits(__floats2half2_rn(wp[0], wp[9]));
        }
    }

    // ---- input tile: warp per ci-pair, BN1+ReLU fused, no div/mod ----
    {
        const int p2 = warp;                     // ci pair 0..7
        const int cg = g * 16 + 2 * p2;
        const __half* src0 = g_y1h + ((size_t)(n * CD) + cg) * HW;
        const __half* src1 = src0 + HW;
        const float sc0 = g_scale1[cg], sh0 = g_shift1[cg];
        const float sc1 = g_scale1[cg + 1], sh1 = g_shift1[cg + 1];
        uint32_t* drow = &s_in2[p2 * CI2_STRIDE];
        #pragma unroll
        for (int yy = 0; yy < 10; yy++) {
            int gy = y0 + yy - 1;
            bool yok = (gy >= 0) && (gy < H);
            const __half* r0 = src0 + gy * W;
            const __half* r1 = src1 + gy * W;
            #pragma unroll
            for (int xc = 0; xc < 2; xc++) {
                int xx = xc * 32 + lane;
                if (xx < 58) {
                    int gx = xx - 1;
                    float v0 = 0.f, v1 = 0.f;
                    if (yok && (unsigned)gx < (unsigned)W) {
                        v0 = fmaxf(fmaf(sc0, __half2float(r0[gx]), sh0), 0.f);
                        v1 = fmaxf(fmaf(sc1, __half2float(r1[gx]), sh1), 0.f);
                    }
                    drow[yy * 58 + xx] = h2bits(__floats2half2_rn(v0, v1));
                }
            }
        }
    }
    __syncthreads();

    float acc[7][4];
    #pragma unroll
    for (int f = 0; f < 7; f++)
        #pragma unroll
        for (int r = 0; r < 4; r++) acc[f][r] = 0.f;

    const int row = warp;

    #pragma unroll
    for (int kk = 0; kk < 9; kk++) {
        const int dy = kk / 3, dx = kk % 3;      // compile-time (full unroll)
        uint4 av = *(const uint4*)&s_w[kk * 128 + lane * 4];
        uint32_t a[4] = {av.x, av.y, av.z, av.w};
        const uint32_t* bb = &s_in2[lc * CI2_STRIDE + (row + dy) * 58 + dx + lr];
        #pragma unroll
        for (int f = 0; f < 7; f++) {
            uint32_t b[2];
            b[0] = bb[f * 8];
            b[1] = bb[f * 8 + 4 * CI2_STRIDE];
            mma_f16(acc[f], a, b);
        }
    }

    // ---- BN2 partials (fixed order, fp32 accs) ----
    {
        float sl = 0.f, ql = 0.f, shi = 0.f, qhi = 0.f;
        #pragma unroll
        for (int f = 0; f < 7; f++) {
            sl += acc[f][0] + acc[f][1];
            ql += acc[f][0] * acc[f][0] + acc[f][1] * acc[f][1];
            shi += acc[f][2] + acc[f][3];
            qhi += acc[f][2] * acc[f][2] + acc[f][3] * acc[f][3];
        }
        #pragma unroll
        for (int o = 1; o < 4; o <<= 1) {
            sl  += __shfl_xor_sync(0xffffffffu, sl,  o);
            ql  += __shfl_xor_sync(0xffffffffu, ql,  o);
            shi += __shfl_xor_sync(0xffffffffu, shi, o);
            qhi += __shfl_xor_sync(0xffffffffu, qhi, o);
        }
        if (lc == 0) {
            s3[warp][lr]     = make_float2(sl, ql);
            s3[warp][lr + 8] = make_float2(shi, qhi);
        }
    }
    __syncthreads();
    if (tid < 16) {
        float s = 0.f, q = 0.f;
        #pragma unroll
        for (int w = 0; w < 8; w++) { float2 p = s3[w][tid]; s += p.x; q += p.y; }
        g_part2[(size_t)(g * 16 + tid) * 224 + n * 7 + blockIdx.x] = make_float2(s, q);
    }

    __half* dst = g_y2h + (size_t)(n * CD + g * 16) * HW + (size_t)(y0 + row) * W;
    #pragma unroll
    for (int f = 0; f < 7; f++) {
        int px = f * 8 + lc * 2;
        *(__half2*)&dst[(size_t)lr * HW + px] = __floats2half2_rn(acc[f][0], acc[f][1]);
        *(__half2*)&dst[(size_t)(lr + 8) * HW + px] = __floats2half2_rn(acc[f][2], acc[f][3]);
    }
}

// ---------------------------------------------------------------------------
// Final: out = relu(scale3*y3 + shift3 + x)
// ---------------------------------------------------------------------------
__global__ void __launch_bounds__(256) final_kernel(const float* __restrict__ x,
                                                    float* __restrict__ out)
{
    int i = blockIdx.x * 256 + threadIdx.x;
    int c = (i / HW4) & (COUT - 1);
    float4 v  = ((const float4*)g_y3)[i];
    float4 xv = ((const float4*)x)[i];
    float sc = g_scale3[c], sh = g_shift3[c];
    float4 o;
    o.x = fmaxf(fmaf(sc, v.x, sh) + xv.x, 0.f);
    o.y = fmaxf(fmaf(sc, v.y, sh) + xv.y, 0.f);
    o.z = fmaxf(fmaf(sc, v.z, sh) + xv.z, 0.f);
    o.w = fmaxf(fmaf(sc, v.w, sh) + xv.w, 0.f);
    ((float4*)out)[i] = o;
}

// ---------------------------------------------------------------------------
extern "C" void kernel_launch(void* const* d_in, const int* in_sizes, int n_in,
                              void* d_out, int out_size)
{
    const float* x  = (const float*)d_in[0];
    const float* w1 = (const float*)d_in[1];
    const float* g1 = (const float*)d_in[2];
    const float* b1 = (const float*)d_in[3];
    const float* w3 = (const float*)d_in[4];
    const float* g3 = (const float*)d_in[5];
    const float* b3 = (const float*)d_in[6];
    const float* wa = (const float*)d_in[7];
    const float* ga = (const float*)d_in[8];
    const float* ba = (const float*)d_in[9];
    float* out = (float*)d_out;

    cudaFuncSetAttribute(mma_gemm_kernel<0>, cudaFuncAttributeMaxDynamicSharedMemorySize, GEMM_SMEM);
    cudaFuncSetAttribute(mma_gemm_kernel<1>, cudaFuncAttributeMaxDynamicSharedMemorySize, GEMM_SMEM);

    // 0: combined prepass (weights permute + x pack)
    cvt_all_kernel<<<(131072 + NB * 8 * 16 * HW + 255) / 256, 256>>>(w1, wa, x);
    // 1: conv1 (M=512 -> 2 M-tiles, K=256)
    mma_gemm_kernel<0><<<dim3(49, 2, NB), 256, GEMM_SMEM>>>(x);
    // 2
    bn_fin_kernel<1><<<CD, 256>>>(g1, b1);
    // 3: grouped 3x3 fp16 tensor cores
    conv3x3_tc_kernel<<<dim3(7, GRP, NB), 256>>>(w3);
    // 4
    bn_fin_kernel<2><<<CD, 256>>>(g3, b3);
    // 5: convA (profiled by ncu -s 5 -c 1)
    mma_gemm_kernel<1><<<dim3(49, 1, NB), 256, GEMM_SMEM>>>(nullptr);
    // 6
    bn_fin_kernel<3><<<COUT, 256>>>(ga, ba);
    // 7: final residual
    final_kernel<<<(NB * COUT * HW4) / 256, 256>>>(x, out);
}

// round 14
// speedup vs baseline: 3.9224x; 1.0482x over previous
#include <cuda_runtime.h>
#include <cuda_fp16.h>
#include <cstdint>

// Problem constants
#define NB   32
#define CIN  256
#define CD   512
#define COUT 256
#define H    56
#define W    56
#define HW   3136          // 56*56
#define HW4  784           // HW/4
#define NTOT (NB*HW)       // 100352
#define GRP  32

// Scratch (allocation-free: __device__ globals)
__device__ __align__(16) __half g_y1h[NB * CD * HW];   // conv1 raw output (fp16)
__device__ __align__(16) __half g_y2h[NB * CD * HW];   // conv3 raw output (fp16)
__device__ __align__(16) __half g_y3h[NB * COUT * HW]; // convA raw output (fp16)
__device__ float g_scale1[CD], g_shift1[CD];
__device__ float g_scale2[CD], g_shift2[CD];
__device__ float g_scale3[COUT], g_shift3[COUT];
// Per-CTA BN partial sums (sum, sumsq) from fp32 accumulators
__device__ float2 g_part1[CD * 1568];    // conv1: 49 px-tiles * 32 imgs
__device__ float2 g_part2[CD * 224];     // conv3: 7 y-tiles * 32 imgs
__device__ float2 g_part3[COUT * 1568];  // convA
// Pre-converted fp16 weights in frag-permuted layout
__device__ __align__(16) uint32_t g_cw1h[CD * CIN / 2];
__device__ __align__(16) uint32_t g_cwah[COUT * CD / 2];
// Pre-packed x in B-frag layout: [n][chunk 0..7][kp 0..15][px] u32=half2
__device__ __align__(16) uint32_t g_xt[NB * 8 * 16 * HW];

__device__ __forceinline__ uint32_t h2bits(__half2 h) {
    return *reinterpret_cast<uint32_t*>(&h);
}
__device__ __forceinline__ __half2 bits2h2(uint32_t u) {
    return *reinterpret_cast<__half2*>(&u);
}
__device__ __forceinline__ uint32_t smem_u32addr(const void* p) {
    uint32_t a;
    asm("{ .reg .u64 t; cvta.to.shared.u64 t, %1; cvt.u32.u64 %0, t; }" : "=r"(a) : "l"(p));
    return a;
}
#define CP_A16(dst, src) asm volatile("cp.async.cg.shared.global [%0], [%1], 16;" :: "r"(dst), "l"(src))
#define CP_COMMIT()      asm volatile("cp.async.commit_group;")
#define CP_WAIT1()       asm volatile("cp.async.wait_group 1;" ::: "memory")
#define CP_WAIT0()       asm volatile("cp.async.wait_group 0;" ::: "memory")

__device__ __forceinline__ void mma_f16(float* c, const uint32_t* a, const uint32_t* b) {
    asm volatile(
        "mma.sync.aligned.m16n8k16.row.col.f32.f16.f16.f32 "
        "{%0,%1,%2,%3}, {%4,%5,%6,%7}, {%8,%9}, {%0,%1,%2,%3};"
        : "+f"(c[0]), "+f"(c[1]), "+f"(c[2]), "+f"(c[3])
        : "r"(a[0]), "r"(a[1]), "r"(a[2]), "r"(a[3]), "r"(b[0]), "r"(b[1]));
}

// ---------------------------------------------------------------------------
// Combined prepass: w1 + wa frag-permute, and x -> g_xt B-frag pack.
// ---------------------------------------------------------------------------
__device__ __forceinline__ void wperm(const float* __restrict__ w, uint32_t* __restrict__ dst,
                                      int u, int NCH, int KK) {
    int blk = u >> 12, r = u & 4095;
    int mt = blk / NCH, ch = blk % NCH;
    int fr = r >> 7, lane = (r >> 2) & 31, ww = r & 3;
    int mbl = fr >> 1, ks = fr & 1, lr = lane >> 2, lc = lane & 3;
    int row = mt * 256 + mbl * 16 + lr + (ww & 1) * 8;
    int k   = ch * 32 + ks * 16 + (ww >> 1) * 8 + lc * 2;
    __half2 h = __floats2half2_rn(w[(size_t)row * KK + k], w[(size_t)row * KK + k + 1]);
    dst[u] = h2bits(h);
}

__global__ void __launch_bounds__(256) cvt_all_kernel(const float* __restrict__ w1,
                                                      const float* __restrict__ wa,
                                                      const float* __restrict__ x)
{
    int u = blockIdx.x * 256 + threadIdx.x;
    if (u < 65536) {
        wperm(w1, g_cw1h, u, 8, 256);
    } else if (u < 131072) {
        wperm(wa, g_cwah, u - 65536, 16, 512);
    } else {
        u -= 131072;                       // 0 .. 12845055
        int px = u % HW;
        int r  = u / HW;
        int kp = r & 15; r >>= 4;
        int c  = r & 7;  r >>= 3;
        int n  = r;
        int k = c * 32 + 2 * kp;
        float v0 = x[((size_t)n * CIN + k) * HW + px];
        float v1 = x[((size_t)n * CIN + k + 1) * HW + px];
        g_xt[u] = h2bits(__floats2half2_rn(v0, v1));
    }
}

// ---------------------------------------------------------------------------
// fp16 mma.sync 1x1-conv GEMM, cp.async 3-stage pipeline.
// MODE 0: conv1 (K=256, B from g_xt via cp.async, out g_y1h fp16)
// MODE 1: convA (K=512, B = relu(bn2(g_y2h)) half2 transform, out g_y3h fp16)
// ---------------------------------------------------------------------------
#define PXS 72
#define STG_U32 (4096 + 16 * PXS)          // 5248
#define DEPTH 3
#define GEMM_SMEM (DEPTH * STG_U32 * 4)    // 62976 B

template<int MODE>
__global__ void __launch_bounds__(256) mma_gemm_kernel(const float* __restrict__ Bx)
{
    constexpr int K = (MODE == 0) ? CIN : CD;
    constexpr int CH = K / 32;
    const uint32_t* __restrict__ Wp = (MODE == 0) ? g_cw1h : g_cwah;
    float2* __restrict__ Part = (MODE == 0) ? g_part1 : g_part3;

    extern __shared__ uint32_t smem[];
    const uint32_t sbase = smem_u32addr(smem);

    const int tid = threadIdx.x;
    const int wid = tid >> 5, lane = tid & 31;
    const int lr = lane >> 2, lc = lane & 3;
    const int wm = (wid & 3) * 64;
    const int wn = (wid >> 2) * 32;
    const int pb0 = blockIdx.x * 64;
    const int mbb = blockIdx.y * 256;
    const int n   = blockIdx.z;
    const uint32_t* Ablk = Wp + ((size_t)blockIdx.y * CH) * 4096;
    const int kp  = tid >> 4, seg = tid & 15;

    float acc[4][4][4];
    #pragma unroll
    for (int m = 0; m < 4; m++)
        #pragma unroll
        for (int q = 0; q < 4; q++)
            #pragma unroll
            for (int r = 0; r < 4; r++) acc[m][q][r] = 0.f;

    uint32_t breg[4];

    auto issueA = [&](int c) {
        int s = c % DEPTH;
        uint32_t dst = sbase + s * (STG_U32 * 4) + tid * 16;
        const uint32_t* src = Ablk + (size_t)c * 4096 + tid * 4;
        #pragma unroll
        for (int jj = 0; jj < 4; jj++)
            CP_A16(dst + jj * 4096, src + jj * 1024);
    };
    auto issueB0 = [&](int c) {
        int s = c % DEPTH;
        uint32_t dst = sbase + s * (STG_U32 * 4) + (4096 + kp * PXS + seg * 4) * 4;
        const uint32_t* src = g_xt + (((size_t)n * 8 + c) * 16 + kp) * HW + pb0 + seg * 4;
        CP_A16(dst, src);
    };
    auto ldgB1 = [&](int c) {
        int k = c * 32 + kp * 2;
        const __half* base = g_y2h + ((size_t)n * CD + k) * HW + pb0 + seg * 4;
        uint2 r0 = *(const uint2*)base;            // px0..3 of channel k
        uint2 r1 = *(const uint2*)(base + HW);     // px0..3 of channel k+1
        __half2 s0 = __float2half2_rn(g_scale2[k]);
        __half2 h0 = __float2half2_rn(g_shift2[k]);
        __half2 s1 = __float2half2_rn(g_scale2[k + 1]);
        __half2 h1 = __float2half2_rn(g_shift2[k + 1]);
        __half2 v0a = __hfma2_relu(bits2h2(r0.x), s0, h0);   // k:  px0,px1
        __half2 v0b = __hfma2_relu(bits2h2(r0.y), s0, h0);   // k:  px2,px3
        __half2 v1a = __hfma2_relu(bits2h2(r1.x), s1, h1);   // k+1:px0,px1
        __half2 v1b = __hfma2_relu(bits2h2(r1.y), s1, h1);   // k+1:px2,px3
        breg[0] = h2bits(__lows2half2(v0a, v1a));
        breg[1] = h2bits(__highs2half2(v0a, v1a));
        breg[2] = h2bits(__lows2half2(v0b, v1b));
        breg[3] = h2bits(__highs2half2(v0b, v1b));
    };
    auto stsB1 = [&](int c) {
        int s = c % DEPTH;
        *(uint4*)&smem[s * STG_U32 + 4096 + kp * PXS + seg * 4] = *(uint4*)breg;
    };

    auto compute = [&](int s) {
        const uint32_t* A = smem + s * STG_U32;
        const uint32_t* B = A + 4096;
        #pragma unroll
        for (int ks = 0; ks < 2; ks++) {
            uint32_t a[4][4], b[4][2];
            #pragma unroll
            for (int m = 0; m < 4; m++) {
                int mbl = (wid & 3) * 4 + m;
                uint4 t = *(const uint4*)&A[(mbl * 2 + ks) * 128 + lane * 4];
                a[m][0] = t.x; a[m][1] = t.y; a[m][2] = t.z; a[m][3] = t.w;
            }
            #pragma unroll
            for (int q = 0; q < 4; q++) {
                b[q][0] = B[(ks * 8 + lc) * PXS + wn + q * 8 + lr];
                b[q][1] = B[(ks * 8 + 4 + lc) * PXS + wn + q * 8 + lr];
            }
            #pragma unroll
            for (int m = 0; m < 4; m++)
                #pragma unroll
                for (int q = 0; q < 4; q++)
                    mma_f16(acc[m][q], a[m], b[q]);
        }
    };

    #pragma unroll
    for (int c = 0; c < DEPTH - 1; c++) {
        if (MODE == 1) { ldgB1(c); stsB1(c); }
        issueA(c);
        if (MODE == 0) issueB0(c);
        CP_COMMIT();
    }

    for (int c = 0; c < CH; c++) {
        CP_WAIT1();
        __syncthreads();
        if (MODE == 1 && c + 2 < CH) ldgB1(c + 2);
        compute(c % DEPTH);
        if (c + 2 < CH) {
            if (MODE == 1) stsB1(c + 2);
            issueA(c + 2);
            if (MODE == 0) issueB0(c + 2);
        }
        CP_COMMIT();
    }
    CP_WAIT0();
    __syncthreads();

    // ---- BN partial stats (deterministic fixed-order reduction) ----
    float2* s_st = (float2*)smem;
    const int pxg = wid >> 2;
    #pragma unroll
    for (int m = 0; m < 4; m++) {
        float sl = 0.f, ql = 0.f, shi = 0.f, qhi = 0.f;
        #pragma unroll
        for (int q = 0; q < 4; q++) {
            const float* a = acc[m][q];
            sl += a[0] + a[1];
            ql += a[0] * a[0] + a[1] * a[1];
            shi += a[2] + a[3];
            qhi += a[2] * a[2] + a[3] * a[3];
        }
        #pragma unroll
        for (int o = 1; o < 4; o <<= 1) {
            sl  += __shfl_xor_sync(0xffffffffu, sl,  o);
            ql  += __shfl_xor_sync(0xffffffffu, ql,  o);
            shi += __shfl_xor_sync(0xffffffffu, shi, o);
            qhi += __shfl_xor_sync(0xffffffffu, qhi, o);
        }
        if (lc == 0) {
            s_st[pxg * 256 + wm + m * 16 + lr]     = make_float2(sl, ql);
            s_st[pxg * 256 + wm + m * 16 + lr + 8] = make_float2(shi, qhi);
        }
    }
    __syncthreads();
    {
        float2 a = s_st[tid], b = s_st[256 + tid];
        Part[(size_t)(mbb + tid) * 1568 + n * 49 + blockIdx.x] =
            make_float2(a.x + b.x, a.y + b.y);
    }

    // ---- output STG (fp16 both modes) ----
    __half* Cp = ((MODE == 0) ? g_y1h : g_y3h)
                 + (size_t)n * ((MODE == 0) ? CD : COUT) * HW;
    #pragma unroll
    for (int m = 0; m < 4; m++) {
        #pragma unroll
        for (int q = 0; q < 4; q++) {
            int row = mbb + wm + m * 16 + lr;
            int pix = pb0 + wn + q * 8 + lc * 2;
            *(__half2*)&Cp[(size_t)row * HW + pix] =
                __floats2half2_rn(acc[m][q][0], acc[m][q][1]);
            *(__half2*)&Cp[(size_t)(row + 8) * HW + pix] =
                __floats2half2_rn(acc[m][q][2], acc[m][q][3]);
        }
    }
}

// ---------------------------------------------------------------------------
// Finalize BN: reduce per-CTA partials (fixed order) -> scale/shift
// ---------------------------------------------------------------------------
template<int WHICH>
__global__ void __launch_bounds__(256) bn_fin_kernel(const float* __restrict__ gamma,
                                                     const float* __restrict__ beta)
{
    constexpr int PARTS = (WHICH == 2) ? 224 : 1568;
    const float2* __restrict__ part =
        (WHICH == 1) ? g_part1 : (WHICH == 2) ? g_part2 : g_part3;
    float* __restrict__ scale = (WHICH == 1) ? g_scale1 : (WHICH == 2) ? g_scale2 : g_scale3;
    float* __restrict__ shift = (WHICH == 1) ? g_shift1 : (WHICH == 2) ? g_shift2 : g_shift3;

    const int c = blockIdx.x;
    float s = 0.f, sq = 0.f;
    for (int i = threadIdx.x; i < PARTS; i += 256) {
        float2 p = part[(size_t)c * PARTS + i];
        s += p.x; sq += p.y;
    }
    __shared__ float sh_s[8], sh_q[8];
    #pragma unroll
    for (int o = 16; o; o >>= 1) {
        s  += __shfl_down_sync(0xffffffffu, s,  o);
        sq += __shfl_down_sync(0xffffffffu, sq, o);
    }
    int lane = threadIdx.x & 31, wrp = threadIdx.x >> 5;
    if (lane == 0) { sh_s[wrp] = s; sh_q[wrp] = sq; }
    __syncthreads();
    if (threadIdx.x < 8) {
        s = sh_s[threadIdx.x]; sq = sh_q[threadIdx.x];
        #pragma unroll
        for (int o = 4; o; o >>= 1) {
            s  += __shfl_down_sync(0xffu, s,  o);
            sq += __shfl_down_sync(0xffu, sq, o);
        }
        if (threadIdx.x == 0) {
            const float inv = 1.f / (float)NTOT;
            float mean = s * inv;
            float var  = sq * inv - mean * mean;
            float sc = gamma[c] * rsqrtf(var + 1e-5f);
            scale[c] = sc;
            shift[c] = beta[c] - mean * sc;
        }
    }
}

// ---------------------------------------------------------------------------
// Grouped 3x3 conv, fp16 m16n8k16 implicit GEMM (ALU-lean, R12 layout).
// L1-latency-bound -> force 6 CTAs/SM via launch_bounds (42-reg cap).
// ---------------------------------------------------------------------------
#define CI2_STRIDE 584

__global__ void __launch_bounds__(256, 6) conv3x3_tc_kernel(const float* __restrict__ w3)
{
    __shared__ __align__(16) uint32_t s_w[9 * 128];      // frag-permuted weights
    __shared__ uint32_t s_in2[8 * CI2_STRIDE];           // [ci2][yy*58+xx]
    __shared__ float2 s3[8][16];

    const int tid = threadIdx.x;
    const int warp = tid >> 5, lane = tid & 31;
    const int lr = lane >> 2, lc = lane & 3;
    const int y0 = blockIdx.x * 8;
    const int g  = blockIdx.y;
    const int n  = blockIdx.z;

    // ---- weights -> frag-permuted [kk][lane][j], shift-only mapping ----
    const float* wg = w3 + (size_t)g * 16 * 144;
    #pragma unroll
    for (int it = 0; it < 5; it++) {
        int u = it * 256 + tid;                  // < 1152
        if (u < 9 * 128) {
            int kk = u >> 7, rem = u & 127;
            int ln = rem >> 2, j = rem & 3;
            int co = (ln >> 2) + (j & 1) * 8;
            int p  = (ln & 3) + (j >> 1) * 4;
            const float* wp = wg + co * 144 + p * 18 + kk;
            s_w[u] = h2bits(__floats2half2_rn(wp[0], wp[9]));
        }
    }

    // ---- input tile: warp per ci-pair, BN1+ReLU fused, no div/mod ----
    {
        const int p2 = warp;                     // ci pair 0..7
        const int cg = g * 16 + 2 * p2;
        const __half* src0 = g_y1h + ((size_t)(n * CD) + cg) * HW;
        const __half* src1 = src0 + HW;
        const float sc0 = g_scale1[cg], sh0 = g_shift1[cg];
        const float sc1 = g_scale1[cg + 1], sh1 = g_shift1[cg + 1];
        uint32_t* drow = &s_in2[p2 * CI2_STRIDE];
        #pragma unroll
        for (int yy = 0; yy < 10; yy++) {
            int gy = y0 + yy - 1;
            bool yok = (gy >= 0) && (gy < H);
            const __half* r0 = src0 + gy * W;
            const __half* r1 = src1 + gy * W;
            #pragma unroll
            for (int xc = 0; xc < 2; xc++) {
                int xx = xc * 32 + lane;
                if (xx < 58) {
                    int gx = xx - 1;
                    float v0 = 0.f, v1 = 0.f;
                    if (yok && (unsigned)gx < (unsigned)W) {
                        v0 = fmaxf(fmaf(sc0, __half2float(r0[gx]), sh0), 0.f);
                        v1 = fmaxf(fmaf(sc1, __half2float(r1[gx]), sh1), 0.f);
                    }
                    drow[yy * 58 + xx] = h2bits(__floats2half2_rn(v0, v1));
                }
            }
        }
    }
    __syncthreads();

    float acc[7][4];
    #pragma unroll
    for (int f = 0; f < 7; f++)
        #pragma unroll
        for (int r = 0; r < 4; r++) acc[f][r] = 0.f;

    const int row = warp;

    #pragma unroll
    for (int kk = 0; kk < 9; kk++) {
        const int dy = kk / 3, dx = kk % 3;      // compile-time (full unroll)
        uint4 av = *(const uint4*)&s_w[kk * 128 + lane * 4];
        uint32_t a[4] = {av.x, av.y, av.z, av.w};
        const uint32_t* bb = &s_in2[lc * CI2_STRIDE + (row + dy) * 58 + dx + lr];
        #pragma unroll
        for (int f = 0; f < 7; f++) {
            uint32_t b[2];
            b[0] = bb[f * 8];
            b[1] = bb[f * 8 + 4 * CI2_STRIDE];
            mma_f16(acc[f], a, b);
        }
    }

    // ---- BN2 partials (fixed order, fp32 accs) ----
    {
        float sl = 0.f, ql = 0.f, shi = 0.f, qhi = 0.f;
        #pragma unroll
        for (int f = 0; f < 7; f++) {
            sl += acc[f][0] + acc[f][1];
            ql += acc[f][0] * acc[f][0] + acc[f][1] * acc[f][1];
            shi += acc[f][2] + acc[f][3];
            qhi += acc[f][2] * acc[f][2] + acc[f][3] * acc[f][3];
        }
        #pragma unroll
        for (int o = 1; o < 4; o <<= 1) {
            sl  += __shfl_xor_sync(0xffffffffu, sl,  o);
            ql  += __shfl_xor_sync(0xffffffffu, ql,  o);
            shi += __shfl_xor_sync(0xffffffffu, shi, o);
            qhi += __shfl_xor_sync(0xffffffffu, qhi, o);
        }
        if (lc == 0) {
            s3[warp][lr]     = make_float2(sl, ql);
            s3[warp][lr + 8] = make_float2(shi, qhi);
        }
    }
    __syncthreads();
    if (tid < 16) {
        float s = 0.f, q = 0.f;
        #pragma unroll
        for (int w = 0; w < 8; w++) { float2 p = s3[w][tid]; s += p.x; q += p.y; }
        g_part2[(size_t)(g * 16 + tid) * 224 + n * 7 + blockIdx.x] = make_float2(s, q);
    }

    __half* dst = g_y2h + (size_t)(n * CD + g * 16) * HW + (size_t)(y0 + row) * W;
    #pragma unroll
    for (int f = 0; f < 7; f++) {
        int px = f * 8 + lc * 2;
        *(__half2*)&dst[(size_t)lr * HW + px] = __floats2half2_rn(acc[f][0], acc[f][1]);
        *(__half2*)&dst[(size_t)(lr + 8) * HW + px] = __floats2half2_rn(acc[f][2], acc[f][3]);
    }
}

// ---------------------------------------------------------------------------
// Final: out = relu(scale3*y3h + shift3 + x)   (y3 now fp16)
// ---------------------------------------------------------------------------
__global__ void __launch_bounds__(256) final_kernel(const float* __restrict__ x,
                                                    float* __restrict__ out)
{
    int i = blockIdx.x * 256 + threadIdx.x;
    int c = (i / HW4) & (COUT - 1);
    uint2 vh = ((const uint2*)g_y3h)[i];
    float2 v01 = __half22float2(bits2h2(vh.x));
    float2 v23 = __half22float2(bits2h2(vh.y));
    float4 xv = ((const float4*)x)[i];
    float sc = g_scale3[c], sh = g_shift3[c];
    float4 o;
    o.x = fmaxf(fmaf(sc, v01.x, sh) + xv.x, 0.f);
    o.y = fmaxf(fmaf(sc, v01.y, sh) + xv.y, 0.f);
    o.z = fmaxf(fmaf(sc, v23.x, sh) + xv.z, 0.f);
    o.w = fmaxf(fmaf(sc, v23.y, sh) + xv.w, 0.f);
    ((float4*)out)[i] = o;
}

// ---------------------------------------------------------------------------
extern "C" void kernel_launch(void* const* d_in, const int* in_sizes, int n_in,
                              void* d_out, int out_size)
{
    const float* x  = (const float*)d_in[0];
    const float* w1 = (const float*)d_in[1];
    const float* g1 = (const float*)d_in[2];
    const float* b1 = (const float*)d_in[3];
    const float* w3 = (const float*)d_in[4];
    const float* g3 = (const float*)d_in[5];
    const float* b3 = (const float*)d_in[6];
    const float* wa = (const float*)d_in[7];
    const float* ga = (const float*)d_in[8];
    const float* ba = (const float*)d_in[9];
    float* out = (float*)d_out;

    cudaFuncSetAttribute(mma_gemm_kernel<0>, cudaFuncAttributeMaxDynamicSharedMemorySize, GEMM_SMEM);
    cudaFuncSetAttribute(mma_gemm_kernel<1>, cudaFuncAttributeMaxDynamicSharedMemorySize, GEMM_SMEM);

    // 0: combined prepass (weights permute + x pack)
    cvt_all_kernel<<<(131072 + NB * 8 * 16 * HW + 255) / 256, 256>>>(w1, wa, x);
    // 1: conv1 (M=512 -> 2 M-tiles, K=256)
    mma_gemm_kernel<0><<<dim3(49, 2, NB), 256, GEMM_SMEM>>>(x);
    // 2
    bn_fin_kernel<1><<<CD, 256>>>(g1, b1);
    // 3: grouped 3x3 fp16 tensor cores
    conv3x3_tc_kernel<<<dim3(7, GRP, NB), 256>>>(w3);
    // 4
    bn_fin_kernel<2><<<CD, 256>>>(g3, b3);
    // 5: convA (K=512)
    mma_gemm_kernel<1><<<dim3(49, 1, NB), 256, GEMM_SMEM>>>(nullptr);
    // 6
    bn_fin_kernel<3><<<COUT, 256>>>(ga, ba);
    // 7: final residual
    final_kernel<<<(NB * COUT * HW4) / 256, 256>>>(x, out);
}